// round 10
// baseline (speedup 1.0000x reference)
#include <cuda_runtime.h>
#include <cuda_bf16.h>
#include <cuda_fp16.h>
#include <math.h>
#include <cstdint>

#define NTOK 8192
#define HIDDEN 2048
#define HEADS 16
#define DH 128
#define BLK 256
#define NCHUNK 32
#define QKVW 6144

#if defined(__CUDA_ARCH_FEAT_SM103_ALL) || \
    (defined(__CUDA_ARCH_SPECIFIC__) && (__CUDA_ARCH_SPECIFIC__ == 1030)) || \
    (defined(__CUDA_ARCH_FAMILY_SPECIFIC__) && (__CUDA_ARCH_FAMILY_SPECIFIC__ == 1030))
#define HAS_TCGEN05 1
#else
#define HAS_TCGEN05 0
#endif

// ================= PTX helpers ==============================================
__device__ __forceinline__ uint32_t elect_one_pred() {
    uint32_t pred;
    asm volatile("{\n\t.reg .pred p;\n\telect.sync _|p, 0xFFFFFFFF;\n\t"
                 "selp.b32 %0, 1, 0, p;\n\t}" : "=r"(pred));
    return pred;
}
__device__ __forceinline__ uint32_t smem_to_u32(const void* p) {
    uint32_t a;
    asm("{ .reg .u64 t; cvta.to.shared.u64 t, %1; cvt.u32.u64 %0, t; }"
        : "=r"(a) : "l"(p));
    return a;
}
__device__ __forceinline__ uint32_t cluster_rank() {
    uint32_t r;
    asm("mov.u32 %0, %%cluster_ctarank;" : "=r"(r));
    return r;
}
#define CLUSTER_SYNC() do { \
    asm volatile("barrier.cluster.arrive.aligned;" ::: "memory"); \
    asm volatile("barrier.cluster.wait.aligned;" ::: "memory"); \
} while (0)
#define MBARRIER_INIT(addr, cnt) \
    asm volatile("mbarrier.init.shared.b64 [%0], %1;" :: "r"((uint32_t)(addr)), "r"((uint32_t)(cnt)) : "memory")
#define MBARRIER_WAIT_PARITY(addr, par) do { \
    uint32_t _m = (uint32_t)(addr); uint32_t _p = (uint32_t)(par); uint32_t _d; \
    asm volatile("{\n\t.reg .pred p;\n\t" \
        "mbarrier.try_wait.parity.acquire.cta.shared::cta.b64 p, [%1], %2;\n\t" \
        "selp.b32 %0, 1, 0, p;\n\t}" : "=r"(_d) : "r"(_m), "r"(_p) : "memory"); \
    if (!_d) { \
        asm volatile("{\n\t.reg .pred P1;\n\t" \
            "WL_%=:\n\t" \
            "mbarrier.try_wait.parity.acquire.cta.shared::cta.b64 P1, [%0], %1, 0x989680;\n\t" \
            "@P1 bra.uni WD_%=;\n\tbra.uni WL_%=;\n\tWD_%=:\n\t}" \
            :: "r"(_m), "r"(_p) : "memory"); \
    } } while (0)
#define MBARRIER_WAIT_PARITY_CL(addr, par) do { \
    uint32_t _m = (uint32_t)(addr); uint32_t _p = (uint32_t)(par); uint32_t _d; \
    asm volatile("{\n\t.reg .pred p;\n\t" \
        "mbarrier.try_wait.parity.acquire.cluster.shared::cta.b64 p, [%1], %2;\n\t" \
        "selp.b32 %0, 1, 0, p;\n\t}" : "=r"(_d) : "r"(_m), "r"(_p) : "memory"); \
    if (!_d) { \
        asm volatile("{\n\t.reg .pred P1;\n\t" \
            "WL_%=:\n\t" \
            "mbarrier.try_wait.parity.acquire.cluster.shared::cta.b64 P1, [%0], %1, 0x989680;\n\t" \
            "@P1 bra.uni WD_%=;\n\tbra.uni WL_%=;\n\tWD_%=:\n\t}" \
            :: "r"(_m), "r"(_p) : "memory"); \
    } } while (0)
#define MBARRIER_ARRIVE_CLUSTER(local_addr, target_rank) \
    asm volatile( \
        "{\n\t.reg .b32 remAddr32;\n\t" \
        "mapa.shared::cluster.u32 remAddr32, %0, %1;\n\t" \
        "mbarrier.arrive.release.cluster.shared::cluster.b64 _, [remAddr32];\n\t}" \
        :: "r"((uint32_t)(local_addr)), "r"((uint32_t)(target_rank)) : "memory")
#define TCGEN05_ALLOC(smem_addr, n) \
    asm volatile("tcgen05.alloc.cta_group::1.sync.aligned.shared::cta.b32 [%0], %1;" \
        :: "r"((uint32_t)(smem_addr)), "r"((uint32_t)(n)) : "memory")
#define TCGEN05_DEALLOC(tmem, n) \
    asm volatile("tcgen05.dealloc.cta_group::1.sync.aligned.b32 %0, %1;" :: "r"(tmem), "r"((uint32_t)(n)))
#define TCGEN05_RELINQ() \
    asm volatile("tcgen05.relinquish_alloc_permit.cta_group::1.sync.aligned;")
#define TCGEN05_ALLOC_CG2(smem_addr, n) \
    asm volatile("tcgen05.alloc.cta_group::2.sync.aligned.shared::cta.b32 [%0], %1;" \
        :: "r"((uint32_t)(smem_addr)), "r"((uint32_t)(n)) : "memory")
#define TCGEN05_DEALLOC_CG2(tmem, n) \
    asm volatile("tcgen05.dealloc.cta_group::2.sync.aligned.b32 %0, %1;" :: "r"(tmem), "r"((uint32_t)(n)))
#define TCGEN05_RELINQ_CG2() \
    asm volatile("tcgen05.relinquish_alloc_permit.cta_group::2.sync.aligned;")
#define TCGEN05_COMMIT(mbar) \
    asm volatile("tcgen05.commit.cta_group::1.mbarrier::arrive::one.shared::cluster.b64 [%0];" \
        :: "r"((uint32_t)(mbar)) : "memory")
#define TCGEN05_COMMIT_MC_CG2(mbar, mask) \
    asm volatile("tcgen05.commit.cta_group::2.mbarrier::arrive::one.shared::cluster.multicast::cluster.b64 [%0], %1;" \
        :: "r"((uint32_t)(mbar)), "h"((uint16_t)(mask)) : "memory")
#define TCGEN05_FENCE_AFTER() asm volatile("tcgen05.fence::after_thread_sync;" ::: "memory")
#define TCGEN05_WAIT_LD() asm volatile("tcgen05.wait::ld.sync.aligned;" ::: "memory")
#define FENCE_ASYNC_SHARED() asm volatile("fence.proxy.async.shared::cta;" ::: "memory")
#define TCGEN05_LD_X32(r, addr) \
    asm volatile("tcgen05.ld.sync.aligned.32x32b.x32.b32 " \
        "{%0, %1, %2, %3, %4, %5, %6, %7, %8, %9, %10, %11, %12, %13, %14, %15, " \
        " %16, %17, %18, %19, %20, %21, %22, %23, %24, %25, %26, %27, %28, %29, %30, %31}, [%32];" \
        : "=r"((r)[0]),  "=r"((r)[1]),  "=r"((r)[2]),  "=r"((r)[3]), \
          "=r"((r)[4]),  "=r"((r)[5]),  "=r"((r)[6]),  "=r"((r)[7]), \
          "=r"((r)[8]),  "=r"((r)[9]),  "=r"((r)[10]), "=r"((r)[11]), \
          "=r"((r)[12]), "=r"((r)[13]), "=r"((r)[14]), "=r"((r)[15]), \
          "=r"((r)[16]), "=r"((r)[17]), "=r"((r)[18]), "=r"((r)[19]), \
          "=r"((r)[20]), "=r"((r)[21]), "=r"((r)[22]), "=r"((r)[23]), \
          "=r"((r)[24]), "=r"((r)[25]), "=r"((r)[26]), "=r"((r)[27]), \
          "=r"((r)[28]), "=r"((r)[29]), "=r"((r)[30]), "=r"((r)[31]) \
        : "r"(addr))

static constexpr uint64_t SMEM_DESC_BASE_SW128 =
    (uint64_t(2) << 61) | (uint64_t(1) << 46) | (uint64_t(64) << 32) | (uint64_t(1) << 16);
#define MAKE_SMEM_DESC(a) (SMEM_DESC_BASE_SW128 | ((uint64_t)((a) >> 4) & 0x3FFF))

#if HAS_TCGEN05
__device__ __forceinline__ void mma_f16_ss(uint32_t d_tmem, uint64_t a_desc,
                                           uint64_t b_desc, uint32_t idesc, bool acc) {
    uint32_t en = acc ? 1u : 0u;
    asm volatile(
        "{\n\t.reg .pred p;\n\tsetp.ne.u32 p, %5, 0;\n\t"
        "tcgen05.mma.cta_group::1.kind::f16 [%0], %1, %2, %3, {%4, %4, %4, %4}, p;\n\t}"
        :: "r"(d_tmem), "l"(a_desc), "l"(b_desc), "r"(idesc), "r"(0u), "r"(en)
        : "memory");
}
__device__ __forceinline__ void mma_f16_ss_cg2(uint32_t d_tmem, uint64_t a_desc,
                                               uint64_t b_desc, uint32_t idesc, bool acc) {
    uint32_t en = acc ? 1u : 0u;
    asm volatile(
        "{\n\t.reg .pred p;\n\tsetp.ne.u32 p, %5, 0;\n\t"
        "tcgen05.mma.cta_group::2.kind::f16 [%0], %1, %2, %3, "
        "{%4, %4, %4, %4, %4, %4, %4, %4}, p;\n\t}"
        :: "r"(d_tmem), "l"(a_desc), "l"(b_desc), "r"(idesc), "r"(0u), "r"(en)
        : "memory");
}
#endif

__device__ __forceinline__ uint32_t bswz(int row, int col, int atomrows) {
    uint32_t off = (uint32_t)(((row >> 3) + (col >> 6) * atomrows) << 10)
                 + ((row & 7) << 7) + ((col & 63) << 1);
    return off ^ ((off >> 3) & 0x70);
}
__device__ __forceinline__ uint32_t pk(__nv_bfloat16 a, __nv_bfloat16 b) {
    __nv_bfloat162 t{a, b};
    return *(uint32_t*)&t;
}

// ================= scratch ===================================================
__device__ float g_qkv[(size_t)NTOK * QKVW];
__device__ float g_gate[(size_t)NTOK * HIDDEN];
__device__ float g_attn[(size_t)NTOK * HIDDEN];
__device__ float g_kvblk[(size_t)HEADS * NCHUNK * DH * DH];
__device__ float g_kvstate[(size_t)HEADS * NCHUNK * DH * DH];
__device__ float g_invf[64];
__device__ float g_slopes[HEADS];
__device__ __nv_bfloat16 g_vThi[(size_t)HEADS * NCHUNK * 32768];
__device__ __nv_bfloat16 g_vTlo[(size_t)HEADS * NCHUNK * 32768];
__device__ __half g_ah[(size_t)NTOK * HIDDEN];
__device__ __half g_yh[(size_t)NTOK * HIDDEN];
__device__ __half g_bqkv_hi[(size_t)QKVW * HIDDEN];
__device__ __half g_bqkv_lo[(size_t)QKVW * HIDDEN];
__device__ __half g_bg_hi[(size_t)HIDDEN * HIDDEN];
__device__ __half g_bg_lo[(size_t)HIDDEN * HIDDEN];
__device__ __half g_bd_hi[(size_t)HIDDEN * HIDDEN];
__device__ __half g_bd_lo[(size_t)HIDDEN * HIDDEN];

// ================= init tables ================================================
__global__ void init_tables() {
    int t = threadIdx.x;
    if (t < 64) g_invf[t] = (float)pow(600000.0, -(double)t / 64.0);
    if (t < HEADS) {
        double start = pow(2.0, -pow(2.0, -(log2(16.0) - 3.0)));
        g_slopes[t] = (float)(start * pow(start, (double)t) * (1.0 + 1e-5));
    }
}

// ================= convert fp32 -> fp16 (A operand, single) =================
__global__ void conv_act(const float* __restrict__ x, __half* __restrict__ h, int n4) {
    int i = blockIdx.x * blockDim.x + threadIdx.x;
    if (i >= n4) return;
    float4 v = ((const float4*)x)[i];
    __half2 a{__float2half_rn(v.x), __float2half_rn(v.y)};
    __half2 b{__float2half_rn(v.z), __float2half_rn(v.w)};
    ((__half2*)h)[i * 2]     = a;
    ((__half2*)h)[i * 2 + 1] = b;
}

// ======= transpose + split W[K,N] fp32 -> Thi/Tlo [N,K] fp16 ================
__global__ void transposeW(const float* __restrict__ W, __half* __restrict__ Thi,
                           __half* __restrict__ Tlo, int K, int N) {
    __shared__ float t[32][33];
    int n0 = blockIdx.x * 32, k0 = blockIdx.y * 32;
    int c = threadIdx.x & 31, r0 = threadIdx.x >> 5;
    #pragma unroll
    for (int rr = r0; rr < 32; rr += 8)
        t[rr][c] = W[(size_t)(k0 + rr) * N + n0 + c];
    __syncthreads();
    #pragma unroll
    for (int rr = r0; rr < 32; rr += 8) {
        float v = t[c][rr];
        __half h = __float2half_rn(v);
        Thi[(size_t)(n0 + rr) * K + k0 + c] = h;
        Tlo[(size_t)(n0 + rr) * K + k0 + c] = __float2half_rn(v - __half2float(h));
    }
}

#if HAS_TCGEN05
template <int ROWS>
__device__ __forceinline__ void load_tile(char* dst, const __half* src, int ld) {
    int tid = threadIdx.x;
    #pragma unroll
    for (int l = 0; l < ROWS / 32; l++) {
        int i = l * 256 + tid;
        int r = i >> 3, sg = i & 7;
        uint4 v = *(const uint4*)(src + (size_t)r * ld + sg * 8);
        uint32_t off = (uint32_t)(r * 128 + sg * 16);
        off ^= (off >> 3) & 0x70;
        *(uint4*)(dst + off) = v;
    }
}
// load a [128 rows, 128 half] chunk in blocked SW128 layout (two 64-col blocks)
__device__ __forceinline__ void load_tile128(char* dst, const __half* src, int ld) {
    load_tile<128>(dst,          src,      ld);
    load_tile<128>(dst + 16384,  src + 64, ld);
}
#endif

// ======= cg2 fp16 2-term GEMM, K-chunk = 128 =================================
// per-buffer: A 32K | Bhi 32K | Blo 32K = 96KB; x2 buffers
#define CG2_BUF 98304
#define CG2_SMEM (1024 + 2 * CG2_BUF)
#define IDESC_CG2 ((1u << 4) | (32u << 17) | (16u << 24))

// ======= fused qkv+gate GEMM (cg2 fp16, gate 1-term) with RoPE epilogue ======
__global__ __launch_bounds__(256, 1) __cluster_dims__(2, 1, 1)
void gemm_qkvgate(const __half* __restrict__ A, const int* __restrict__ positions) {
    const int K = HIDDEN;
    uint32_t rank = cluster_rank();
    int bm = blockIdx.y * 256;
    int bn = (blockIdx.x >> 1) * 256;
    int gcs = bn + (int)rank * 128;
    bool isGate = (bn >= QKVW);       // cluster-uniform (QKVW % 256 == 0)
    const __half* Bhi = (gcs < QKVW) ? g_bqkv_hi + (size_t)gcs * K
                                     : g_bg_hi + (size_t)(gcs - QKVW) * K;
    const __half* Blo = (gcs < QKVW) ? g_bqkv_lo + (size_t)gcs * K
                                     : g_bg_lo + (size_t)(gcs - QKVW) * K;
#if HAS_TCGEN05
    extern __shared__ char smem[];
    uint32_t sb = smem_to_u32(smem);
    int tid = threadIdx.x;
    const uint32_t dn0 = sb + 8,  dn1 = sb + 16;
    const uint32_t rd0 = sb + 24, rd1 = sb + 32;
    if (tid < 32) TCGEN05_ALLOC_CG2(sb, 256);
    if (tid == 0) {
        MBARRIER_INIT(dn0, 1); MBARRIER_INIT(dn1, 1);
        MBARRIER_INIT(rd0, 2); MBARRIER_INIT(rd1, 2);
    }
    __syncthreads();
    uint32_t tmem;
    asm volatile("ld.shared.b32 %0, [%1];" : "=r"(tmem) : "r"(sb));
    if (tid < 32) TCGEN05_RELINQ_CG2();
    CLUSTER_SYNC();

    const __half* pA = A + (size_t)(bm + rank * 128) * K;

    int phd[2] = {0, 0};
    int phr[2] = {0, 0};
    for (int ch = 0; ch < 16; ch++) {            // K-chunk 128
        int b = ch & 1;
        char* st = smem + 1024 + b * CG2_BUF;
        if (ch >= 2) {
            MBARRIER_WAIT_PARITY_CL(b ? dn1 : dn0, phd[b]);
            phd[b] ^= 1;
        }
        int k0 = ch << 7;
        load_tile128(st,         pA + k0,  K);
        load_tile128(st + 32768, Bhi + k0, K);
        if (!isGate) load_tile128(st + 65536, Blo + k0, K);
        FENCE_ASYNC_SHARED();
        __syncthreads();
        if (tid == 0) MBARRIER_ARRIVE_CLUSTER(b ? rd1 : rd0, 0);
        if (rank == 0 && tid < 32) {
            MBARRIER_WAIT_PARITY_CL(b ? rd1 : rd0, phr[b]);
            phr[b] ^= 1;
            uint32_t sa = sb + 1024 + b * CG2_BUF;
            uint64_t dA  = MAKE_SMEM_DESC(sa);
            uint64_t dBh = MAKE_SMEM_DESC(sa + 32768);
            uint64_t dBl = MAKE_SMEM_DESC(sa + 65536);
            if (elect_one_pred()) {
                #pragma unroll
                for (int k = 0; k < 8; k++) {
                    uint32_t u = ((uint32_t)(k >> 2) << 10) | ((uint32_t)(k & 3) << 1);
                    bool first = (ch == 0) && (k == 0);
                    mma_f16_ss_cg2(tmem, dA + u, dBh + u, IDESC_CG2, !first);
                    if (!isGate)
                        mma_f16_ss_cg2(tmem, dA + u, dBl + u, IDESC_CG2, true);
                }
                TCGEN05_COMMIT_MC_CG2(b ? dn1 : dn0, 0x3);
            }
        }
    }
    MBARRIER_WAIT_PARITY_CL(dn0, phd[0]);
    MBARRIER_WAIT_PARITY_CL(dn1, phd[1]);
    TCGEN05_FENCE_AFTER();
    __syncthreads();

    int w = tid >> 5, l = tid & 31;
    int sub = w & 3;
    int colbase = (w >> 2) * 128;
    int row = bm + (int)rank * 128 + sub * 32 + l;
    int gc0 = bn + colbase;
    bool isQ = gc0 < 2048;
    bool isK = (gc0 >= 2048) && (gc0 < 4096);
    float* dst = (gc0 < QKVW) ? g_qkv + (size_t)row * QKVW + gc0
                              : g_gate + (size_t)row * HIDDEN + (gc0 - QKVW);
    if (isQ || isK) {
        float pos = (float)positions[row];
        float qs = isQ ? 0.08838834764831845f : 1.0f;
        #pragma unroll
        for (int half = 0; half < 2; half++) {
            uint32_t a[32], b[32];
            TCGEN05_LD_X32(a, tmem + colbase + half * 32);
            TCGEN05_WAIT_LD();
            TCGEN05_LD_X32(b, tmem + colbase + half * 32 + 64);
            TCGEN05_WAIT_LD();
            #pragma unroll
            for (int j0 = 0; j0 < 32; j0 += 4) {
                float o1[4], o2[4];
                #pragma unroll
                for (int j = 0; j < 4; j++) {
                    int jin = half * 32 + j0 + j;
                    float f = pos * g_invf[jin];
                    float sv, cv;
                    sincosf(f, &sv, &cv);
                    float x1 = __uint_as_float(a[j0 + j]);
                    float x2 = __uint_as_float(b[j0 + j]);
                    o1[j] = (x1 * cv - x2 * sv) * qs;
                    o2[j] = (x2 * cv + x1 * sv) * qs;
                }
                *(float4*)&dst[half * 32 + j0]      = make_float4(o1[0], o1[1], o1[2], o1[3]);
                *(float4*)&dst[half * 32 + 64 + j0] = make_float4(o2[0], o2[1], o2[2], o2[3]);
            }
        }
    } else {
        #pragma unroll
        for (int cb = 0; cb < 128; cb += 32) {
            uint32_t r[32];
            TCGEN05_LD_X32(r, tmem + colbase + cb);
            TCGEN05_WAIT_LD();
            #pragma unroll
            for (int j = 0; j < 32; j += 4)
                *(float4*)&dst[cb + j] = make_float4(
                    __uint_as_float(r[j]), __uint_as_float(r[j + 1]),
                    __uint_as_float(r[j + 2]), __uint_as_float(r[j + 3]));
        }
    }
    __syncthreads();
    if (tid < 32) TCGEN05_DEALLOC_CG2(tmem, 256);
    CLUSTER_SYNC();
#else
    extern __shared__ char smemraw[];
    float* As = (float*)smemraw;
    float* Bs = As + 16 * 128;
    int tid = threadIdx.x;
    int bmr = bm + (int)rank * 128;
    int ty = tid >> 4, tx = tid & 15;
    float acc[8][16];
    #pragma unroll
    for (int i = 0; i < 8; i++)
        #pragma unroll
        for (int j = 0; j < 16; j++) acc[i][j] = 0.f;
    for (int k0 = 0; k0 < K; k0 += 16) {
        #pragma unroll
        for (int l = 0; l < 8; l++) {
            int i = l * 256 + tid;
            int k = i & 15, m = i >> 4;
            As[k * 128 + m] = __half2float(A[(size_t)(bmr + m) * K + k0 + k]);
        }
        #pragma unroll
        for (int l = 0; l < 16; l++) {
            int i = l * 256 + tid;
            int k = i & 15, n = i >> 4;
            int gc = bn + n;
            const __half* bh = (gc < QKVW) ? g_bqkv_hi + (size_t)gc * K
                                           : g_bg_hi + (size_t)(gc - QKVW) * K;
            const __half* bl = (gc < QKVW) ? g_bqkv_lo + (size_t)gc * K
                                           : g_bg_lo + (size_t)(gc - QKVW) * K;
            float bv = __half2float(bh[k0 + k]);
            if (!isGate) bv += __half2float(bl[k0 + k]);
            Bs[k * 256 + n] = bv;
        }
        __syncthreads();
        #pragma unroll
        for (int kk = 0; kk < 16; kk++) {
            float a[8], b[16];
            #pragma unroll
            for (int i = 0; i < 8; i++) a[i] = As[kk * 128 + ty * 8 + i];
            #pragma unroll
            for (int j = 0; j < 16; j++) b[j] = Bs[kk * 256 + tx * 16 + j];
            #pragma unroll
            for (int i = 0; i < 8; i++)
                #pragma unroll
                for (int j = 0; j < 16; j++) acc[i][j] += a[i] * b[j];
        }
        __syncthreads();
    }
    float* tileS = (float*)smemraw;
    #pragma unroll
    for (int i = 0; i < 8; i++)
        #pragma unroll
        for (int j = 0; j < 16; j++)
            tileS[(ty * 8 + i) * 257 + tx * 16 + j] = acc[i][j];
    __syncthreads();
    {
        int r = tid >> 1, sp = tid & 1;
        int row = bmr + r;
        int gc0 = bn + sp * 128;
        bool isQ = gc0 < 2048;
        bool isK = (gc0 >= 2048) && (gc0 < 4096);
        float* dst = (gc0 < QKVW) ? g_qkv + (size_t)row * QKVW + gc0
                                  : g_gate + (size_t)row * HIDDEN + (gc0 - QKVW);
        const float* src = &tileS[r * 257 + sp * 128];
        if (isQ || isK) {
            float pos = (float)positions[row];
            float qs = isQ ? 0.08838834764831845f : 1.0f;
            for (int j = 0; j < 64; j++) {
                float f = pos * g_invf[j];
                float sv, cv;
                sincosf(f, &sv, &cv);
                float x1 = src[j], x2 = src[j + 64];
                dst[j]      = (x1 * cv - x2 * sv) * qs;
                dst[j + 64] = (x2 * cv + x1 * sv) * qs;
            }
        } else {
            for (int j = 0; j < 128; j++) dst[j] = src[j];
        }
    }
#endif
}

// ================= cg2 fp16 2-term down-projection GEMM, K-chunk 128 =========
__global__ __launch_bounds__(256, 1) __cluster_dims__(2, 1, 1)
void gemm_down(const __half* __restrict__ A,
               const __half* __restrict__ Bhi, const __half* __restrict__ Blo,
               float* __restrict__ C, int Nn, int K) {
    uint32_t rank = cluster_rank();
    int bm = blockIdx.y * 256;
    int bn = (blockIdx.x >> 1) * 256;
#if HAS_TCGEN05
    extern __shared__ char smem[];
    uint32_t sb = smem_to_u32(smem);
    int tid = threadIdx.x;
    const uint32_t dn0 = sb + 8,  dn1 = sb + 16;
    const uint32_t rd0 = sb + 24, rd1 = sb + 32;
    if (tid < 32) TCGEN05_ALLOC_CG2(sb, 256);
    if (tid == 0) {
        MBARRIER_INIT(dn0, 1); MBARRIER_INIT(dn1, 1);
        MBARRIER_INIT(rd0, 2); MBARRIER_INIT(rd1, 2);
    }
    __syncthreads();
    uint32_t tmem;
    asm volatile("ld.shared.b32 %0, [%1];" : "=r"(tmem) : "r"(sb));
    if (tid < 32) TCGEN05_RELINQ_CG2();
    CLUSTER_SYNC();

    const __half* pA   = A   + (size_t)(bm + rank * 128) * K;
    const __half* pBhi = Bhi + (size_t)(bn + rank * 128) * K;
    const __half* pBlo = Blo + (size_t)(bn + rank * 128) * K;

    int phd[2] = {0, 0};
    int phr[2] = {0, 0};
    const int nch = K >> 7;
    for (int ch = 0; ch < nch; ch++) {
        int b = ch & 1;
        char* st = smem + 1024 + b * CG2_BUF;
        if (ch >= 2) {
            MBARRIER_WAIT_PARITY_CL(b ? dn1 : dn0, phd[b]);
            phd[b] ^= 1;
        }
        int k0 = ch << 7;
        load_tile128(st,         pA + k0,   K);
        load_tile128(st + 32768, pBhi + k0, K);
        load_tile128(st + 65536, pBlo + k0, K);
        FENCE_ASYNC_SHARED();
        __syncthreads();
        if (tid == 0) MBARRIER_ARRIVE_CLUSTER(b ? rd1 : rd0, 0);
        if (rank == 0 && tid < 32) {
            MBARRIER_WAIT_PARITY_CL(b ? rd1 : rd0, phr[b]);
            phr[b] ^= 1;
            uint32_t sa = sb + 1024 + b * CG2_BUF;
            uint64_t dA  = MAKE_SMEM_DESC(sa);
            uint64_t dBh = MAKE_SMEM_DESC(sa + 32768);
            uint64_t dBl = MAKE_SMEM_DESC(sa + 65536);
            if (elect_one_pred()) {
                #pragma unroll
                for (int k = 0; k < 8; k++) {
                    uint32_t u = ((uint32_t)(k >> 2) << 10) | ((uint32_t)(k & 3) << 1);
                    bool first = (ch == 0) && (k == 0);
                    mma_f16_ss_cg2(tmem, dA + u, dBh + u, IDESC_CG2, !first);
                    mma_f16_ss_cg2(tmem, dA + u, dBl + u, IDESC_CG2, true);
                }
                TCGEN05_COMMIT_MC_CG2(b ? dn1 : dn0, 0x3);
            }
        }
    }
    MBARRIER_WAIT_PARITY_CL(dn0, phd[0]);
    MBARRIER_WAIT_PARITY_CL(dn1, phd[1]);
    TCGEN05_FENCE_AFTER();
    __syncthreads();

    int w = tid >> 5, l = tid & 31;
    int sub = w & 3;
    int colbase = (w >> 2) * 128;
    int row = bm + (int)rank * 128 + sub * 32 + l;
    float* dst_row = C + (size_t)row * Nn + bn + colbase;
    #pragma unroll
    for (int cb = 0; cb < 128; cb += 32) {
        uint32_t r[32];
        TCGEN05_LD_X32(r, tmem + colbase + cb);
        TCGEN05_WAIT_LD();
        #pragma unroll
        for (int j = 0; j < 32; j += 4)
            *(float4*)(dst_row + cb + j) = make_float4(
                __uint_as_float(r[j]), __uint_as_float(r[j + 1]),
                __uint_as_float(r[j + 2]), __uint_as_float(r[j + 3]));
    }
    __syncthreads();
    if (tid < 32) TCGEN05_DEALLOC_CG2(tmem, 256);
    CLUSTER_SYNC();
#else
    extern __shared__ char smemraw[];
    float* As = (float*)smemraw;
    float* Bs = As + 16 * 128;
    int tid = threadIdx.x;
    int bmr = bm + (int)rank * 128;
    int ty = tid >> 4, tx = tid & 15;
    float acc[8][16];
    #pragma unroll
    for (int i = 0; i < 8; i++)
        #pragma unroll
        for (int j = 0; j < 16; j++) acc[i][j] = 0.f;
    for (int k0 = 0; k0 < K; k0 += 16) {
        #pragma unroll
        for (int l = 0; l < 8; l++) {
            int i = l * 256 + tid;
            int k = i & 15, m = i >> 4;
            As[k * 128 + m] = __half2float(A[(size_t)(bmr + m) * K + k0 + k]);
        }
        #pragma unroll
        for (int l = 0; l < 16; l++) {
            int i = l * 256 + tid;
            int k = i & 15, n = i >> 4;
            size_t off = (size_t)(bn + n) * K + k0 + k;
            Bs[k * 256 + n] = __half2float(Bhi[off]) + __half2float(Blo[off]);
        }
        __syncthreads();
        #pragma unroll
        for (int kk = 0; kk < 16; kk++) {
            float a[8], b[16];
            #pragma unroll
            for (int i = 0; i < 8; i++) a[i] = As[kk * 128 + ty * 8 + i];
            #pragma unroll
            for (int j = 0; j < 16; j++) b[j] = Bs[kk * 256 + tx * 16 + j];
            #pragma unroll
            for (int i = 0; i < 8; i++)
                #pragma unroll
                for (int j = 0; j < 16; j++) acc[i][j] += a[i] * b[j];
        }
        __syncthreads();
    }
    #pragma unroll
    for (int i = 0; i < 8; i++) {
        size_t off = (size_t)(bmr + ty * 8 + i) * Nn + bn + tx * 16;
        #pragma unroll
        for (int j = 0; j < 16; j += 4)
            *(float4*)&C[off + j] = make_float4(acc[i][j], acc[i][j + 1],
                                                acc[i][j + 2], acc[i][j + 3]);
    }
#endif
}

// ============ Phase A: kvblkT (tensor, bf16x3 — unchanged) ==================
__global__ __launch_bounds__(256, 1) void kvblkT_kernel() {
#if HAS_TCGEN05
    extern __shared__ char smem[];
    uint32_t sb = smem_to_u32(smem);
    int tid = threadIdx.x;
    int h = blockIdx.x & 15, c = blockIdx.x >> 4;
    float s = g_slopes[h];
    float* decay_tab = (float*)(smem + 16);
    const int STG = 2048;
    const int KTHI = STG + 67584;
    const int KTLO = KTHI + 32768;
    const int VTHI = KTLO + 32768;
    const int VTLO = VTHI + 32768;
    uint32_t mb = sb + 8;
    if (tid < 32) TCGEN05_ALLOC(sb, 128);
    if (tid == 0) MBARRIER_INIT(mb, 1);
    for (int i = tid; i < 257; i += 256) decay_tab[i] = expf(-s * (float)i);
    __syncthreads();
    uint32_t tmem;
    asm volatile("ld.shared.b32 %0, [%1];" : "=r"(tmem) : "r"(sb));
    if (tid < 32) TCGEN05_RELINQ();
    float* stg = (float*)(smem + STG);
    const uint32_t IDESC128 = (1u << 4) | (1u << 7) | (1u << 10) | (16u << 17) | (8u << 24);

    for (int half = 0; half < 2; half++) {
        if (half == 1) MBARRIER_WAIT_PARITY(mb, 0);
        const float* kb = g_qkv + (size_t)(c * 256 + half * 128) * QKVW + 2048 + (size_t)h * DH;
        #pragma unroll
        for (int it = 0; it < 16; it++) {
            int j = it * 256 + tid;
            int r = j >> 5, dq = (j & 31) << 2;
            *(float4*)&stg[r * 132 + dq] = *(const float4*)&kb[(size_t)r * QKVW + dq];
        }
        __syncthreads();
        #pragma unroll
        for (int it = 0; it < 8; it++) {
            int t = it * 256 + tid;
            int d = t & 127, g = t >> 7;
            uint32_t hp[4], lp[4];
            #pragma unroll
            for (int jj = 0; jj < 4; jj++) {
                int n0 = g * 8 + jj * 2;
                float v0 = stg[n0 * 132 + d]       * decay_tab[255 - (half * 128 + n0)];
                float v1 = stg[(n0 + 1) * 132 + d] * decay_tab[255 - (half * 128 + n0 + 1)];
                __nv_bfloat16 h0 = __float2bfloat16(v0), h1 = __float2bfloat16(v1);
                hp[jj] = pk(h0, h1);
                lp[jj] = pk(__float2bfloat16(v0 - __bfloat162float(h0)),
                            __float2bfloat16(v1 - __bfloat162float(h1)));
            }
            uint32_t o = bswz(d, g * 8, 16);
            *(uint4*)(smem + KTHI + o) = make_uint4(hp[0], hp[1], hp[2], hp[3]);
            *(uint4*)(smem + KTLO + o) = make_uint4(lp[0], lp[1], lp[2], lp[3]);
        }
        __syncthreads();
        const float* vb = g_qkv + (size_t)(c * 256 + half * 128) * QKVW + 4096 + (size_t)h * DH;
        #pragma unroll
        for (int it = 0; it < 16; it++) {
            int j = it * 256 + tid;
            int r = j >> 5, dq = (j & 31) << 2;
            *(float4*)&stg[r * 132 + dq] = *(const float4*)&vb[(size_t)r * QKVW + dq];
        }
        __syncthreads();
        #pragma unroll
        for (int it = 0; it < 8; it++) {
            int t = it * 256 + tid;
            int d = t & 127, g = t >> 7;
            uint32_t hp[4], lp[4];
            #pragma unroll
            for (int jj = 0; jj < 4; jj++) {
                int n0 = g * 8 + jj * 2;
                float v0 = stg[n0 * 132 + d];
                float v1 = stg[(n0 + 1) * 132 + d];
                __nv_bfloat16 h0 = __float2bfloat16(v0), h1 = __float2bfloat16(v1);
                hp[jj] = pk(h0, h1);
                lp[jj] = pk(__float2bfloat16(v0 - __bfloat162float(h0)),
                            __float2bfloat16(v1 - __bfloat162float(h1)));
            }
            uint32_t o = bswz(d, g * 8, 16);
            *(uint4*)(smem + VTHI + o) = make_uint4(hp[0], hp[1], hp[2], hp[3]);
            *(uint4*)(smem + VTLO + o) = make_uint4(lp[0], lp[1], lp[2], lp[3]);
        }
        __syncthreads();
        {
            uint4* dh = (uint4*)(g_vThi + ((size_t)(h * 32 + c)) * 32768 + half * 16384);
            uint4* dl = (uint4*)(g_vTlo + ((size_t)(h * 32 + c)) * 32768 + half * 16384);
            const uint4* sh = (const uint4*)(smem + VTHI);
            const uint4* sl = (const uint4*)(smem + VTLO);
            #pragma unroll
            for (int it = 0; it < 8; it++) {
                int j = it * 256 + tid;
                dh[j] = sh[j];
                dl[j] = sl[j];
            }
        }
        FENCE_ASYNC_SHARED();
        __syncthreads();
        if (tid < 32) {
            uint64_t dVh = MAKE_SMEM_DESC(sb + VTHI), dVl = MAKE_SMEM_DESC(sb + VTLO);
            uint64_t dKh = MAKE_SMEM_DESC(sb + KTHI), dKl = MAKE_SMEM_DESC(sb + KTLO);
            if (elect_one_pred()) {
                #pragma unroll
                for (int st = 0; st < 8; st++) {
                    uint32_t u = ((st >> 2) << 10) + ((st & 3) << 1);
                    bool first = (half == 0 && st == 0);
                    mma_f16_ss(tmem, dVh + u, dKh + u, IDESC128, !first);
                    mma_f16_ss(tmem, dVh + u, dKl + u, IDESC128, true);
                    mma_f16_ss(tmem, dVl + u, dKh + u, IDESC128, true);
                }
                TCGEN05_COMMIT(mb);
            }
        }
    }
    MBARRIER_WAIT_PARITY(mb, 1);
    TCGEN05_FENCE_AFTER();
    __syncthreads();
    if (tid < 128) {
        int w = tid >> 5, l = tid & 31, e = w * 32 + l;
        float* dst = g_kvblk + ((size_t)(h * 32 + c)) * 16384 + (size_t)e * 128;
        #pragma unroll
        for (int cb = 0; cb < 4; cb++) {
            uint32_t r[32];
            TCGEN05_LD_X32(r, tmem + cb * 32);
            TCGEN05_WAIT_LD();
            #pragma unroll
            for (int j = 0; j < 32; j += 4)
                *(float4*)&dst[cb * 32 + j] = make_float4(
                    __uint_as_float(r[j]), __uint_as_float(r[j + 1]),
                    __uint_as_float(r[j + 2]), __uint_as_float(r[j + 3]));
        }
    }
    __syncthreads();
    if (tid < 32) TCGEN05_DEALLOC(tmem, 128);
#else
    int h = blockIdx.x & 15, c = blockIdx.x >> 4;
    float s = g_slopes[h];
    for (int idx = threadIdx.x; idx < 16384; idx += 256) {
        int e = idx >> 7, d = idx & 127;
        float acc = 0.f;
        for (int n = 0; n < 256; n++) {
            size_t t = (size_t)(c * 256 + n) * QKVW + (size_t)h * DH;
            acc += expf(-s * (float)(255 - n)) * g_qkv[t + 2048 + d] * g_qkv[t + 4096 + e];
        }
        g_kvblk[((size_t)(h * 32 + c)) * 16384 + (size_t)e * 128 + d] = acc;
    }
#endif
}

// ============ Phase B: decay scan — 256 CTAs ================================
__global__ void kvscan_kernel() {
    int h = blockIdx.x >> 4;
    int seg = blockIdx.x & 15;
    float bdec = expf(-g_slopes[h] * 256.0f);
    int e = seg * 1024 + threadIdx.x;
    #pragma unroll
    for (int r = 0; r < 4; r++, e += 256) {
        float acc = 0.f;
        size_t base = (size_t)h * NCHUNK * 16384 + e;
        #pragma unroll
        for (int c = 0; c < NCHUNK; c++) {
            g_kvstate[base + (size_t)c * 16384] = acc;
            acc = bdec * acc + g_kvblk[base + (size_t)c * 16384];
        }
    }
}

// ============ Phase C: attention output (tensor, bf16x3 — unchanged) ========
__global__ __launch_bounds__(256, 1) void attn_tensor_kernel() {
#if HAS_TCGEN05
    extern __shared__ char smem[];
    uint32_t sb = smem_to_u32(smem);
    int tid = threadIdx.x;
    int mi = blockIdx.x & 1, c = (blockIdx.x >> 1) & 31, h = blockIdx.x >> 6;
    float s = g_slopes[h];
    float* decay_tab = (float*)(smem + 16);
    const int QHI = 2048,  QLO = 34816;
    const int KVHI = 67584, KVLO = 100352;
    const int KHI = 67584,  KLO = 83968;
    const int VHI = 100352, VLO = 116736;
    const int SHI = 133120, SLO = 149504;
    uint32_t mb = sb + 8;
    if (tid < 32) TCGEN05_ALLOC(sb, 512);
    if (tid == 0) MBARRIER_INIT(mb, 1);
    for (int i = tid; i < 257; i += 256) decay_tab[i] = expf(-s * (float)i);
    __syncthreads();
    uint32_t tmem;
    asm volatile("ld.shared.b32 %0, [%1];" : "=r"(tmem) : "r"(sb));
    if (tid < 32) TCGEN05_RELINQ();
    const uint32_t O1T = tmem, O2T = tmem + 128, ST = tmem + 256;
    const uint32_t IDESC128 = (1u << 4) | (1u << 7) | (1u << 10) | (16u << 17) | (8u << 24);
    const uint32_t IDESC64  = (1u << 4) | (1u << 7) | (1u << 10) | (8u  << 17) | (8u << 24);

    const float* qb = g_qkv + (size_t)(c * 256 + mi * 128) * QKVW + (size_t)h * DH;
    #pragma unroll
    for (int it = 0; it < 16; it++) {
        int j = it * 256 + tid;
        int r = j >> 5, dq = (j & 31) << 2;
        float4 v = *(const float4*)&qb[(size_t)r * QKVW + dq];
        __nv_bfloat16 h0 = __float2bfloat16(v.x), h1 = __float2bfloat16(v.y);
        __nv_bfloat16 h2 = __float2bfloat16(v.z), h3 = __float2bfloat16(v.w);
        uint32_t o = bswz(r, dq, 16);
        *(uint2*)(smem + QHI + o) = make_uint2(pk(h0, h1), pk(h2, h3));
        *(uint2*)(smem + QLO + o) = make_uint2(
            pk(__float2bfloat16(v.x - __bfloat162float(h0)), __float2bfloat16(v.y - __bfloat162float(h1))),
            pk(__float2bfloat16(v.z - __bfloat162float(h2)), __float2bfloat16(v.w - __bfloat162float(h3))));
    }
    const float* kvb = g_kvstate + (size_t)(h * 32 + c) * 16384;
    #pragma unroll
    for (int it = 0; it < 16; it++) {
        int j = it * 256 + tid;
        int r = j >> 5, dq = (j & 31) << 2;
        float4 v = *(const float4*)&kvb[(size_t)r * 128 + dq];
        __nv_bfloat16 h0 = __float2bfloat16(v.x), h1 = __float2bfloat16(v.y);
        __nv_bfloat16 h2 = __float2bfloat16(v.z), h3 = __float2bfloat16(v.w);
        uint32_t o = bswz(r, dq, 16);
        *(uint2*)(smem + KVHI + o) = make_uint2(pk(h0, h1), pk(h2, h3));
        *(uint2*)(smem + KVLO + o) = make_uint2(
            pk(__float2bfloat16(v.x - __bfloat162float(h0)), __float2bfloat16(v.y - __bfloat162float(h1))),
            pk(__float2bfloat16(v.z - __bfloat162float(h2)), __float2bfloat16(v.w - __bfloat162float(h3))));
    }
    FENCE_ASYNC_SHARED();
    __syncthreads();
    int ph = 0;
    if (tid < 32) {
        uint64_t dQh = MAKE_SMEM_DESC(sb + QHI), dQl = MAKE_SMEM_DESC(sb + QLO);
        uint64_t dKh = MAKE_SMEM_DESC(sb + KVHI), dKl = MAKE_SMEM_DESC(sb + KVLO);
        if (elect_one_pred()) {
            #pragma unroll
            for (int st = 0; st < 8; st++) {
                uint32_t u = ((st >> 2) << 10) + ((st & 3) << 1);
                mma_f16_ss(O1T, dQh + u, dKh + u, IDESC128, st != 0);
                mma_f16_ss(O1T, dQh + u, dKl + u, IDESC128, true);
                mma_f16_ss(O1T, dQl + u, dKh + u, IDESC128, true);
            }
            TCGEN05_COMMIT(mb);
        }
    }
    MBARRIER_WAIT_PARITY(mb, ph & 1); ph++;

    const int nch = 2 * mi + 2;
    for (int cn = 0; cn < nch; cn++) {
        const float* kb = g_qkv + (size_t)(c * 256 + cn * 64) * QKVW + 2048 + (size_t)h * DH;
        #pragma unroll
        for (int it = 0; it < 8; it++) {
            int j = it * 256 + tid;
            int r = j >> 5, dq = (j & 31) << 2;
            float4 v = *(const float4*)&kb[(size_t)r * QKVW + dq];
            __nv_bfloat16 h0 = __float2bfloat16(v.x), h1 = __float2bfloat16(v.y);
            __nv_bfloat16 h2 = __float2bfloat16(v.z), h3 = __float2bfloat16(v.w);
            uint32_t o = bswz(r, dq, 8);
            *(uint2*)(smem + KHI + o) = make_uint2(pk(h0, h1), pk(h2, h3));
            *(uint2*)(smem + KLO + o) = make_uint2(
                pk(__float2bfloat16(v.x - __bfloat162float(h0)), __float2bfloat16(v.y - __bfloat162float(h1))),
                pk(__float2bfloat16(v.z - __bfloat162float(h2)), __float2bfloat16(v.w - __bfloat162float(h3))));
        }
        {
            const uint4* sh = (const uint4*)(g_vThi + (size_t)(h * 32 + c) * 32768 + cn * 8192);
            const uint4* sl = (const uint4*)(g_vTlo + (size_t)(h * 32 + c) * 32768 + cn * 8192);
            uint4* dh = (uint4*)(smem + VHI);
            uint4* dl = (uint4*)(smem + VLO);
            #pragma unroll
            for (int it = 0; it < 4; it++) {
                int j = it * 256 + tid;
                dh[j] = sh[j];
                dl[j] = sl[j];
            }
        }
        FENCE_ASYNC_SHARED();
        __syncthreads();
        if (tid < 32) {
            uint64_t dQh = MAKE_SMEM_DESC(sb + QHI), dQl = MAKE_SMEM_DESC(sb + QLO);
            uint64_t dKh = MAKE_SMEM_DESC(sb + KHI), dKl = MAKE_SMEM_DESC(sb + KLO);
            if (elect_one_pred()) {
                #pragma unroll
                for (int st = 0; st < 8; st++) {
                    uint32_t uq = ((st >> 2) << 10) + ((st & 3) << 1);
                    uint32_t uk = ((st >> 2) << 9) + ((st & 3) << 1);
                    mma_f16_ss(ST, dQh + uq, dKh + uk, IDESC64, st != 0);
                    mma_f16_ss(ST, dQh + uq, dKl + uk, IDESC64, true);
                    mma_f16_ss(ST, dQl + uq, dKh + uk, IDESC64, true);
                }
                TCGEN05_COMMIT(mb);
            }
        }
        MBARRIER_WAIT_PARITY(mb, ph & 1); ph++;
        TCGEN05_FENCE_AFTER();
        if (tid < 128) {
            int w = tid >> 5, l = tid & 31, m = w * 32 + l;
            int gm = mi * 128 + m;
            uint32_t r0[32], r1[32];
            TCGEN05_LD_X32(r0, ST);
            TCGEN05_WAIT_LD();
            TCGEN05_LD_X32(r1, ST + 32);
            TCGEN05_WAIT_LD();
            #pragma unroll
            for (int g = 0; g < 8; g++) {
                uint32_t hp[4], lp[4];
                #pragma unroll
                for (int jj = 0; jj < 4; jj++) {
                    int j0 = g * 8 + jj * 2;
                    float v0 = __uint_as_float(j0 < 32 ? r0[j0] : r1[j0 - 32]);
                    float v1 = __uint_as_float((j0 + 1) < 32 ? r0[j0 + 1] : r1[j0 - 31]);
                    int gn0 = cn * 64 + j0;
                    v0 = (gm >= gn0)     ? v0 * decay_tab[gm - gn0]     : 0.f;
                    v1 = (gm >= gn0 + 1) ? v1 * decay_tab[gm - gn0 - 1] : 0.f;
                    __nv_bfloat16 h0 = __float2bfloat16(v0), h1 = __float2bfloat16(v1);
                    hp[jj] = pk(h0, h1);
                    lp[jj] = pk(__float2bfloat16(v0 - __bfloat162float(h0)),
                                __float2bfloat16(v1 - __bfloat162float(h1)));
                }
                uint32_t o = bswz(m, g * 8, 16);
                *(uint4*)(smem + SHI + o) = make_uint4(hp[0], hp[1], hp[2], hp[3]);
                *(uint4*)(smem + SLO + o) = make_uint4(lp[0], lp[1], lp[2], lp[3]);
            }
        }
        FENCE_ASYNC_SHARED();
        __syncthreads();
        if (tid < 32) {
            uint64_t dSh = MAKE_SMEM_DESC(sb + SHI), dSl = MAKE_SMEM_DESC(sb + SLO);
            uint64_t dVh = MAKE_SMEM_DESC(sb + VHI), dVl = MAKE_SMEM_DESC(sb + VLO);
            if (elect_one_pred()) {
                #pragma unroll
                for (int st = 0; st < 4; st++) {
                    uint32_t u = (uint32_t)st << 1;
                    bool first = (cn == 0 && st == 0);
                    mma_f16_ss(O2T, dSh + u, dVh + u, IDESC128, !first);
                    mma_f16_ss(O2T, dSh + u, dVl + u, IDESC128, true);
                    mma_f16_ss(O2T, dSl + u, dVh + u, IDESC128, true);
                }
                TCGEN05_COMMIT(mb);
            }
        }
        MBARRIER_WAIT_PARITY(mb, ph & 1); ph++;
    }
    TCGEN05_FENCE_AFTER();
    if (tid < 128) {
        int w = tid >> 5, l = tid & 31, m = w * 32 + l;
        int gm = mi * 128 + m;
        float qd = decay_tab[gm + 1];
        float* dst = g_attn + (size_t)(c * 256 + gm) * HIDDEN + (size_t)h * DH;
        #pragma unroll
        for (int cb = 0; cb < 4; cb++) {
            uint32_t a[32], b[32];
            TCGEN05_LD_X32(a, O1T + cb * 32);
            TCGEN05_WAIT_LD();
            TCGEN05_LD_X32(b, O2T + cb * 32);
            TCGEN05_WAIT_LD();
            #pragma unroll
            for (int j = 0; j < 32; j += 4)
                *(float4*)&dst[cb * 32 + j] = make_float4(
                    qd * __uint_as_float(a[j])     + __uint_as_float(b[j]),
                    qd * __uint_as_float(a[j + 1]) + __uint_as_float(b[j + 1]),
                    qd * __uint_as_float(a[j + 2]) + __uint_as_float(b[j + 2]),
                    qd * __uint_as_float(a[j + 3]) + __uint_as_float(b[j + 3]));
        }
    }
    __syncthreads();
    if (tid < 32) TCGEN05_DEALLOC(tmem, 512);
#else
    int mi = blockIdx.x & 1, c = (blockIdx.x >> 1) & 31, h = blockIdx.x >> 6;
    float s = g_slopes[h];
    const float* kvst = g_kvstate + (size_t)(h * 32 + c) * 16384;
    for (int idx = threadIdx.x; idx < 16384; idx += 256) {
        int m = idx >> 7, e = idx & 127;
        int gm = mi * 128 + m;
        size_t tq = (size_t)(c * 256 + gm) * QKVW + (size_t)h * DH;
        float o = 0.f;
        for (int d = 0; d < 128; d++) o += g_qkv[tq + d] * kvst[(size_t)e * 128 + d];
        o *= expf(-s * (float)(gm + 1));
        for (int n = 0; n <= gm; n++) {
            size_t tk = (size_t)(c * 256 + n) * QKVW + (size_t)h * DH;
            float qk = 0.f;
            for (int d = 0; d < 128; d++) qk += g_qkv[tq + d] * g_qkv[tk + 2048 + d];
            o += expf(-s * (float)(gm - n)) * qk * g_qkv[tk + 4096 + e];
        }
        g_attn[(size_t)(c * 256 + gm) * HIDDEN + (size_t)h * DH + e] = o;
    }
#endif
}

// ============ RMS norm + sigmoid gate -> fp16 output ========================
__global__ void rmsgate_kernel(const float* __restrict__ gnw) {
    int t = blockIdx.x;
    int tid = threadIdx.x;
    const float* a = g_attn + (size_t)t * HIDDEN;
    const float* g = g_gate + (size_t)t * HIDDEN;
    float ss = 0.f;
    for (int j = tid; j < HIDDEN; j += 256) { float v = a[j]; ss += v * v; }
    #pragma unroll
    for (int o = 16; o; o >>= 1) ss += __shfl_xor_sync(0xffffffffu, ss, o);
    __shared__ float red[8];
    __shared__ float tot;
    if ((tid & 31) == 0) red[tid >> 5] = ss;
    __syncthreads();
    if (tid == 0) {
        float tsum = 0.f;
        #pragma unroll
        for (int w = 0; w < 8; w++) tsum += red[w];
        tot = tsum;
    }
    __syncthreads();
    float rms = rsqrtf(tot * (1.0f / HIDDEN) + 1e-5f);
    for (int j = tid; j < HIDDEN; j += 256) {
        float gv = g[j];
        float sig = 1.0f / (1.0f + expf(-gv));
        float val = a[j] * rms * gnw[j] * sig;
        g_yh[(size_t)t * HIDDEN + j] = __float2half_rn(val);
    }
}

// ================= launch =====================================================
extern "C" void kernel_launch(void* const* d_in, const int* in_sizes, int n_in,
                              void* d_out, int out_size) {
    const float* hidden    = (const float*)d_in[0];
    const int*   positions = (const int*)d_in[1];
    const float* Wqkv      = (const float*)d_in[2];
    const float* Wg        = (const float*)d_in[3];
    const float* Wd        = (const float*)d_in[4];
    const float* gnw       = (const float*)d_in[5];
    float* out = (float*)d_out;

    void *ah_p, *yh_p;
    void *bqh_p, *bql_p, *bgh_p, *bgl_p, *bdh_p, *bdl_p;
    cudaGetSymbolAddress(&ah_p, g_ah);
    cudaGetSymbolAddress(&yh_p, g_yh);
    cudaGetSymbolAddress(&bqh_p, g_bqkv_hi); cudaGetSymbolAddress(&bql_p, g_bqkv_lo);
    cudaGetSymbolAddress(&bgh_p, g_bg_hi);   cudaGetSymbolAddress(&bgl_p, g_bg_lo);
    cudaGetSymbolAddress(&bdh_p, g_bd_hi);   cudaGetSymbolAddress(&bdl_p, g_bd_lo);

    cudaFuncSetAttribute(gemm_qkvgate, cudaFuncAttributeMaxDynamicSharedMemorySize, CG2_SMEM);
    cudaFuncSetAttribute(gemm_down, cudaFuncAttributeMaxDynamicSharedMemorySize, CG2_SMEM);
    const int kvblk_smem = 2048 + 67584 + 4 * 32768;
    cudaFuncSetAttribute(kvblkT_kernel, cudaFuncAttributeMaxDynamicSharedMemorySize, kvblk_smem);
    const int attn_smem = 149504 + 16384;
    cudaFuncSetAttribute(attn_tensor_kernel, cudaFuncAttributeMaxDynamicSharedMemorySize, attn_smem);

    init_tables<<<1, 64>>>();
    conv_act<<<(NTOK * HIDDEN / 4 + 255) / 256, 256>>>(hidden, (__half*)ah_p,
                                                       NTOK * HIDDEN / 4);
    transposeW<<<dim3(QKVW / 32, HIDDEN / 32), 256>>>(Wqkv,
        (__half*)bqh_p, (__half*)bql_p, HIDDEN, QKVW);
    transposeW<<<dim3(HIDDEN / 32, HIDDEN / 32), 256>>>(Wg,
        (__half*)bgh_p, (__half*)bgl_p, HIDDEN, HIDDEN);
    transposeW<<<dim3(HIDDEN / 32, HIDDEN / 32), 256>>>(Wd,
        (__half*)bdh_p, (__half*)bdl_p, HIDDEN, HIDDEN);
    gemm_qkvgate<<<dim3(((QKVW + HIDDEN) / 256) * 2, NTOK / 256), 256, CG2_SMEM>>>(
        (const __half*)ah_p, positions);
    kvblkT_kernel<<<HEADS * NCHUNK, 256, kvblk_smem>>>();
    kvscan_kernel<<<HEADS * 16, 256>>>();
    attn_tensor_kernel<<<HEADS * NCHUNK * 2, 256, attn_smem>>>();
    rmsgate_kernel<<<NTOK, 256>>>(gnw);
    gemm_down<<<dim3((HIDDEN / 256) * 2, NTOK / 256), 256, CG2_SMEM>>>(
        (const __half*)yh_p,
        (const __half*)bdh_p, (const __half*)bdl_p,
        out, HIDDEN, HIDDEN);
}

// round 11
// speedup vs baseline: 1.0842x; 1.0842x over previous
#include <cuda_runtime.h>
#include <cuda_bf16.h>
#include <cuda_fp16.h>
#include <math.h>
#include <cstdint>

#define NTOK 8192
#define HIDDEN 2048
#define HEADS 16
#define DH 128
#define BLK 256
#define NCHUNK 32
#define QKVW 6144

#if defined(__CUDA_ARCH_FEAT_SM103_ALL) || \
    (defined(__CUDA_ARCH_SPECIFIC__) && (__CUDA_ARCH_SPECIFIC__ == 1030)) || \
    (defined(__CUDA_ARCH_FAMILY_SPECIFIC__) && (__CUDA_ARCH_FAMILY_SPECIFIC__ == 1030))
#define HAS_TCGEN05 1
#else
#define HAS_TCGEN05 0
#endif

// ================= PTX helpers ==============================================
__device__ __forceinline__ uint32_t elect_one_pred() {
    uint32_t pred;
    asm volatile("{\n\t.reg .pred p;\n\telect.sync _|p, 0xFFFFFFFF;\n\t"
                 "selp.b32 %0, 1, 0, p;\n\t}" : "=r"(pred));
    return pred;
}
__device__ __forceinline__ uint32_t smem_to_u32(const void* p) {
    uint32_t a;
    asm("{ .reg .u64 t; cvta.to.shared.u64 t, %1; cvt.u32.u64 %0, t; }"
        : "=r"(a) : "l"(p));
    return a;
}
__device__ __forceinline__ uint32_t cluster_rank() {
    uint32_t r;
    asm("mov.u32 %0, %%cluster_ctarank;" : "=r"(r));
    return r;
}
#define CLUSTER_SYNC() do { \
    asm volatile("barrier.cluster.arrive.aligned;" ::: "memory"); \
    asm volatile("barrier.cluster.wait.aligned;" ::: "memory"); \
} while (0)
#define MBARRIER_INIT(addr, cnt) \
    asm volatile("mbarrier.init.shared.b64 [%0], %1;" :: "r"((uint32_t)(addr)), "r"((uint32_t)(cnt)) : "memory")
#define MBARRIER_WAIT_PARITY(addr, par) do { \
    uint32_t _m = (uint32_t)(addr); uint32_t _p = (uint32_t)(par); uint32_t _d; \
    asm volatile("{\n\t.reg .pred p;\n\t" \
        "mbarrier.try_wait.parity.acquire.cta.shared::cta.b64 p, [%1], %2;\n\t" \
        "selp.b32 %0, 1, 0, p;\n\t}" : "=r"(_d) : "r"(_m), "r"(_p) : "memory"); \
    if (!_d) { \
        asm volatile("{\n\t.reg .pred P1;\n\t" \
            "WL_%=:\n\t" \
            "mbarrier.try_wait.parity.acquire.cta.shared::cta.b64 P1, [%0], %1, 0x989680;\n\t" \
            "@P1 bra.uni WD_%=;\n\tbra.uni WL_%=;\n\tWD_%=:\n\t}" \
            :: "r"(_m), "r"(_p) : "memory"); \
    } } while (0)
#define MBARRIER_WAIT_PARITY_CL(addr, par) do { \
    uint32_t _m = (uint32_t)(addr); uint32_t _p = (uint32_t)(par); uint32_t _d; \
    asm volatile("{\n\t.reg .pred p;\n\t" \
        "mbarrier.try_wait.parity.acquire.cluster.shared::cta.b64 p, [%1], %2;\n\t" \
        "selp.b32 %0, 1, 0, p;\n\t}" : "=r"(_d) : "r"(_m), "r"(_p) : "memory"); \
    if (!_d) { \
        asm volatile("{\n\t.reg .pred P1;\n\t" \
            "WL_%=:\n\t" \
            "mbarrier.try_wait.parity.acquire.cluster.shared::cta.b64 P1, [%0], %1, 0x989680;\n\t" \
            "@P1 bra.uni WD_%=;\n\tbra.uni WL_%=;\n\tWD_%=:\n\t}" \
            :: "r"(_m), "r"(_p) : "memory"); \
    } } while (0)
#define MBARRIER_ARRIVE_CLUSTER(local_addr, target_rank) \
    asm volatile( \
        "{\n\t.reg .b32 remAddr32;\n\t" \
        "mapa.shared::cluster.u32 remAddr32, %0, %1;\n\t" \
        "mbarrier.arrive.release.cluster.shared::cluster.b64 _, [remAddr32];\n\t}" \
        :: "r"((uint32_t)(local_addr)), "r"((uint32_t)(target_rank)) : "memory")
#define TCGEN05_ALLOC(smem_addr, n) \
    asm volatile("tcgen05.alloc.cta_group::1.sync.aligned.shared::cta.b32 [%0], %1;" \
        :: "r"((uint32_t)(smem_addr)), "r"((uint32_t)(n)) : "memory")
#define TCGEN05_DEALLOC(tmem, n) \
    asm volatile("tcgen05.dealloc.cta_group::1.sync.aligned.b32 %0, %1;" :: "r"(tmem), "r"((uint32_t)(n)))
#define TCGEN05_RELINQ() \
    asm volatile("tcgen05.relinquish_alloc_permit.cta_group::1.sync.aligned;")
#define TCGEN05_ALLOC_CG2(smem_addr, n) \
    asm volatile("tcgen05.alloc.cta_group::2.sync.aligned.shared::cta.b32 [%0], %1;" \
        :: "r"((uint32_t)(smem_addr)), "r"((uint32_t)(n)) : "memory")
#define TCGEN05_DEALLOC_CG2(tmem, n) \
    asm volatile("tcgen05.dealloc.cta_group::2.sync.aligned.b32 %0, %1;" :: "r"(tmem), "r"((uint32_t)(n)))
#define TCGEN05_RELINQ_CG2() \
    asm volatile("tcgen05.relinquish_alloc_permit.cta_group::2.sync.aligned;")
#define TCGEN05_COMMIT(mbar) \
    asm volatile("tcgen05.commit.cta_group::1.mbarrier::arrive::one.shared::cluster.b64 [%0];" \
        :: "r"((uint32_t)(mbar)) : "memory")
#define TCGEN05_COMMIT_MC_CG2(mbar, mask) \
    asm volatile("tcgen05.commit.cta_group::2.mbarrier::arrive::one.shared::cluster.multicast::cluster.b64 [%0], %1;" \
        :: "r"((uint32_t)(mbar)), "h"((uint16_t)(mask)) : "memory")
#define TCGEN05_FENCE_AFTER() asm volatile("tcgen05.fence::after_thread_sync;" ::: "memory")
#define TCGEN05_WAIT_LD() asm volatile("tcgen05.wait::ld.sync.aligned;" ::: "memory")
#define FENCE_ASYNC_SHARED() asm volatile("fence.proxy.async.shared::cta;" ::: "memory")
#define TCGEN05_LD_X32(r, addr) \
    asm volatile("tcgen05.ld.sync.aligned.32x32b.x32.b32 " \
        "{%0, %1, %2, %3, %4, %5, %6, %7, %8, %9, %10, %11, %12, %13, %14, %15, " \
        " %16, %17, %18, %19, %20, %21, %22, %23, %24, %25, %26, %27, %28, %29, %30, %31}, [%32];" \
        : "=r"((r)[0]),  "=r"((r)[1]),  "=r"((r)[2]),  "=r"((r)[3]), \
          "=r"((r)[4]),  "=r"((r)[5]),  "=r"((r)[6]),  "=r"((r)[7]), \
          "=r"((r)[8]),  "=r"((r)[9]),  "=r"((r)[10]), "=r"((r)[11]), \
          "=r"((r)[12]), "=r"((r)[13]), "=r"((r)[14]), "=r"((r)[15]), \
          "=r"((r)[16]), "=r"((r)[17]), "=r"((r)[18]), "=r"((r)[19]), \
          "=r"((r)[20]), "=r"((r)[21]), "=r"((r)[22]), "=r"((r)[23]), \
          "=r"((r)[24]), "=r"((r)[25]), "=r"((r)[26]), "=r"((r)[27]), \
          "=r"((r)[28]), "=r"((r)[29]), "=r"((r)[30]), "=r"((r)[31]) \
        : "r"(addr))

static constexpr uint64_t SMEM_DESC_BASE_SW128 =
    (uint64_t(2) << 61) | (uint64_t(1) << 46) | (uint64_t(64) << 32) | (uint64_t(1) << 16);
#define MAKE_SMEM_DESC(a) (SMEM_DESC_BASE_SW128 | ((uint64_t)((a) >> 4) & 0x3FFF))

#if HAS_TCGEN05
__device__ __forceinline__ void mma_f16_ss(uint32_t d_tmem, uint64_t a_desc,
                                           uint64_t b_desc, uint32_t idesc, bool acc) {
    uint32_t en = acc ? 1u : 0u;
    asm volatile(
        "{\n\t.reg .pred p;\n\tsetp.ne.u32 p, %5, 0;\n\t"
        "tcgen05.mma.cta_group::1.kind::f16 [%0], %1, %2, %3, {%4, %4, %4, %4}, p;\n\t}"
        :: "r"(d_tmem), "l"(a_desc), "l"(b_desc), "r"(idesc), "r"(0u), "r"(en)
        : "memory");
}
__device__ __forceinline__ void mma_f16_ss_cg2(uint32_t d_tmem, uint64_t a_desc,
                                               uint64_t b_desc, uint32_t idesc, bool acc) {
    uint32_t en = acc ? 1u : 0u;
    asm volatile(
        "{\n\t.reg .pred p;\n\tsetp.ne.u32 p, %5, 0;\n\t"
        "tcgen05.mma.cta_group::2.kind::f16 [%0], %1, %2, %3, "
        "{%4, %4, %4, %4, %4, %4, %4, %4}, p;\n\t}"
        :: "r"(d_tmem), "l"(a_desc), "l"(b_desc), "r"(idesc), "r"(0u), "r"(en)
        : "memory");
}
#endif

__device__ __forceinline__ uint32_t bswz(int row, int col, int atomrows) {
    uint32_t off = (uint32_t)(((row >> 3) + (col >> 6) * atomrows) << 10)
                 + ((row & 7) << 7) + ((col & 63) << 1);
    return off ^ ((off >> 3) & 0x70);
}
__device__ __forceinline__ uint32_t pk(__nv_bfloat16 a, __nv_bfloat16 b) {
    __nv_bfloat162 t{a, b};
    return *(uint32_t*)&t;
}

// ================= scratch ===================================================
__device__ float g_qkv[(size_t)NTOK * QKVW];
__device__ float g_gate[(size_t)NTOK * HIDDEN];
__device__ float g_attn[(size_t)NTOK * HIDDEN];
__device__ float g_kvblk[(size_t)HEADS * NCHUNK * DH * DH];
__device__ float g_kvstate[(size_t)HEADS * NCHUNK * DH * DH];
__device__ float g_invf[64];
__device__ float g_slopes[HEADS];
__device__ __nv_bfloat16 g_vThi[(size_t)HEADS * NCHUNK * 32768];
__device__ __nv_bfloat16 g_vTlo[(size_t)HEADS * NCHUNK * 32768];
__device__ __half g_ah[(size_t)NTOK * HIDDEN];
__device__ __half g_yh[(size_t)NTOK * HIDDEN];
__device__ __half g_bqkv_hi[(size_t)QKVW * HIDDEN];
__device__ __half g_bqkv_lo[(size_t)QKVW * HIDDEN];
__device__ __half g_bg_hi[(size_t)HIDDEN * HIDDEN];
__device__ __half g_bg_lo[(size_t)HIDDEN * HIDDEN];
__device__ __half g_bd_hi[(size_t)HIDDEN * HIDDEN];
__device__ __half g_bd_lo[(size_t)HIDDEN * HIDDEN];

// ================= init tables ================================================
__global__ void init_tables() {
    int t = threadIdx.x;
    if (t < 64) g_invf[t] = (float)pow(600000.0, -(double)t / 64.0);
    if (t < HEADS) {
        double start = pow(2.0, -pow(2.0, -(log2(16.0) - 3.0)));
        g_slopes[t] = (float)(start * pow(start, (double)t) * (1.0 + 1e-5));
    }
}

// ================= convert fp32 -> fp16 (A operand, single) =================
__global__ void conv_act(const float* __restrict__ x, __half* __restrict__ h, int n4) {
    int i = blockIdx.x * blockDim.x + threadIdx.x;
    if (i >= n4) return;
    float4 v = ((const float4*)x)[i];
    __half2 a{__float2half_rn(v.x), __float2half_rn(v.y)};
    __half2 b{__float2half_rn(v.z), __float2half_rn(v.w)};
    ((__half2*)h)[i * 2]     = a;
    ((__half2*)h)[i * 2 + 1] = b;
}

// ======= transpose + split W[K,N] fp32 -> Thi/Tlo [N,K] fp16 ================
__global__ void transposeW(const float* __restrict__ W, __half* __restrict__ Thi,
                           __half* __restrict__ Tlo, int K, int N) {
    __shared__ float t[32][33];
    int n0 = blockIdx.x * 32, k0 = blockIdx.y * 32;
    int c = threadIdx.x & 31, r0 = threadIdx.x >> 5;
    #pragma unroll
    for (int rr = r0; rr < 32; rr += 8)
        t[rr][c] = W[(size_t)(k0 + rr) * N + n0 + c];
    __syncthreads();
    #pragma unroll
    for (int rr = r0; rr < 32; rr += 8) {
        float v = t[c][rr];
        __half h = __float2half_rn(v);
        Thi[(size_t)(n0 + rr) * K + k0 + c] = h;
        Tlo[(size_t)(n0 + rr) * K + k0 + c] = __float2half_rn(v - __half2float(h));
    }
}

#if HAS_TCGEN05
template <int ROWS>
__device__ __forceinline__ void load_tile(char* dst, const __half* src, int ld) {
    int tid = threadIdx.x;
    #pragma unroll
    for (int l = 0; l < ROWS / 32; l++) {
        int i = l * 256 + tid;
        int r = i >> 3, sg = i & 7;
        uint4 v = *(const uint4*)(src + (size_t)r * ld + sg * 8);
        uint32_t off = (uint32_t)(r * 128 + sg * 16);
        off ^= (off >> 3) & 0x70;
        *(uint4*)(dst + off) = v;
    }
}
#endif

// ======= cg2 fp16 GEMM constants (K-chunk 64, R9 structure) ==================
// per-buffer: A 16K | Bhi 16K | Blo 16K = 48KB; x2 buffers
#define CG2_BUF 49152
#define CG2_SMEM (1024 + 2 * CG2_BUF)
#define IDESC_CG2 ((1u << 4) | (32u << 17) | (16u << 24))

// ======= fused qkv+gate GEMM (cg2 fp16; gate B-lo skipped) ===================
__global__ __launch_bounds__(256, 1) __cluster_dims__(2, 1, 1)
void gemm_qkvgate(const __half* __restrict__ A, const int* __restrict__ positions) {
    const int K = HIDDEN;
    uint32_t rank = cluster_rank();
    int bm = blockIdx.y * 256;
    int bn = (blockIdx.x >> 1) * 256;
    int gcs = bn + (int)rank * 128;
    bool isGate = (bn >= QKVW);       // cluster-uniform
    const __half* Bhi = (gcs < QKVW) ? g_bqkv_hi + (size_t)gcs * K
                                     : g_bg_hi + (size_t)(gcs - QKVW) * K;
    const __half* Blo = (gcs < QKVW) ? g_bqkv_lo + (size_t)gcs * K
                                     : g_bg_lo + (size_t)(gcs - QKVW) * K;
#if HAS_TCGEN05
    extern __shared__ char smem[];
    uint32_t sb = smem_to_u32(smem);
    int tid = threadIdx.x;
    const uint32_t dn0 = sb + 8,  dn1 = sb + 16;
    const uint32_t rd0 = sb + 24, rd1 = sb + 32;
    if (tid < 32) TCGEN05_ALLOC_CG2(sb, 256);
    if (tid == 0) {
        MBARRIER_INIT(dn0, 1); MBARRIER_INIT(dn1, 1);
        MBARRIER_INIT(rd0, 2); MBARRIER_INIT(rd1, 2);
    }
    __syncthreads();
    uint32_t tmem;
    asm volatile("ld.shared.b32 %0, [%1];" : "=r"(tmem) : "r"(sb));
    if (tid < 32) TCGEN05_RELINQ_CG2();
    CLUSTER_SYNC();

    const __half* pA = A + (size_t)(bm + rank * 128) * K;

    int phd[2] = {0, 0};
    int phr[2] = {0, 0};
    for (int ch = 0; ch < 32; ch++) {
        int b = ch & 1;
        char* st = smem + 1024 + b * CG2_BUF;
        if (ch >= 2) {
            MBARRIER_WAIT_PARITY_CL(b ? dn1 : dn0, phd[b]);
            phd[b] ^= 1;
        }
        int k0 = ch << 6;
        load_tile<128>(st,         pA + k0,  K);
        load_tile<128>(st + 16384, Bhi + k0, K);
        if (!isGate) load_tile<128>(st + 32768, Blo + k0, K);
        FENCE_ASYNC_SHARED();
        __syncthreads();
        if (tid == 0) MBARRIER_ARRIVE_CLUSTER(b ? rd1 : rd0, 0);
        if (rank == 0 && tid < 32) {
            MBARRIER_WAIT_PARITY_CL(b ? rd1 : rd0, phr[b]);
            phr[b] ^= 1;
            uint32_t sa = sb + 1024 + b * CG2_BUF;
            uint64_t dA  = MAKE_SMEM_DESC(sa);
            uint64_t dBh = MAKE_SMEM_DESC(sa + 16384);
            uint64_t dBl = MAKE_SMEM_DESC(sa + 32768);
            if (elect_one_pred()) {
                #pragma unroll
                for (int k = 0; k < 4; k++) {
                    bool first = (ch == 0) && (k == 0);
                    mma_f16_ss_cg2(tmem, dA + k * 2, dBh + k * 2, IDESC_CG2, !first);
                    if (!isGate)
                        mma_f16_ss_cg2(tmem, dA + k * 2, dBl + k * 2, IDESC_CG2, true);
                }
                TCGEN05_COMMIT_MC_CG2(b ? dn1 : dn0, 0x3);
            }
        }
    }
    MBARRIER_WAIT_PARITY_CL(dn0, phd[0]);
    MBARRIER_WAIT_PARITY_CL(dn1, phd[1]);
    TCGEN05_FENCE_AFTER();
    __syncthreads();

    int w = tid >> 5, l = tid & 31;
    int sub = w & 3;
    int colbase = (w >> 2) * 128;
    int row = bm + (int)rank * 128 + sub * 32 + l;
    int gc0 = bn + colbase;
    bool isQ = gc0 < 2048;
    bool isK = (gc0 >= 2048) && (gc0 < 4096);
    float* dst = (gc0 < QKVW) ? g_qkv + (size_t)row * QKVW + gc0
                              : g_gate + (size_t)row * HIDDEN + (gc0 - QKVW);
    if (isQ || isK) {
        float pos = (float)positions[row];
        float qs = isQ ? 0.08838834764831845f : 1.0f;
        #pragma unroll
        for (int half = 0; half < 2; half++) {
            uint32_t a[32], b[32];
            TCGEN05_LD_X32(a, tmem + colbase + half * 32);
            TCGEN05_WAIT_LD();
            TCGEN05_LD_X32(b, tmem + colbase + half * 32 + 64);
            TCGEN05_WAIT_LD();
            #pragma unroll
            for (int j0 = 0; j0 < 32; j0 += 4) {
                float o1[4], o2[4];
                #pragma unroll
                for (int j = 0; j < 4; j++) {
                    int jin = half * 32 + j0 + j;
                    float f = pos * g_invf[jin];
                    float sv, cv;
                    sincosf(f, &sv, &cv);
                    float x1 = __uint_as_float(a[j0 + j]);
                    float x2 = __uint_as_float(b[j0 + j]);
                    o1[j] = (x1 * cv - x2 * sv) * qs;
                    o2[j] = (x2 * cv + x1 * sv) * qs;
                }
                *(float4*)&dst[half * 32 + j0]      = make_float4(o1[0], o1[1], o1[2], o1[3]);
                *(float4*)&dst[half * 32 + 64 + j0] = make_float4(o2[0], o2[1], o2[2], o2[3]);
            }
        }
    } else {
        #pragma unroll
        for (int cb = 0; cb < 128; cb += 32) {
            uint32_t r[32];
            TCGEN05_LD_X32(r, tmem + colbase + cb);
            TCGEN05_WAIT_LD();
            #pragma unroll
            for (int j = 0; j < 32; j += 4)
                *(float4*)&dst[cb + j] = make_float4(
                    __uint_as_float(r[j]), __uint_as_float(r[j + 1]),
                    __uint_as_float(r[j + 2]), __uint_as_float(r[j + 3]));
        }
    }
    __syncthreads();
    if (tid < 32) TCGEN05_DEALLOC_CG2(tmem, 256);
    CLUSTER_SYNC();
#else
    extern __shared__ char smemraw[];
    float* As = (float*)smemraw;
    float* Bs = As + 16 * 128;
    int tid = threadIdx.x;
    int bmr = bm + (int)rank * 128;
    int ty = tid >> 4, tx = tid & 15;
    float acc[8][16];
    #pragma unroll
    for (int i = 0; i < 8; i++)
        #pragma unroll
        for (int j = 0; j < 16; j++) acc[i][j] = 0.f;
    for (int k0 = 0; k0 < K; k0 += 16) {
        #pragma unroll
        for (int l = 0; l < 8; l++) {
            int i = l * 256 + tid;
            int k = i & 15, m = i >> 4;
            As[k * 128 + m] = __half2float(A[(size_t)(bmr + m) * K + k0 + k]);
        }
        #pragma unroll
        for (int l = 0; l < 16; l++) {
            int i = l * 256 + tid;
            int k = i & 15, n = i >> 4;
            int gc = bn + n;
            const __half* bh = (gc < QKVW) ? g_bqkv_hi + (size_t)gc * K
                                           : g_bg_hi + (size_t)(gc - QKVW) * K;
            const __half* bl = (gc < QKVW) ? g_bqkv_lo + (size_t)gc * K
                                           : g_bg_lo + (size_t)(gc - QKVW) * K;
            float bv = __half2float(bh[k0 + k]);
            if (!isGate) bv += __half2float(bl[k0 + k]);
            Bs[k * 256 + n] = bv;
        }
        __syncthreads();
        #pragma unroll
        for (int kk = 0; kk < 16; kk++) {
            float a[8], b[16];
            #pragma unroll
            for (int i = 0; i < 8; i++) a[i] = As[kk * 128 + ty * 8 + i];
            #pragma unroll
            for (int j = 0; j < 16; j++) b[j] = Bs[kk * 256 + tx * 16 + j];
            #pragma unroll
            for (int i = 0; i < 8; i++)
                #pragma unroll
                for (int j = 0; j < 16; j++) acc[i][j] += a[i] * b[j];
        }
        __syncthreads();
    }
    float* tileS = (float*)smemraw;
    #pragma unroll
    for (int i = 0; i < 8; i++)
        #pragma unroll
        for (int j = 0; j < 16; j++)
            tileS[(ty * 8 + i) * 257 + tx * 16 + j] = acc[i][j];
    __syncthreads();
    {
        int r = tid >> 1, sp = tid & 1;
        int row = bmr + r;
        int gc0 = bn + sp * 128;
        bool isQ = gc0 < 2048;
        bool isK = (gc0 >= 2048) && (gc0 < 4096);
        float* dst = (gc0 < QKVW) ? g_qkv + (size_t)row * QKVW + gc0
                                  : g_gate + (size_t)row * HIDDEN + (gc0 - QKVW);
        const float* src = &tileS[r * 257 + sp * 128];
        if (isQ || isK) {
            float pos = (float)positions[row];
            float qs = isQ ? 0.08838834764831845f : 1.0f;
            for (int j = 0; j < 64; j++) {
                float f = pos * g_invf[j];
                float sv, cv;
                sincosf(f, &sv, &cv);
                float x1 = src[j], x2 = src[j + 64];
                dst[j]      = (x1 * cv - x2 * sv) * qs;
                dst[j + 64] = (x2 * cv + x1 * sv) * qs;
            }
        } else {
            for (int j = 0; j < 128; j++) dst[j] = src[j];
        }
    }
#endif
}

// ================= cg2 fp16 2-term down-projection GEMM (R9 structure) =======
__global__ __launch_bounds__(256, 1) __cluster_dims__(2, 1, 1)
void gemm_down(const __half* __restrict__ A,
               const __half* __restrict__ Bhi, const __half* __restrict__ Blo,
               float* __restrict__ C, int Nn, int K) {
    uint32_t rank = cluster_rank();
    int bm = blockIdx.y * 256;
    int bn = (blockIdx.x >> 1) * 256;
#if HAS_TCGEN05
    extern __shared__ char smem[];
    uint32_t sb = smem_to_u32(smem);
    int tid = threadIdx.x;
    const uint32_t dn0 = sb + 8,  dn1 = sb + 16;
    const uint32_t rd0 = sb + 24, rd1 = sb + 32;
    if (tid < 32) TCGEN05_ALLOC_CG2(sb, 256);
    if (tid == 0) {
        MBARRIER_INIT(dn0, 1); MBARRIER_INIT(dn1, 1);
        MBARRIER_INIT(rd0, 2); MBARRIER_INIT(rd1, 2);
    }
    __syncthreads();
    uint32_t tmem;
    asm volatile("ld.shared.b32 %0, [%1];" : "=r"(tmem) : "r"(sb));
    if (tid < 32) TCGEN05_RELINQ_CG2();
    CLUSTER_SYNC();

    const __half* pA   = A   + (size_t)(bm + rank * 128) * K;
    const __half* pBhi = Bhi + (size_t)(bn + rank * 128) * K;
    const __half* pBlo = Blo + (size_t)(bn + rank * 128) * K;

    int phd[2] = {0, 0};
    int phr[2] = {0, 0};
    const int nch = K >> 6;
    for (int ch = 0; ch < nch; ch++) {
        int b = ch & 1;
        char* st = smem + 1024 + b * CG2_BUF;
        if (ch >= 2) {
            MBARRIER_WAIT_PARITY_CL(b ? dn1 : dn0, phd[b]);
            phd[b] ^= 1;
        }
        int k0 = ch << 6;
        load_tile<128>(st,         pA + k0,   K);
        load_tile<128>(st + 16384, pBhi + k0, K);
        load_tile<128>(st + 32768, pBlo + k0, K);
        FENCE_ASYNC_SHARED();
        __syncthreads();
        if (tid == 0) MBARRIER_ARRIVE_CLUSTER(b ? rd1 : rd0, 0);
        if (rank == 0 && tid < 32) {
            MBARRIER_WAIT_PARITY_CL(b ? rd1 : rd0, phr[b]);
            phr[b] ^= 1;
            uint32_t sa = sb + 1024 + b * CG2_BUF;
            uint64_t dA  = MAKE_SMEM_DESC(sa);
            uint64_t dBh = MAKE_SMEM_DESC(sa + 16384);
            uint64_t dBl = MAKE_SMEM_DESC(sa + 32768);
            if (elect_one_pred()) {
                #pragma unroll
                for (int k = 0; k < 4; k++) {
                    bool first = (ch == 0) && (k == 0);
                    mma_f16_ss_cg2(tmem, dA + k * 2, dBh + k * 2, IDESC_CG2, !first);
                    mma_f16_ss_cg2(tmem, dA + k * 2, dBl + k * 2, IDESC_CG2, true);
                }
                TCGEN05_COMMIT_MC_CG2(b ? dn1 : dn0, 0x3);
            }
        }
    }
    MBARRIER_WAIT_PARITY_CL(dn0, phd[0]);
    MBARRIER_WAIT_PARITY_CL(dn1, phd[1]);
    TCGEN05_FENCE_AFTER();
    __syncthreads();

    int w = tid >> 5, l = tid & 31;
    int sub = w & 3;
    int colbase = (w >> 2) * 128;
    int row = bm + (int)rank * 128 + sub * 32 + l;
    float* dst_row = C + (size_t)row * Nn + bn + colbase;
    #pragma unroll
    for (int cb = 0; cb < 128; cb += 32) {
        uint32_t r[32];
        TCGEN05_LD_X32(r, tmem + colbase + cb);
        TCGEN05_WAIT_LD();
        #pragma unroll
        for (int j = 0; j < 32; j += 4)
            *(float4*)(dst_row + cb + j) = make_float4(
                __uint_as_float(r[j]), __uint_as_float(r[j + 1]),
                __uint_as_float(r[j + 2]), __uint_as_float(r[j + 3]));
    }
    __syncthreads();
    if (tid < 32) TCGEN05_DEALLOC_CG2(tmem, 256);
    CLUSTER_SYNC();
#else
    extern __shared__ char smemraw[];
    float* As = (float*)smemraw;
    float* Bs = As + 16 * 128;
    int tid = threadIdx.x;
    int bmr = bm + (int)rank * 128;
    int ty = tid >> 4, tx = tid & 15;
    float acc[8][16];
    #pragma unroll
    for (int i = 0; i < 8; i++)
        #pragma unroll
        for (int j = 0; j < 16; j++) acc[i][j] = 0.f;
    for (int k0 = 0; k0 < K; k0 += 16) {
        #pragma unroll
        for (int l = 0; l < 8; l++) {
            int i = l * 256 + tid;
            int k = i & 15, m = i >> 4;
            As[k * 128 + m] = __half2float(A[(size_t)(bmr + m) * K + k0 + k]);
        }
        #pragma unroll
        for (int l = 0; l < 16; l++) {
            int i = l * 256 + tid;
            int k = i & 15, n = i >> 4;
            size_t off = (size_t)(bn + n) * K + k0 + k;
            Bs[k * 256 + n] = __half2float(Bhi[off]) + __half2float(Blo[off]);
        }
        __syncthreads();
        #pragma unroll
        for (int kk = 0; kk < 16; kk++) {
            float a[8], b[16];
            #pragma unroll
            for (int i = 0; i < 8; i++) a[i] = As[kk * 128 + ty * 8 + i];
            #pragma unroll
            for (int j = 0; j < 16; j++) b[j] = Bs[kk * 256 + tx * 16 + j];
            #pragma unroll
            for (int i = 0; i < 8; i++)
                #pragma unroll
                for (int j = 0; j < 16; j++) acc[i][j] += a[i] * b[j];
        }
        __syncthreads();
    }
    #pragma unroll
    for (int i = 0; i < 8; i++) {
        size_t off = (size_t)(bmr + ty * 8 + i) * Nn + bn + tx * 16;
        #pragma unroll
        for (int j = 0; j < 16; j += 4)
            *(float4*)&C[off + j] = make_float4(acc[i][j], acc[i][j + 1],
                                                acc[i][j + 2], acc[i][j + 3]);
    }
#endif
}

// ============ Phase A: kvblkT (tensor, bf16x3 — unchanged) ==================
__global__ __launch_bounds__(256, 1) void kvblkT_kernel() {
#if HAS_TCGEN05
    extern __shared__ char smem[];
    uint32_t sb = smem_to_u32(smem);
    int tid = threadIdx.x;
    int h = blockIdx.x & 15, c = blockIdx.x >> 4;
    float s = g_slopes[h];
    float* decay_tab = (float*)(smem + 16);
    const int STG = 2048;
    const int KTHI = STG + 67584;
    const int KTLO = KTHI + 32768;
    const int VTHI = KTLO + 32768;
    const int VTLO = VTHI + 32768;
    uint32_t mb = sb + 8;
    if (tid < 32) TCGEN05_ALLOC(sb, 128);
    if (tid == 0) MBARRIER_INIT(mb, 1);
    for (int i = tid; i < 257; i += 256) decay_tab[i] = expf(-s * (float)i);
    __syncthreads();
    uint32_t tmem;
    asm volatile("ld.shared.b32 %0, [%1];" : "=r"(tmem) : "r"(sb));
    if (tid < 32) TCGEN05_RELINQ();
    float* stg = (float*)(smem + STG);
    const uint32_t IDESC128 = (1u << 4) | (1u << 7) | (1u << 10) | (16u << 17) | (8u << 24);

    for (int half = 0; half < 2; half++) {
        if (half == 1) MBARRIER_WAIT_PARITY(mb, 0);
        const float* kb = g_qkv + (size_t)(c * 256 + half * 128) * QKVW + 2048 + (size_t)h * DH;
        #pragma unroll
        for (int it = 0; it < 16; it++) {
            int j = it * 256 + tid;
            int r = j >> 5, dq = (j & 31) << 2;
            *(float4*)&stg[r * 132 + dq] = *(const float4*)&kb[(size_t)r * QKVW + dq];
        }
        __syncthreads();
        #pragma unroll
        for (int it = 0; it < 8; it++) {
            int t = it * 256 + tid;
            int d = t & 127, g = t >> 7;
            uint32_t hp[4], lp[4];
            #pragma unroll
            for (int jj = 0; jj < 4; jj++) {
                int n0 = g * 8 + jj * 2;
                float v0 = stg[n0 * 132 + d]       * decay_tab[255 - (half * 128 + n0)];
                float v1 = stg[(n0 + 1) * 132 + d] * decay_tab[255 - (half * 128 + n0 + 1)];
                __nv_bfloat16 h0 = __float2bfloat16(v0), h1 = __float2bfloat16(v1);
                hp[jj] = pk(h0, h1);
                lp[jj] = pk(__float2bfloat16(v0 - __bfloat162float(h0)),
                            __float2bfloat16(v1 - __bfloat162float(h1)));
            }
            uint32_t o = bswz(d, g * 8, 16);
            *(uint4*)(smem + KTHI + o) = make_uint4(hp[0], hp[1], hp[2], hp[3]);
            *(uint4*)(smem + KTLO + o) = make_uint4(lp[0], lp[1], lp[2], lp[3]);
        }
        __syncthreads();
        const float* vb = g_qkv + (size_t)(c * 256 + half * 128) * QKVW + 4096 + (size_t)h * DH;
        #pragma unroll
        for (int it = 0; it < 16; it++) {
            int j = it * 256 + tid;
            int r = j >> 5, dq = (j & 31) << 2;
            *(float4*)&stg[r * 132 + dq] = *(const float4*)&vb[(size_t)r * QKVW + dq];
        }
        __syncthreads();
        #pragma unroll
        for (int it = 0; it < 8; it++) {
            int t = it * 256 + tid;
            int d = t & 127, g = t >> 7;
            uint32_t hp[4], lp[4];
            #pragma unroll
            for (int jj = 0; jj < 4; jj++) {
                int n0 = g * 8 + jj * 2;
                float v0 = stg[n0 * 132 + d];
                float v1 = stg[(n0 + 1) * 132 + d];
                __nv_bfloat16 h0 = __float2bfloat16(v0), h1 = __float2bfloat16(v1);
                hp[jj] = pk(h0, h1);
                lp[jj] = pk(__float2bfloat16(v0 - __bfloat162float(h0)),
                            __float2bfloat16(v1 - __bfloat162float(h1)));
            }
            uint32_t o = bswz(d, g * 8, 16);
            *(uint4*)(smem + VTHI + o) = make_uint4(hp[0], hp[1], hp[2], hp[3]);
            *(uint4*)(smem + VTLO + o) = make_uint4(lp[0], lp[1], lp[2], lp[3]);
        }
        __syncthreads();
        {
            uint4* dh = (uint4*)(g_vThi + ((size_t)(h * 32 + c)) * 32768 + half * 16384);
            uint4* dl = (uint4*)(g_vTlo + ((size_t)(h * 32 + c)) * 32768 + half * 16384);
            const uint4* sh = (const uint4*)(smem + VTHI);
            const uint4* sl = (const uint4*)(smem + VTLO);
            #pragma unroll
            for (int it = 0; it < 8; it++) {
                int j = it * 256 + tid;
                dh[j] = sh[j];
                dl[j] = sl[j];
            }
        }
        FENCE_ASYNC_SHARED();
        __syncthreads();
        if (tid < 32) {
            uint64_t dVh = MAKE_SMEM_DESC(sb + VTHI), dVl = MAKE_SMEM_DESC(sb + VTLO);
            uint64_t dKh = MAKE_SMEM_DESC(sb + KTHI), dKl = MAKE_SMEM_DESC(sb + KTLO);
            if (elect_one_pred()) {
                #pragma unroll
                for (int st = 0; st < 8; st++) {
                    uint32_t u = ((st >> 2) << 10) + ((st & 3) << 1);
                    bool first = (half == 0 && st == 0);
                    mma_f16_ss(tmem, dVh + u, dKh + u, IDESC128, !first);
                    mma_f16_ss(tmem, dVh + u, dKl + u, IDESC128, true);
                    mma_f16_ss(tmem, dVl + u, dKh + u, IDESC128, true);
                }
                TCGEN05_COMMIT(mb);
            }
        }
    }
    MBARRIER_WAIT_PARITY(mb, 1);
    TCGEN05_FENCE_AFTER();
    __syncthreads();
    if (tid < 128) {
        int w = tid >> 5, l = tid & 31, e = w * 32 + l;
        float* dst = g_kvblk + ((size_t)(h * 32 + c)) * 16384 + (size_t)e * 128;
        #pragma unroll
        for (int cb = 0; cb < 4; cb++) {
            uint32_t r[32];
            TCGEN05_LD_X32(r, tmem + cb * 32);
            TCGEN05_WAIT_LD();
            #pragma unroll
            for (int j = 0; j < 32; j += 4)
                *(float4*)&dst[cb * 32 + j] = make_float4(
                    __uint_as_float(r[j]), __uint_as_float(r[j + 1]),
                    __uint_as_float(r[j + 2]), __uint_as_float(r[j + 3]));
        }
    }
    __syncthreads();
    if (tid < 32) TCGEN05_DEALLOC(tmem, 128);
#else
    int h = blockIdx.x & 15, c = blockIdx.x >> 4;
    float s = g_slopes[h];
    for (int idx = threadIdx.x; idx < 16384; idx += 256) {
        int e = idx >> 7, d = idx & 127;
        float acc = 0.f;
        for (int n = 0; n < 256; n++) {
            size_t t = (size_t)(c * 256 + n) * QKVW + (size_t)h * DH;
            acc += expf(-s * (float)(255 - n)) * g_qkv[t + 2048 + d] * g_qkv[t + 4096 + e];
        }
        g_kvblk[((size_t)(h * 32 + c)) * 16384 + (size_t)e * 128 + d] = acc;
    }
#endif
}

// ============ Phase B: decay scan — 256 CTAs ================================
__global__ void kvscan_kernel() {
    int h = blockIdx.x >> 4;
    int seg = blockIdx.x & 15;
    float bdec = expf(-g_slopes[h] * 256.0f);
    int e = seg * 1024 + threadIdx.x;
    #pragma unroll
    for (int r = 0; r < 4; r++, e += 256) {
        float acc = 0.f;
        size_t base = (size_t)h * NCHUNK * 16384 + e;
        #pragma unroll
        for (int c = 0; c < NCHUNK; c++) {
            g_kvstate[base + (size_t)c * 16384] = acc;
            acc = bdec * acc + g_kvblk[base + (size_t)c * 16384];
        }
    }
}

// ============ Phase C: attention output (tensor, bf16x3 — unchanged) ========
__global__ __launch_bounds__(256, 1) void attn_tensor_kernel() {
#if HAS_TCGEN05
    extern __shared__ char smem[];
    uint32_t sb = smem_to_u32(smem);
    int tid = threadIdx.x;
    int mi = blockIdx.x & 1, c = (blockIdx.x >> 1) & 31, h = blockIdx.x >> 6;
    float s = g_slopes[h];
    float* decay_tab = (float*)(smem + 16);
    const int QHI = 2048,  QLO = 34816;
    const int KVHI = 67584, KVLO = 100352;
    const int KHI = 67584,  KLO = 83968;
    const int VHI = 100352, VLO = 116736;
    const int SHI = 133120, SLO = 149504;
    uint32_t mb = sb + 8;
    if (tid < 32) TCGEN05_ALLOC(sb, 512);
    if (tid == 0) MBARRIER_INIT(mb, 1);
    for (int i = tid; i < 257; i += 256) decay_tab[i] = expf(-s * (float)i);
    __syncthreads();
    uint32_t tmem;
    asm volatile("ld.shared.b32 %0, [%1];" : "=r"(tmem) : "r"(sb));
    if (tid < 32) TCGEN05_RELINQ();
    const uint32_t O1T = tmem, O2T = tmem + 128, ST = tmem + 256;
    const uint32_t IDESC128 = (1u << 4) | (1u << 7) | (1u << 10) | (16u << 17) | (8u << 24);
    const uint32_t IDESC64  = (1u << 4) | (1u << 7) | (1u << 10) | (8u  << 17) | (8u << 24);

    const float* qb = g_qkv + (size_t)(c * 256 + mi * 128) * QKVW + (size_t)h * DH;
    #pragma unroll
    for (int it = 0; it < 16; it++) {
        int j = it * 256 + tid;
        int r = j >> 5, dq = (j & 31) << 2;
        float4 v = *(const float4*)&qb[(size_t)r * QKVW + dq];
        __nv_bfloat16 h0 = __float2bfloat16(v.x), h1 = __float2bfloat16(v.y);
        __nv_bfloat16 h2 = __float2bfloat16(v.z), h3 = __float2bfloat16(v.w);
        uint32_t o = bswz(r, dq, 16);
        *(uint2*)(smem + QHI + o) = make_uint2(pk(h0, h1), pk(h2, h3));
        *(uint2*)(smem + QLO + o) = make_uint2(
            pk(__float2bfloat16(v.x - __bfloat162float(h0)), __float2bfloat16(v.y - __bfloat162float(h1))),
            pk(__float2bfloat16(v.z - __bfloat162float(h2)), __float2bfloat16(v.w - __bfloat162float(h3))));
    }
    const float* kvb = g_kvstate + (size_t)(h * 32 + c) * 16384;
    #pragma unroll
    for (int it = 0; it < 16; it++) {
        int j = it * 256 + tid;
        int r = j >> 5, dq = (j & 31) << 2;
        float4 v = *(const float4*)&kvb[(size_t)r * 128 + dq];
        __nv_bfloat16 h0 = __float2bfloat16(v.x), h1 = __float2bfloat16(v.y);
        __nv_bfloat16 h2 = __float2bfloat16(v.z), h3 = __float2bfloat16(v.w);
        uint32_t o = bswz(r, dq, 16);
        *(uint2*)(smem + KVHI + o) = make_uint2(pk(h0, h1), pk(h2, h3));
        *(uint2*)(smem + KVLO + o) = make_uint2(
            pk(__float2bfloat16(v.x - __bfloat162float(h0)), __float2bfloat16(v.y - __bfloat162float(h1))),
            pk(__float2bfloat16(v.z - __bfloat162float(h2)), __float2bfloat16(v.w - __bfloat162float(h3))));
    }
    FENCE_ASYNC_SHARED();
    __syncthreads();
    int ph = 0;
    if (tid < 32) {
        uint64_t dQh = MAKE_SMEM_DESC(sb + QHI), dQl = MAKE_SMEM_DESC(sb + QLO);
        uint64_t dKh = MAKE_SMEM_DESC(sb + KVHI), dKl = MAKE_SMEM_DESC(sb + KVLO);
        if (elect_one_pred()) {
            #pragma unroll
            for (int st = 0; st < 8; st++) {
                uint32_t u = ((st >> 2) << 10) + ((st & 3) << 1);
                mma_f16_ss(O1T, dQh + u, dKh + u, IDESC128, st != 0);
                mma_f16_ss(O1T, dQh + u, dKl + u, IDESC128, true);
                mma_f16_ss(O1T, dQl + u, dKh + u, IDESC128, true);
            }
            TCGEN05_COMMIT(mb);
        }
    }
    MBARRIER_WAIT_PARITY(mb, ph & 1); ph++;

    const int nch = 2 * mi + 2;
    for (int cn = 0; cn < nch; cn++) {
        const float* kb = g_qkv + (size_t)(c * 256 + cn * 64) * QKVW + 2048 + (size_t)h * DH;
        #pragma unroll
        for (int it = 0; it < 8; it++) {
            int j = it * 256 + tid;
            int r = j >> 5, dq = (j & 31) << 2;
            float4 v = *(const float4*)&kb[(size_t)r * QKVW + dq];
            __nv_bfloat16 h0 = __float2bfloat16(v.x), h1 = __float2bfloat16(v.y);
            __nv_bfloat16 h2 = __float2bfloat16(v.z), h3 = __float2bfloat16(v.w);
            uint32_t o = bswz(r, dq, 8);
            *(uint2*)(smem + KHI + o) = make_uint2(pk(h0, h1), pk(h2, h3));
            *(uint2*)(smem + KLO + o) = make_uint2(
                pk(__float2bfloat16(v.x - __bfloat162float(h0)), __float2bfloat16(v.y - __bfloat162float(h1))),
                pk(__float2bfloat16(v.z - __bfloat162float(h2)), __float2bfloat16(v.w - __bfloat162float(h3))));
        }
        {
            const uint4* sh = (const uint4*)(g_vThi + (size_t)(h * 32 + c) * 32768 + cn * 8192);
            const uint4* sl = (const uint4*)(g_vTlo + (size_t)(h * 32 + c) * 32768 + cn * 8192);
            uint4* dh = (uint4*)(smem + VHI);
            uint4* dl = (uint4*)(smem + VLO);
            #pragma unroll
            for (int it = 0; it < 4; it++) {
                int j = it * 256 + tid;
                dh[j] = sh[j];
                dl[j] = sl[j];
            }
        }
        FENCE_ASYNC_SHARED();
        __syncthreads();
        if (tid < 32) {
            uint64_t dQh = MAKE_SMEM_DESC(sb + QHI), dQl = MAKE_SMEM_DESC(sb + QLO);
            uint64_t dKh = MAKE_SMEM_DESC(sb + KHI), dKl = MAKE_SMEM_DESC(sb + KLO);
            if (elect_one_pred()) {
                #pragma unroll
                for (int st = 0; st < 8; st++) {
                    uint32_t uq = ((st >> 2) << 10) + ((st & 3) << 1);
                    uint32_t uk = ((st >> 2) << 9) + ((st & 3) << 1);
                    mma_f16_ss(ST, dQh + uq, dKh + uk, IDESC64, st != 0);
                    mma_f16_ss(ST, dQh + uq, dKl + uk, IDESC64, true);
                    mma_f16_ss(ST, dQl + uq, dKh + uk, IDESC64, true);
                }
                TCGEN05_COMMIT(mb);
            }
        }
        MBARRIER_WAIT_PARITY(mb, ph & 1); ph++;
        TCGEN05_FENCE_AFTER();
        if (tid < 128) {
            int w = tid >> 5, l = tid & 31, m = w * 32 + l;
            int gm = mi * 128 + m;
            uint32_t r0[32], r1[32];
            TCGEN05_LD_X32(r0, ST);
            TCGEN05_WAIT_LD();
            TCGEN05_LD_X32(r1, ST + 32);
            TCGEN05_WAIT_LD();
            #pragma unroll
            for (int g = 0; g < 8; g++) {
                uint32_t hp[4], lp[4];
                #pragma unroll
                for (int jj = 0; jj < 4; jj++) {
                    int j0 = g * 8 + jj * 2;
                    float v0 = __uint_as_float(j0 < 32 ? r0[j0] : r1[j0 - 32]);
                    float v1 = __uint_as_float((j0 + 1) < 32 ? r0[j0 + 1] : r1[j0 - 31]);
                    int gn0 = cn * 64 + j0;
                    v0 = (gm >= gn0)     ? v0 * decay_tab[gm - gn0]     : 0.f;
                    v1 = (gm >= gn0 + 1) ? v1 * decay_tab[gm - gn0 - 1] : 0.f;
                    __nv_bfloat16 h0 = __float2bfloat16(v0), h1 = __float2bfloat16(v1);
                    hp[jj] = pk(h0, h1);
                    lp[jj] = pk(__float2bfloat16(v0 - __bfloat162float(h0)),
                                __float2bfloat16(v1 - __bfloat162float(h1)));
                }
                uint32_t o = bswz(m, g * 8, 16);
                *(uint4*)(smem + SHI + o) = make_uint4(hp[0], hp[1], hp[2], hp[3]);
                *(uint4*)(smem + SLO + o) = make_uint4(lp[0], lp[1], lp[2], lp[3]);
            }
        }
        FENCE_ASYNC_SHARED();
        __syncthreads();
        if (tid < 32) {
            uint64_t dSh = MAKE_SMEM_DESC(sb + SHI), dSl = MAKE_SMEM_DESC(sb + SLO);
            uint64_t dVh = MAKE_SMEM_DESC(sb + VHI), dVl = MAKE_SMEM_DESC(sb + VLO);
            if (elect_one_pred()) {
                #pragma unroll
                for (int st = 0; st < 4; st++) {
                    uint32_t u = (uint32_t)st << 1;
                    bool first = (cn == 0 && st == 0);
                    mma_f16_ss(O2T, dSh + u, dVh + u, IDESC128, !first);
                    mma_f16_ss(O2T, dSh + u, dVl + u, IDESC128, true);
                    mma_f16_ss(O2T, dSl + u, dVh + u, IDESC128, true);
                }
                TCGEN05_COMMIT(mb);
            }
        }
        MBARRIER_WAIT_PARITY(mb, ph & 1); ph++;
    }
    TCGEN05_FENCE_AFTER();
    if (tid < 128) {
        int w = tid >> 5, l = tid & 31, m = w * 32 + l;
        int gm = mi * 128 + m;
        float qd = decay_tab[gm + 1];
        float* dst = g_attn + (size_t)(c * 256 + gm) * HIDDEN + (size_t)h * DH;
        #pragma unroll
        for (int cb = 0; cb < 4; cb++) {
            uint32_t a[32], b[32];
            TCGEN05_LD_X32(a, O1T + cb * 32);
            TCGEN05_WAIT_LD();
            TCGEN05_LD_X32(b, O2T + cb * 32);
            TCGEN05_WAIT_LD();
            #pragma unroll
            for (int j = 0; j < 32; j += 4)
                *(float4*)&dst[cb * 32 + j] = make_float4(
                    qd * __uint_as_float(a[j])     + __uint_as_float(b[j]),
                    qd * __uint_as_float(a[j + 1]) + __uint_as_float(b[j + 1]),
                    qd * __uint_as_float(a[j + 2]) + __uint_as_float(b[j + 2]),
                    qd * __uint_as_float(a[j + 3]) + __uint_as_float(b[j + 3]));
        }
    }
    __syncthreads();
    if (tid < 32) TCGEN05_DEALLOC(tmem, 512);
#else
    int mi = blockIdx.x & 1, c = (blockIdx.x >> 1) & 31, h = blockIdx.x >> 6;
    float s = g_slopes[h];
    const float* kvst = g_kvstate + (size_t)(h * 32 + c) * 16384;
    for (int idx = threadIdx.x; idx < 16384; idx += 256) {
        int m = idx >> 7, e = idx & 127;
        int gm = mi * 128 + m;
        size_t tq = (size_t)(c * 256 + gm) * QKVW + (size_t)h * DH;
        float o = 0.f;
        for (int d = 0; d < 128; d++) o += g_qkv[tq + d] * kvst[(size_t)e * 128 + d];
        o *= expf(-s * (float)(gm + 1));
        for (int n = 0; n <= gm; n++) {
            size_t tk = (size_t)(c * 256 + n) * QKVW + (size_t)h * DH;
            float qk = 0.f;
            for (int d = 0; d < 128; d++) qk += g_qkv[tq + d] * g_qkv[tk + 2048 + d];
            o += expf(-s * (float)(gm - n)) * qk * g_qkv[tk + 4096 + e];
        }
        g_attn[(size_t)(c * 256 + gm) * HIDDEN + (size_t)h * DH + e] = o;
    }
#endif
}

// ============ RMS norm + sigmoid gate -> fp16 output ========================
__global__ void rmsgate_kernel(const float* __restrict__ gnw) {
    int t = blockIdx.x;
    int tid = threadIdx.x;
    const float* a = g_attn + (size_t)t * HIDDEN;
    const float* g = g_gate + (size_t)t * HIDDEN;
    float ss = 0.f;
    for (int j = tid; j < HIDDEN; j += 256) { float v = a[j]; ss += v * v; }
    #pragma unroll
    for (int o = 16; o; o >>= 1) ss += __shfl_xor_sync(0xffffffffu, ss, o);
    __shared__ float red[8];
    __shared__ float tot;
    if ((tid & 31) == 0) red[tid >> 5] = ss;
    __syncthreads();
    if (tid == 0) {
        float tsum = 0.f;
        #pragma unroll
        for (int w = 0; w < 8; w++) tsum += red[w];
        tot = tsum;
    }
    __syncthreads();
    float rms = rsqrtf(tot * (1.0f / HIDDEN) + 1e-5f);
    for (int j = tid; j < HIDDEN; j += 256) {
        float gv = g[j];
        float sig = 1.0f / (1.0f + expf(-gv));
        float val = a[j] * rms * gnw[j] * sig;
        g_yh[(size_t)t * HIDDEN + j] = __float2half_rn(val);
    }
}

// ================= launch =====================================================
extern "C" void kernel_launch(void* const* d_in, const int* in_sizes, int n_in,
                              void* d_out, int out_size) {
    const float* hidden    = (const float*)d_in[0];
    const int*   positions = (const int*)d_in[1];
    const float* Wqkv      = (const float*)d_in[2];
    const float* Wg        = (const float*)d_in[3];
    const float* Wd        = (const float*)d_in[4];
    const float* gnw       = (const float*)d_in[5];
    float* out = (float*)d_out;

    void *ah_p, *yh_p;
    void *bqh_p, *bql_p, *bgh_p, *bgl_p, *bdh_p, *bdl_p;
    cudaGetSymbolAddress(&ah_p, g_ah);
    cudaGetSymbolAddress(&yh_p, g_yh);
    cudaGetSymbolAddress(&bqh_p, g_bqkv_hi); cudaGetSymbolAddress(&bql_p, g_bqkv_lo);
    cudaGetSymbolAddress(&bgh_p, g_bg_hi);   cudaGetSymbolAddress(&bgl_p, g_bg_lo);
    cudaGetSymbolAddress(&bdh_p, g_bd_hi);   cudaGetSymbolAddress(&bdl_p, g_bd_lo);

    cudaFuncSetAttribute(gemm_qkvgate, cudaFuncAttributeMaxDynamicSharedMemorySize, CG2_SMEM);
    cudaFuncSetAttribute(gemm_down, cudaFuncAttributeMaxDynamicSharedMemorySize, CG2_SMEM);
    const int kvblk_smem = 2048 + 67584 + 4 * 32768;
    cudaFuncSetAttribute(kvblkT_kernel, cudaFuncAttributeMaxDynamicSharedMemorySize, kvblk_smem);
    const int attn_smem = 149504 + 16384;
    cudaFuncSetAttribute(attn_tensor_kernel, cudaFuncAttributeMaxDynamicSharedMemorySize, attn_smem);

    init_tables<<<1, 64>>>();
    conv_act<<<(NTOK * HIDDEN / 4 + 255) / 256, 256>>>(hidden, (__half*)ah_p,
                                                       NTOK * HIDDEN / 4);
    transposeW<<<dim3(QKVW / 32, HIDDEN / 32), 256>>>(Wqkv,
        (__half*)bqh_p, (__half*)bql_p, HIDDEN, QKVW);
    transposeW<<<dim3(HIDDEN / 32, HIDDEN / 32), 256>>>(Wg,
        (__half*)bgh_p, (__half*)bgl_p, HIDDEN, HIDDEN);
    transposeW<<<dim3(HIDDEN / 32, HIDDEN / 32), 256>>>(Wd,
        (__half*)bdh_p, (__half*)bdl_p, HIDDEN, HIDDEN);
    gemm_qkvgate<<<dim3(((QKVW + HIDDEN) / 256) * 2, NTOK / 256), 256, CG2_SMEM>>>(
        (const __half*)ah_p, positions);
    kvblkT_kernel<<<HEADS * NCHUNK, 256, kvblk_smem>>>();
    kvscan_kernel<<<HEADS * 16, 256>>>();
    attn_tensor_kernel<<<HEADS * NCHUNK * 2, 256, attn_smem>>>();
    rmsgate_kernel<<<NTOK, 256>>>(gnw);
    gemm_down<<<dim3((HIDDEN / 256) * 2, NTOK / 256), 256, CG2_SMEM>>>(
        (const __half*)yh_p,
        (const __half*)bdh_p, (const __half*)bdl_p,
        out, HIDDEN, HIDDEN);
}

// round 12
// speedup vs baseline: 1.1145x; 1.0279x over previous
#include <cuda_runtime.h>
#include <cuda_bf16.h>
#include <cuda_fp16.h>
#include <math.h>
#include <cstdint>

#define NTOK 8192
#define HIDDEN 2048
#define HEADS 16
#define DH 128
#define BLK 256
#define NCHUNK 32
#define QKVW 6144

#if defined(__CUDA_ARCH_FEAT_SM103_ALL) || \
    (defined(__CUDA_ARCH_SPECIFIC__) && (__CUDA_ARCH_SPECIFIC__ == 1030)) || \
    (defined(__CUDA_ARCH_FAMILY_SPECIFIC__) && (__CUDA_ARCH_FAMILY_SPECIFIC__ == 1030))
#define HAS_TCGEN05 1
#else
#define HAS_TCGEN05 0
#endif

// ================= PTX helpers ==============================================
__device__ __forceinline__ uint32_t elect_one_pred() {
    uint32_t pred;
    asm volatile("{\n\t.reg .pred p;\n\telect.sync _|p, 0xFFFFFFFF;\n\t"
                 "selp.b32 %0, 1, 0, p;\n\t}" : "=r"(pred));
    return pred;
}
__device__ __forceinline__ uint32_t smem_to_u32(const void* p) {
    uint32_t a;
    asm("{ .reg .u64 t; cvta.to.shared.u64 t, %1; cvt.u32.u64 %0, t; }"
        : "=r"(a) : "l"(p));
    return a;
}
__device__ __forceinline__ uint32_t cluster_rank() {
    uint32_t r;
    asm("mov.u32 %0, %%cluster_ctarank;" : "=r"(r));
    return r;
}
#define CLUSTER_SYNC() do { \
    asm volatile("barrier.cluster.arrive.aligned;" ::: "memory"); \
    asm volatile("barrier.cluster.wait.aligned;" ::: "memory"); \
} while (0)
#define MBARRIER_INIT(addr, cnt) \
    asm volatile("mbarrier.init.shared.b64 [%0], %1;" :: "r"((uint32_t)(addr)), "r"((uint32_t)(cnt)) : "memory")
#define MBARRIER_WAIT_PARITY(addr, par) do { \
    uint32_t _m = (uint32_t)(addr); uint32_t _p = (uint32_t)(par); uint32_t _d; \
    asm volatile("{\n\t.reg .pred p;\n\t" \
        "mbarrier.try_wait.parity.acquire.cta.shared::cta.b64 p, [%1], %2;\n\t" \
        "selp.b32 %0, 1, 0, p;\n\t}" : "=r"(_d) : "r"(_m), "r"(_p) : "memory"); \
    if (!_d) { \
        asm volatile("{\n\t.reg .pred P1;\n\t" \
            "WL_%=:\n\t" \
            "mbarrier.try_wait.parity.acquire.cta.shared::cta.b64 P1, [%0], %1, 0x989680;\n\t" \
            "@P1 bra.uni WD_%=;\n\tbra.uni WL_%=;\n\tWD_%=:\n\t}" \
            :: "r"(_m), "r"(_p) : "memory"); \
    } } while (0)
#define MBARRIER_WAIT_PARITY_CL(addr, par) do { \
    uint32_t _m = (uint32_t)(addr); uint32_t _p = (uint32_t)(par); uint32_t _d; \
    asm volatile("{\n\t.reg .pred p;\n\t" \
        "mbarrier.try_wait.parity.acquire.cluster.shared::cta.b64 p, [%1], %2;\n\t" \
        "selp.b32 %0, 1, 0, p;\n\t}" : "=r"(_d) : "r"(_m), "r"(_p) : "memory"); \
    if (!_d) { \
        asm volatile("{\n\t.reg .pred P1;\n\t" \
            "WL_%=:\n\t" \
            "mbarrier.try_wait.parity.acquire.cluster.shared::cta.b64 P1, [%0], %1, 0x989680;\n\t" \
            "@P1 bra.uni WD_%=;\n\tbra.uni WL_%=;\n\tWD_%=:\n\t}" \
            :: "r"(_m), "r"(_p) : "memory"); \
    } } while (0)
#define MBARRIER_ARRIVE_CLUSTER(local_addr, target_rank) \
    asm volatile( \
        "{\n\t.reg .b32 remAddr32;\n\t" \
        "mapa.shared::cluster.u32 remAddr32, %0, %1;\n\t" \
        "mbarrier.arrive.release.cluster.shared::cluster.b64 _, [remAddr32];\n\t}" \
        :: "r"((uint32_t)(local_addr)), "r"((uint32_t)(target_rank)) : "memory")
#define TCGEN05_ALLOC(smem_addr, n) \
    asm volatile("tcgen05.alloc.cta_group::1.sync.aligned.shared::cta.b32 [%0], %1;" \
        :: "r"((uint32_t)(smem_addr)), "r"((uint32_t)(n)) : "memory")
#define TCGEN05_DEALLOC(tmem, n) \
    asm volatile("tcgen05.dealloc.cta_group::1.sync.aligned.b32 %0, %1;" :: "r"(tmem), "r"((uint32_t)(n)))
#define TCGEN05_RELINQ() \
    asm volatile("tcgen05.relinquish_alloc_permit.cta_group::1.sync.aligned;")
#define TCGEN05_ALLOC_CG2(smem_addr, n) \
    asm volatile("tcgen05.alloc.cta_group::2.sync.aligned.shared::cta.b32 [%0], %1;" \
        :: "r"((uint32_t)(smem_addr)), "r"((uint32_t)(n)) : "memory")
#define TCGEN05_DEALLOC_CG2(tmem, n) \
    asm volatile("tcgen05.dealloc.cta_group::2.sync.aligned.b32 %0, %1;" :: "r"(tmem), "r"((uint32_t)(n)))
#define TCGEN05_RELINQ_CG2() \
    asm volatile("tcgen05.relinquish_alloc_permit.cta_group::2.sync.aligned;")
#define TCGEN05_COMMIT(mbar) \
    asm volatile("tcgen05.commit.cta_group::1.mbarrier::arrive::one.shared::cluster.b64 [%0];" \
        :: "r"((uint32_t)(mbar)) : "memory")
#define TCGEN05_COMMIT_MC_CG2(mbar, mask) \
    asm volatile("tcgen05.commit.cta_group::2.mbarrier::arrive::one.shared::cluster.multicast::cluster.b64 [%0], %1;" \
        :: "r"((uint32_t)(mbar)), "h"((uint16_t)(mask)) : "memory")
#define TCGEN05_FENCE_AFTER() asm volatile("tcgen05.fence::after_thread_sync;" ::: "memory")
#define TCGEN05_WAIT_LD() asm volatile("tcgen05.wait::ld.sync.aligned;" ::: "memory")
#define FENCE_ASYNC_SHARED() asm volatile("fence.proxy.async.shared::cta;" ::: "memory")
#define TCGEN05_LD_X32(r, addr) \
    asm volatile("tcgen05.ld.sync.aligned.32x32b.x32.b32 " \
        "{%0, %1, %2, %3, %4, %5, %6, %7, %8, %9, %10, %11, %12, %13, %14, %15, " \
        " %16, %17, %18, %19, %20, %21, %22, %23, %24, %25, %26, %27, %28, %29, %30, %31}, [%32];" \
        : "=r"((r)[0]),  "=r"((r)[1]),  "=r"((r)[2]),  "=r"((r)[3]), \
          "=r"((r)[4]),  "=r"((r)[5]),  "=r"((r)[6]),  "=r"((r)[7]), \
          "=r"((r)[8]),  "=r"((r)[9]),  "=r"((r)[10]), "=r"((r)[11]), \
          "=r"((r)[12]), "=r"((r)[13]), "=r"((r)[14]), "=r"((r)[15]), \
          "=r"((r)[16]), "=r"((r)[17]), "=r"((r)[18]), "=r"((r)[19]), \
          "=r"((r)[20]), "=r"((r)[21]), "=r"((r)[22]), "=r"((r)[23]), \
          "=r"((r)[24]), "=r"((r)[25]), "=r"((r)[26]), "=r"((r)[27]), \
          "=r"((r)[28]), "=r"((r)[29]), "=r"((r)[30]), "=r"((r)[31]) \
        : "r"(addr))

static constexpr uint64_t SMEM_DESC_BASE_SW128 =
    (uint64_t(2) << 61) | (uint64_t(1) << 46) | (uint64_t(64) << 32) | (uint64_t(1) << 16);
#define MAKE_SMEM_DESC(a) (SMEM_DESC_BASE_SW128 | ((uint64_t)((a) >> 4) & 0x3FFF))

#if HAS_TCGEN05
__device__ __forceinline__ void mma_f16_ss(uint32_t d_tmem, uint64_t a_desc,
                                           uint64_t b_desc, uint32_t idesc, bool acc) {
    uint32_t en = acc ? 1u : 0u;
    asm volatile(
        "{\n\t.reg .pred p;\n\tsetp.ne.u32 p, %5, 0;\n\t"
        "tcgen05.mma.cta_group::1.kind::f16 [%0], %1, %2, %3, {%4, %4, %4, %4}, p;\n\t}"
        :: "r"(d_tmem), "l"(a_desc), "l"(b_desc), "r"(idesc), "r"(0u), "r"(en)
        : "memory");
}
__device__ __forceinline__ void mma_f16_ss_cg2(uint32_t d_tmem, uint64_t a_desc,
                                               uint64_t b_desc, uint32_t idesc, bool acc) {
    uint32_t en = acc ? 1u : 0u;
    asm volatile(
        "{\n\t.reg .pred p;\n\tsetp.ne.u32 p, %5, 0;\n\t"
        "tcgen05.mma.cta_group::2.kind::f16 [%0], %1, %2, %3, "
        "{%4, %4, %4, %4, %4, %4, %4, %4}, p;\n\t}"
        :: "r"(d_tmem), "l"(a_desc), "l"(b_desc), "r"(idesc), "r"(0u), "r"(en)
        : "memory");
}
#endif

__device__ __forceinline__ uint32_t bswz(int row, int col, int atomrows) {
    uint32_t off = (uint32_t)(((row >> 3) + (col >> 6) * atomrows) << 10)
                 + ((row & 7) << 7) + ((col & 63) << 1);
    return off ^ ((off >> 3) & 0x70);
}
__device__ __forceinline__ uint32_t pkh(__half a, __half b) {
    __half2 t{a, b};
    return *(uint32_t*)&t;
}

// ================= scratch ===================================================
__device__ float g_qkv[(size_t)NTOK * QKVW];
__device__ float g_gate[(size_t)NTOK * HIDDEN];
__device__ float g_attn[(size_t)NTOK * HIDDEN];
__device__ float g_kvblk[(size_t)HEADS * NCHUNK * DH * DH];
__device__ float g_kvstate[(size_t)HEADS * NCHUNK * DH * DH];
__device__ float g_invf[64];
__device__ float g_slopes[HEADS];
__device__ __half g_vThi[(size_t)HEADS * NCHUNK * 32768];
__device__ __half g_vTlo[(size_t)HEADS * NCHUNK * 32768];
__device__ __half g_ah[(size_t)NTOK * HIDDEN];
__device__ __half g_yh[(size_t)NTOK * HIDDEN];
__device__ __half g_bqkv_hi[(size_t)QKVW * HIDDEN];
__device__ __half g_bqkv_lo[(size_t)QKVW * HIDDEN];
__device__ __half g_bg_hi[(size_t)HIDDEN * HIDDEN];
__device__ __half g_bg_lo[(size_t)HIDDEN * HIDDEN];
__device__ __half g_bd_hi[(size_t)HIDDEN * HIDDEN];
__device__ __half g_bd_lo[(size_t)HIDDEN * HIDDEN];

// ================= init tables ================================================
__global__ void init_tables() {
    int t = threadIdx.x;
    if (t < 64) g_invf[t] = (float)pow(600000.0, -(double)t / 64.0);
    if (t < HEADS) {
        double start = pow(2.0, -pow(2.0, -(log2(16.0) - 3.0)));
        g_slopes[t] = (float)(start * pow(start, (double)t) * (1.0 + 1e-5));
    }
}

// ================= convert fp32 -> fp16 (A operand, single) =================
__global__ void conv_act(const float* __restrict__ x, __half* __restrict__ h, int n4) {
    int i = blockIdx.x * blockDim.x + threadIdx.x;
    if (i >= n4) return;
    float4 v = ((const float4*)x)[i];
    __half2 a{__float2half_rn(v.x), __float2half_rn(v.y)};
    __half2 b{__float2half_rn(v.z), __float2half_rn(v.w)};
    ((__half2*)h)[i * 2]     = a;
    ((__half2*)h)[i * 2 + 1] = b;
}

// ======= transpose + split W[K,N] fp32 -> Thi/Tlo [N,K] fp16 ================
__global__ void transposeW(const float* __restrict__ W, __half* __restrict__ Thi,
                           __half* __restrict__ Tlo, int K, int N) {
    __shared__ float t[32][33];
    int n0 = blockIdx.x * 32, k0 = blockIdx.y * 32;
    int c = threadIdx.x & 31, r0 = threadIdx.x >> 5;
    #pragma unroll
    for (int rr = r0; rr < 32; rr += 8)
        t[rr][c] = W[(size_t)(k0 + rr) * N + n0 + c];
    __syncthreads();
    #pragma unroll
    for (int rr = r0; rr < 32; rr += 8) {
        float v = t[c][rr];
        __half h = __float2half_rn(v);
        Thi[(size_t)(n0 + rr) * K + k0 + c] = h;
        Tlo[(size_t)(n0 + rr) * K + k0 + c] = __float2half_rn(v - __half2float(h));
    }
}

#if HAS_TCGEN05
template <int ROWS>
__device__ __forceinline__ void load_tile(char* dst, const __half* src, int ld) {
    int tid = threadIdx.x;
    #pragma unroll
    for (int l = 0; l < ROWS / 32; l++) {
        int i = l * 256 + tid;
        int r = i >> 3, sg = i & 7;
        uint4 v = *(const uint4*)(src + (size_t)r * ld + sg * 8);
        uint32_t off = (uint32_t)(r * 128 + sg * 16);
        off ^= (off >> 3) & 0x70;
        *(uint4*)(dst + off) = v;
    }
}
#endif

// ======= cg2 fp16 GEMM constants (K-chunk 64) ================================
#define CG2_BUF 49152
#define CG2_SMEM (1024 + 2 * CG2_BUF)
#define IDESC_CG2 ((1u << 4) | (32u << 17) | (16u << 24))

// ======= fused qkv+gate GEMM (cg2 fp16; gate B-lo skipped) ===================
__global__ __launch_bounds__(256, 1) __cluster_dims__(2, 1, 1)
void gemm_qkvgate(const __half* __restrict__ A, const int* __restrict__ positions) {
    const int K = HIDDEN;
    uint32_t rank = cluster_rank();
    int bm = blockIdx.y * 256;
    int bn = (blockIdx.x >> 1) * 256;
    int gcs = bn + (int)rank * 128;
    bool isGate = (bn >= QKVW);
    const __half* Bhi = (gcs < QKVW) ? g_bqkv_hi + (size_t)gcs * K
                                     : g_bg_hi + (size_t)(gcs - QKVW) * K;
    const __half* Blo = (gcs < QKVW) ? g_bqkv_lo + (size_t)gcs * K
                                     : g_bg_lo + (size_t)(gcs - QKVW) * K;
#if HAS_TCGEN05
    extern __shared__ char smem[];
    uint32_t sb = smem_to_u32(smem);
    int tid = threadIdx.x;
    const uint32_t dn0 = sb + 8,  dn1 = sb + 16;
    const uint32_t rd0 = sb + 24, rd1 = sb + 32;
    if (tid < 32) TCGEN05_ALLOC_CG2(sb, 256);
    if (tid == 0) {
        MBARRIER_INIT(dn0, 1); MBARRIER_INIT(dn1, 1);
        MBARRIER_INIT(rd0, 2); MBARRIER_INIT(rd1, 2);
    }
    __syncthreads();
    uint32_t tmem;
    asm volatile("ld.shared.b32 %0, [%1];" : "=r"(tmem) : "r"(sb));
    if (tid < 32) TCGEN05_RELINQ_CG2();
    CLUSTER_SYNC();

    const __half* pA = A + (size_t)(bm + rank * 128) * K;

    int phd[2] = {0, 0};
    int phr[2] = {0, 0};
    for (int ch = 0; ch < 32; ch++) {
        int b = ch & 1;
        char* st = smem + 1024 + b * CG2_BUF;
        if (ch >= 2) {
            MBARRIER_WAIT_PARITY_CL(b ? dn1 : dn0, phd[b]);
            phd[b] ^= 1;
        }
        int k0 = ch << 6;
        load_tile<128>(st,         pA + k0,  K);
        load_tile<128>(st + 16384, Bhi + k0, K);
        if (!isGate) load_tile<128>(st + 32768, Blo + k0, K);
        FENCE_ASYNC_SHARED();
        __syncthreads();
        if (tid == 0) MBARRIER_ARRIVE_CLUSTER(b ? rd1 : rd0, 0);
        if (rank == 0 && tid < 32) {
            MBARRIER_WAIT_PARITY_CL(b ? rd1 : rd0, phr[b]);
            phr[b] ^= 1;
            uint32_t sa = sb + 1024 + b * CG2_BUF;
            uint64_t dA  = MAKE_SMEM_DESC(sa);
            uint64_t dBh = MAKE_SMEM_DESC(sa + 16384);
            uint64_t dBl = MAKE_SMEM_DESC(sa + 32768);
            if (elect_one_pred()) {
                #pragma unroll
                for (int k = 0; k < 4; k++) {
                    bool first = (ch == 0) && (k == 0);
                    mma_f16_ss_cg2(tmem, dA + k * 2, dBh + k * 2, IDESC_CG2, !first);
                    if (!isGate)
                        mma_f16_ss_cg2(tmem, dA + k * 2, dBl + k * 2, IDESC_CG2, true);
                }
                TCGEN05_COMMIT_MC_CG2(b ? dn1 : dn0, 0x3);
            }
        }
    }
    MBARRIER_WAIT_PARITY_CL(dn0, phd[0]);
    MBARRIER_WAIT_PARITY_CL(dn1, phd[1]);
    TCGEN05_FENCE_AFTER();
    __syncthreads();

    int w = tid >> 5, l = tid & 31;
    int sub = w & 3;
    int colbase = (w >> 2) * 128;
    int row = bm + (int)rank * 128 + sub * 32 + l;
    int gc0 = bn + colbase;
    bool isQ = gc0 < 2048;
    bool isK = (gc0 >= 2048) && (gc0 < 4096);
    float* dst = (gc0 < QKVW) ? g_qkv + (size_t)row * QKVW + gc0
                              : g_gate + (size_t)row * HIDDEN + (gc0 - QKVW);
    if (isQ || isK) {
        float pos = (float)positions[row];
        float qs = isQ ? 0.08838834764831845f : 1.0f;
        #pragma unroll
        for (int half = 0; half < 2; half++) {
            uint32_t a[32], b[32];
            TCGEN05_LD_X32(a, tmem + colbase + half * 32);
            TCGEN05_WAIT_LD();
            TCGEN05_LD_X32(b, tmem + colbase + half * 32 + 64);
            TCGEN05_WAIT_LD();
            #pragma unroll
            for (int j0 = 0; j0 < 32; j0 += 4) {
                float o1[4], o2[4];
                #pragma unroll
                for (int j = 0; j < 4; j++) {
                    int jin = half * 32 + j0 + j;
                    float f = pos * g_invf[jin];
                    float sv, cv;
                    sincosf(f, &sv, &cv);
                    float x1 = __uint_as_float(a[j0 + j]);
                    float x2 = __uint_as_float(b[j0 + j]);
                    o1[j] = (x1 * cv - x2 * sv) * qs;
                    o2[j] = (x2 * cv + x1 * sv) * qs;
                }
                *(float4*)&dst[half * 32 + j0]      = make_float4(o1[0], o1[1], o1[2], o1[3]);
                *(float4*)&dst[half * 32 + 64 + j0] = make_float4(o2[0], o2[1], o2[2], o2[3]);
            }
        }
    } else {
        #pragma unroll
        for (int cb = 0; cb < 128; cb += 32) {
            uint32_t r[32];
            TCGEN05_LD_X32(r, tmem + colbase + cb);
            TCGEN05_WAIT_LD();
            #pragma unroll
            for (int j = 0; j < 32; j += 4)
                *(float4*)&dst[cb + j] = make_float4(
                    __uint_as_float(r[j]), __uint_as_float(r[j + 1]),
                    __uint_as_float(r[j + 2]), __uint_as_float(r[j + 3]));
        }
    }
    __syncthreads();
    if (tid < 32) TCGEN05_DEALLOC_CG2(tmem, 256);
    CLUSTER_SYNC();
#else
    extern __shared__ char smemraw[];
    float* As = (float*)smemraw;
    float* Bs = As + 16 * 128;
    int tid = threadIdx.x;
    int bmr = bm + (int)rank * 128;
    int ty = tid >> 4, tx = tid & 15;
    float acc[8][16];
    #pragma unroll
    for (int i = 0; i < 8; i++)
        #pragma unroll
        for (int j = 0; j < 16; j++) acc[i][j] = 0.f;
    for (int k0 = 0; k0 < K; k0 += 16) {
        #pragma unroll
        for (int l = 0; l < 8; l++) {
            int i = l * 256 + tid;
            int k = i & 15, m = i >> 4;
            As[k * 128 + m] = __half2float(A[(size_t)(bmr + m) * K + k0 + k]);
        }
        #pragma unroll
        for (int l = 0; l < 16; l++) {
            int i = l * 256 + tid;
            int k = i & 15, n = i >> 4;
            int gc = bn + n;
            const __half* bh = (gc < QKVW) ? g_bqkv_hi + (size_t)gc * K
                                           : g_bg_hi + (size_t)(gc - QKVW) * K;
            const __half* bl = (gc < QKVW) ? g_bqkv_lo + (size_t)gc * K
                                           : g_bg_lo + (size_t)(gc - QKVW) * K;
            float bv = __half2float(bh[k0 + k]);
            if (!isGate) bv += __half2float(bl[k0 + k]);
            Bs[k * 256 + n] = bv;
        }
        __syncthreads();
        #pragma unroll
        for (int kk = 0; kk < 16; kk++) {
            float a[8], b[16];
            #pragma unroll
            for (int i = 0; i < 8; i++) a[i] = As[kk * 128 + ty * 8 + i];
            #pragma unroll
            for (int j = 0; j < 16; j++) b[j] = Bs[kk * 256 + tx * 16 + j];
            #pragma unroll
            for (int i = 0; i < 8; i++)
                #pragma unroll
                for (int j = 0; j < 16; j++) acc[i][j] += a[i] * b[j];
        }
        __syncthreads();
    }
    float* tileS = (float*)smemraw;
    #pragma unroll
    for (int i = 0; i < 8; i++)
        #pragma unroll
        for (int j = 0; j < 16; j++)
            tileS[(ty * 8 + i) * 257 + tx * 16 + j] = acc[i][j];
    __syncthreads();
    {
        int r = tid >> 1, sp = tid & 1;
        int row = bmr + r;
        int gc0 = bn + sp * 128;
        bool isQ = gc0 < 2048;
        bool isK = (gc0 >= 2048) && (gc0 < 4096);
        float* dst = (gc0 < QKVW) ? g_qkv + (size_t)row * QKVW + gc0
                                  : g_gate + (size_t)row * HIDDEN + (gc0 - QKVW);
        const float* src = &tileS[r * 257 + sp * 128];
        if (isQ || isK) {
            float pos = (float)positions[row];
            float qs = isQ ? 0.08838834764831845f : 1.0f;
            for (int j = 0; j < 64; j++) {
                float f = pos * g_invf[j];
                float sv, cv;
                sincosf(f, &sv, &cv);
                float x1 = src[j], x2 = src[j + 64];
                dst[j]      = (x1 * cv - x2 * sv) * qs;
                dst[j + 64] = (x2 * cv + x1 * sv) * qs;
            }
        } else {
            for (int j = 0; j < 128; j++) dst[j] = src[j];
        }
    }
#endif
}

// ================= cg2 fp16 2-term down-projection GEMM ======================
__global__ __launch_bounds__(256, 1) __cluster_dims__(2, 1, 1)
void gemm_down(const __half* __restrict__ A,
               const __half* __restrict__ Bhi, const __half* __restrict__ Blo,
               float* __restrict__ C, int Nn, int K) {
    uint32_t rank = cluster_rank();
    int bm = blockIdx.y * 256;
    int bn = (blockIdx.x >> 1) * 256;
#if HAS_TCGEN05
    extern __shared__ char smem[];
    uint32_t sb = smem_to_u32(smem);
    int tid = threadIdx.x;
    const uint32_t dn0 = sb + 8,  dn1 = sb + 16;
    const uint32_t rd0 = sb + 24, rd1 = sb + 32;
    if (tid < 32) TCGEN05_ALLOC_CG2(sb, 256);
    if (tid == 0) {
        MBARRIER_INIT(dn0, 1); MBARRIER_INIT(dn1, 1);
        MBARRIER_INIT(rd0, 2); MBARRIER_INIT(rd1, 2);
    }
    __syncthreads();
    uint32_t tmem;
    asm volatile("ld.shared.b32 %0, [%1];" : "=r"(tmem) : "r"(sb));
    if (tid < 32) TCGEN05_RELINQ_CG2();
    CLUSTER_SYNC();

    const __half* pA   = A   + (size_t)(bm + rank * 128) * K;
    const __half* pBhi = Bhi + (size_t)(bn + rank * 128) * K;
    const __half* pBlo = Blo + (size_t)(bn + rank * 128) * K;

    int phd[2] = {0, 0};
    int phr[2] = {0, 0};
    const int nch = K >> 6;
    for (int ch = 0; ch < nch; ch++) {
        int b = ch & 1;
        char* st = smem + 1024 + b * CG2_BUF;
        if (ch >= 2) {
            MBARRIER_WAIT_PARITY_CL(b ? dn1 : dn0, phd[b]);
            phd[b] ^= 1;
        }
        int k0 = ch << 6;
        load_tile<128>(st,         pA + k0,   K);
        load_tile<128>(st + 16384, pBhi + k0, K);
        load_tile<128>(st + 32768, pBlo + k0, K);
        FENCE_ASYNC_SHARED();
        __syncthreads();
        if (tid == 0) MBARRIER_ARRIVE_CLUSTER(b ? rd1 : rd0, 0);
        if (rank == 0 && tid < 32) {
            MBARRIER_WAIT_PARITY_CL(b ? rd1 : rd0, phr[b]);
            phr[b] ^= 1;
            uint32_t sa = sb + 1024 + b * CG2_BUF;
            uint64_t dA  = MAKE_SMEM_DESC(sa);
            uint64_t dBh = MAKE_SMEM_DESC(sa + 16384);
            uint64_t dBl = MAKE_SMEM_DESC(sa + 32768);
            if (elect_one_pred()) {
                #pragma unroll
                for (int k = 0; k < 4; k++) {
                    bool first = (ch == 0) && (k == 0);
                    mma_f16_ss_cg2(tmem, dA + k * 2, dBh + k * 2, IDESC_CG2, !first);
                    mma_f16_ss_cg2(tmem, dA + k * 2, dBl + k * 2, IDESC_CG2, true);
                }
                TCGEN05_COMMIT_MC_CG2(b ? dn1 : dn0, 0x3);
            }
        }
    }
    MBARRIER_WAIT_PARITY_CL(dn0, phd[0]);
    MBARRIER_WAIT_PARITY_CL(dn1, phd[1]);
    TCGEN05_FENCE_AFTER();
    __syncthreads();

    int w = tid >> 5, l = tid & 31;
    int sub = w & 3;
    int colbase = (w >> 2) * 128;
    int row = bm + (int)rank * 128 + sub * 32 + l;
    float* dst_row = C + (size_t)row * Nn + bn + colbase;
    #pragma unroll
    for (int cb = 0; cb < 128; cb += 32) {
        uint32_t r[32];
        TCGEN05_LD_X32(r, tmem + colbase + cb);
        TCGEN05_WAIT_LD();
        #pragma unroll
        for (int j = 0; j < 32; j += 4)
            *(float4*)(dst_row + cb + j) = make_float4(
                __uint_as_float(r[j]), __uint_as_float(r[j + 1]),
                __uint_as_float(r[j + 2]), __uint_as_float(r[j + 3]));
    }
    __syncthreads();
    if (tid < 32) TCGEN05_DEALLOC_CG2(tmem, 256);
    CLUSTER_SYNC();
#else
    extern __shared__ char smemraw[];
    float* As = (float*)smemraw;
    float* Bs = As + 16 * 128;
    int tid = threadIdx.x;
    int bmr = bm + (int)rank * 128;
    int ty = tid >> 4, tx = tid & 15;
    float acc[8][16];
    #pragma unroll
    for (int i = 0; i < 8; i++)
        #pragma unroll
        for (int j = 0; j < 16; j++) acc[i][j] = 0.f;
    for (int k0 = 0; k0 < K; k0 += 16) {
        #pragma unroll
        for (int l = 0; l < 8; l++) {
            int i = l * 256 + tid;
            int k = i & 15, m = i >> 4;
            As[k * 128 + m] = __half2float(A[(size_t)(bmr + m) * K + k0 + k]);
        }
        #pragma unroll
        for (int l = 0; l < 16; l++) {
            int i = l * 256 + tid;
            int k = i & 15, n = i >> 4;
            size_t off = (size_t)(bn + n) * K + k0 + k;
            Bs[k * 256 + n] = __half2float(Bhi[off]) + __half2float(Blo[off]);
        }
        __syncthreads();
        #pragma unroll
        for (int kk = 0; kk < 16; kk++) {
            float a[8], b[16];
            #pragma unroll
            for (int i = 0; i < 8; i++) a[i] = As[kk * 128 + ty * 8 + i];
            #pragma unroll
            for (int j = 0; j < 16; j++) b[j] = Bs[kk * 256 + tx * 16 + j];
            #pragma unroll
            for (int i = 0; i < 8; i++)
                #pragma unroll
                for (int j = 0; j < 16; j++) acc[i][j] += a[i] * b[j];
        }
        __syncthreads();
    }
    #pragma unroll
    for (int i = 0; i < 8; i++) {
        size_t off = (size_t)(bmr + ty * 8 + i) * Nn + bn + tx * 16;
        #pragma unroll
        for (int j = 0; j < 16; j += 4)
            *(float4*)&C[off + j] = make_float4(acc[i][j], acc[i][j + 1],
                                                acc[i][j + 2], acc[i][j + 3]);
    }
#endif
}

// ============ Phase A: kvblkT (tensor, fp16 2-term) =========================
__global__ __launch_bounds__(256, 1) void kvblkT_kernel() {
#if HAS_TCGEN05
    extern __shared__ char smem[];
    uint32_t sb = smem_to_u32(smem);
    int tid = threadIdx.x;
    int h = blockIdx.x & 15, c = blockIdx.x >> 4;
    float s = g_slopes[h];
    float* decay_tab = (float*)(smem + 16);
    const int STG = 2048;
    const int KTHI = STG + 67584;
    const int KTLO = KTHI + 32768;
    const int VTHI = KTLO + 32768;
    const int VTLO = VTHI + 32768;
    uint32_t mb = sb + 8;
    if (tid < 32) TCGEN05_ALLOC(sb, 128);
    if (tid == 0) MBARRIER_INIT(mb, 1);
    for (int i = tid; i < 257; i += 256) decay_tab[i] = expf(-s * (float)i);
    __syncthreads();
    uint32_t tmem;
    asm volatile("ld.shared.b32 %0, [%1];" : "=r"(tmem) : "r"(sb));
    if (tid < 32) TCGEN05_RELINQ();
    float* stg = (float*)(smem + STG);
    const uint32_t IDESC128F = (1u << 4) | (16u << 17) | (8u << 24);

    for (int half = 0; half < 2; half++) {
        if (half == 1) MBARRIER_WAIT_PARITY(mb, 0);
        // ---- stage + transpose K (with decay), fp16 hi/lo ----
        const float* kb = g_qkv + (size_t)(c * 256 + half * 128) * QKVW + 2048 + (size_t)h * DH;
        #pragma unroll
        for (int it = 0; it < 16; it++) {
            int j = it * 256 + tid;
            int r = j >> 5, dq = (j & 31) << 2;
            *(float4*)&stg[r * 132 + dq] = *(const float4*)&kb[(size_t)r * QKVW + dq];
        }
        __syncthreads();
        #pragma unroll
        for (int it = 0; it < 8; it++) {
            int t = it * 256 + tid;
            int d = t & 127, g = t >> 7;
            uint32_t hp[4], lp[4];
            #pragma unroll
            for (int jj = 0; jj < 4; jj++) {
                int n0 = g * 8 + jj * 2;
                float v0 = stg[n0 * 132 + d]       * decay_tab[255 - (half * 128 + n0)];
                float v1 = stg[(n0 + 1) * 132 + d] * decay_tab[255 - (half * 128 + n0 + 1)];
                __half h0 = __float2half_rn(v0), h1 = __float2half_rn(v1);
                hp[jj] = pkh(h0, h1);
                lp[jj] = pkh(__float2half_rn(v0 - __half2float(h0)),
                             __float2half_rn(v1 - __half2float(h1)));
            }
            uint32_t o = bswz(d, g * 8, 16);
            *(uint4*)(smem + KTHI + o) = make_uint4(hp[0], hp[1], hp[2], hp[3]);
            *(uint4*)(smem + KTLO + o) = make_uint4(lp[0], lp[1], lp[2], lp[3]);
        }
        __syncthreads();
        // ---- stage + transpose V, fp16 hi/lo (lo persisted for O2 only) ----
        const float* vb = g_qkv + (size_t)(c * 256 + half * 128) * QKVW + 4096 + (size_t)h * DH;
        #pragma unroll
        for (int it = 0; it < 16; it++) {
            int j = it * 256 + tid;
            int r = j >> 5, dq = (j & 31) << 2;
            *(float4*)&stg[r * 132 + dq] = *(const float4*)&vb[(size_t)r * QKVW + dq];
        }
        __syncthreads();
        #pragma unroll
        for (int it = 0; it < 8; it++) {
            int t = it * 256 + tid;
            int d = t & 127, g = t >> 7;
            uint32_t hp[4], lp[4];
            #pragma unroll
            for (int jj = 0; jj < 4; jj++) {
                int n0 = g * 8 + jj * 2;
                float v0 = stg[n0 * 132 + d];
                float v1 = stg[(n0 + 1) * 132 + d];
                __half h0 = __float2half_rn(v0), h1 = __float2half_rn(v1);
                hp[jj] = pkh(h0, h1);
                lp[jj] = pkh(__float2half_rn(v0 - __half2float(h0)),
                             __float2half_rn(v1 - __half2float(h1)));
            }
            uint32_t o = bswz(d, g * 8, 16);
            *(uint4*)(smem + VTHI + o) = make_uint4(hp[0], hp[1], hp[2], hp[3]);
            *(uint4*)(smem + VTLO + o) = make_uint4(lp[0], lp[1], lp[2], lp[3]);
        }
        __syncthreads();
        {
            uint4* dh = (uint4*)(g_vThi + ((size_t)(h * 32 + c)) * 32768 + half * 16384);
            uint4* dl = (uint4*)(g_vTlo + ((size_t)(h * 32 + c)) * 32768 + half * 16384);
            const uint4* sh = (const uint4*)(smem + VTHI);
            const uint4* sl = (const uint4*)(smem + VTLO);
            #pragma unroll
            for (int it = 0; it < 8; it++) {
                int j = it * 256 + tid;
                dh[j] = sh[j];
                dl[j] = sl[j];
            }
        }
        FENCE_ASYNC_SHARED();
        __syncthreads();
        // ---- MMA: D += vThi·(kThi + kTlo)^T — 2 terms ----
        if (tid < 32) {
            uint64_t dVh = MAKE_SMEM_DESC(sb + VTHI);
            uint64_t dKh = MAKE_SMEM_DESC(sb + KTHI), dKl = MAKE_SMEM_DESC(sb + KTLO);
            if (elect_one_pred()) {
                #pragma unroll
                for (int st = 0; st < 8; st++) {
                    uint32_t u = ((st >> 2) << 10) + ((st & 3) << 1);
                    bool first = (half == 0 && st == 0);
                    mma_f16_ss(tmem, dVh + u, dKh + u, IDESC128F, !first);
                    mma_f16_ss(tmem, dVh + u, dKl + u, IDESC128F, true);
                }
                TCGEN05_COMMIT(mb);
            }
        }
    }
    MBARRIER_WAIT_PARITY(mb, 1);
    TCGEN05_FENCE_AFTER();
    __syncthreads();
    if (tid < 128) {
        int w = tid >> 5, l = tid & 31, e = w * 32 + l;
        float* dst = g_kvblk + ((size_t)(h * 32 + c)) * 16384 + (size_t)e * 128;
        #pragma unroll
        for (int cb = 0; cb < 4; cb++) {
            uint32_t r[32];
            TCGEN05_LD_X32(r, tmem + cb * 32);
            TCGEN05_WAIT_LD();
            #pragma unroll
            for (int j = 0; j < 32; j += 4)
                *(float4*)&dst[cb * 32 + j] = make_float4(
                    __uint_as_float(r[j]), __uint_as_float(r[j + 1]),
                    __uint_as_float(r[j + 2]), __uint_as_float(r[j + 3]));
        }
    }
    __syncthreads();
    if (tid < 32) TCGEN05_DEALLOC(tmem, 128);
#else
    int h = blockIdx.x & 15, c = blockIdx.x >> 4;
    float s = g_slopes[h];
    for (int idx = threadIdx.x; idx < 16384; idx += 256) {
        int e = idx >> 7, d = idx & 127;
        float acc = 0.f;
        for (int n = 0; n < 256; n++) {
            size_t t = (size_t)(c * 256 + n) * QKVW + (size_t)h * DH;
            acc += expf(-s * (float)(255 - n)) * g_qkv[t + 2048 + d] * g_qkv[t + 4096 + e];
        }
        g_kvblk[((size_t)(h * 32 + c)) * 16384 + (size_t)e * 128 + d] = acc;
    }
#endif
}

// ============ Phase B: decay scan — 256 CTAs ================================
__global__ void kvscan_kernel() {
    int h = blockIdx.x >> 4;
    int seg = blockIdx.x & 15;
    float bdec = expf(-g_slopes[h] * 256.0f);
    int e = seg * 1024 + threadIdx.x;
    #pragma unroll
    for (int r = 0; r < 4; r++, e += 256) {
        float acc = 0.f;
        size_t base = (size_t)h * NCHUNK * 16384 + e;
        #pragma unroll
        for (int c = 0; c < NCHUNK; c++) {
            g_kvstate[base + (size_t)c * 16384] = acc;
            acc = bdec * acc + g_kvblk[base + (size_t)c * 16384];
        }
    }
}

// ============ Phase C: attention output (tensor, fp16 2-term) ==============
__global__ __launch_bounds__(256, 1) void attn_tensor_kernel() {
#if HAS_TCGEN05
    extern __shared__ char smem[];
    uint32_t sb = smem_to_u32(smem);
    int tid = threadIdx.x;
    int mi = blockIdx.x & 1, c = (blockIdx.x >> 1) & 31, h = blockIdx.x >> 6;
    float s = g_slopes[h];
    float* decay_tab = (float*)(smem + 16);
    const int QH   = 2048;                 // q single fp16 [128,128] 32KB
    const int KVHI = 34816, KVLO = 67584;  // kvstT hi/lo 32KB each
    const int KHI  = 34816, KLO  = 51200;  // reuse: k chunk hi/lo 16KB each
    const int VHI  = 67584, VLO  = 83968;  // reuse: vT chunk hi/lo 16KB each
    const int SH   = 100352;               // S single fp16 [128,64] 16KB
    uint32_t mb = sb + 8;
    if (tid < 32) TCGEN05_ALLOC(sb, 512);
    if (tid == 0) MBARRIER_INIT(mb, 1);
    for (int i = tid; i < 257; i += 256) decay_tab[i] = expf(-s * (float)i);
    __syncthreads();
    uint32_t tmem;
    asm volatile("ld.shared.b32 %0, [%1];" : "=r"(tmem) : "r"(sb));
    if (tid < 32) TCGEN05_RELINQ();
    const uint32_t O1T = tmem, O2T = tmem + 128, ST = tmem + 256;
    const uint32_t IDESC128F = (1u << 4) | (16u << 17) | (8u << 24);
    const uint32_t IDESC64F  = (1u << 4) | (8u  << 17) | (8u << 24);

    // ---- load q (single fp16, blocked) ----
    const float* qb = g_qkv + (size_t)(c * 256 + mi * 128) * QKVW + (size_t)h * DH;
    #pragma unroll
    for (int it = 0; it < 16; it++) {
        int j = it * 256 + tid;
        int r = j >> 5, dq = (j & 31) << 2;
        float4 v = *(const float4*)&qb[(size_t)r * QKVW + dq];
        uint32_t o = bswz(r, dq, 16);
        *(uint2*)(smem + QH + o) = make_uint2(
            pkh(__float2half_rn(v.x), __float2half_rn(v.y)),
            pkh(__float2half_rn(v.z), __float2half_rn(v.w)));
    }
    // ---- load kvstT (fp16 hi/lo) ----
    const float* kvb = g_kvstate + (size_t)(h * 32 + c) * 16384;
    #pragma unroll
    for (int it = 0; it < 16; it++) {
        int j = it * 256 + tid;
        int r = j >> 5, dq = (j & 31) << 2;
        float4 v = *(const float4*)&kvb[(size_t)r * 128 + dq];
        __half h0 = __float2half_rn(v.x), h1 = __float2half_rn(v.y);
        __half h2 = __float2half_rn(v.z), h3 = __float2half_rn(v.w);
        uint32_t o = bswz(r, dq, 16);
        *(uint2*)(smem + KVHI + o) = make_uint2(pkh(h0, h1), pkh(h2, h3));
        *(uint2*)(smem + KVLO + o) = make_uint2(
            pkh(__float2half_rn(v.x - __half2float(h0)), __float2half_rn(v.y - __half2float(h1))),
            pkh(__float2half_rn(v.z - __half2float(h2)), __float2half_rn(v.w - __half2float(h3))));
    }
    FENCE_ASYNC_SHARED();
    __syncthreads();
    int ph = 0;
    // ---- MMA1: O1 = q·(kvst_hi + kvst_lo)^T ----
    if (tid < 32) {
        uint64_t dQ = MAKE_SMEM_DESC(sb + QH);
        uint64_t dKh = MAKE_SMEM_DESC(sb + KVHI), dKl = MAKE_SMEM_DESC(sb + KVLO);
        if (elect_one_pred()) {
            #pragma unroll
            for (int st = 0; st < 8; st++) {
                uint32_t u = ((st >> 2) << 10) + ((st & 3) << 1);
                mma_f16_ss(O1T, dQ + u, dKh + u, IDESC128F, st != 0);
                mma_f16_ss(O1T, dQ + u, dKl + u, IDESC128F, true);
            }
            TCGEN05_COMMIT(mb);
        }
    }
    MBARRIER_WAIT_PARITY(mb, ph & 1); ph++;

    const int nch = 2 * mi + 2;
    for (int cn = 0; cn < nch; cn++) {
        // ---- load k chunk [64,128] fp16 hi/lo ----
        const float* kb = g_qkv + (size_t)(c * 256 + cn * 64) * QKVW + 2048 + (size_t)h * DH;
        #pragma unroll
        for (int it = 0; it < 8; it++) {
            int j = it * 256 + tid;
            int r = j >> 5, dq = (j & 31) << 2;
            float4 v = *(const float4*)&kb[(size_t)r * QKVW + dq];
            __half h0 = __float2half_rn(v.x), h1 = __float2half_rn(v.y);
            __half h2 = __float2half_rn(v.z), h3 = __float2half_rn(v.w);
            uint32_t o = bswz(r, dq, 8);
            *(uint2*)(smem + KHI + o) = make_uint2(pkh(h0, h1), pkh(h2, h3));
            *(uint2*)(smem + KLO + o) = make_uint2(
                pkh(__float2half_rn(v.x - __half2float(h0)), __float2half_rn(v.y - __half2float(h1))),
                pkh(__float2half_rn(v.z - __half2float(h2)), __float2half_rn(v.w - __half2float(h3))));
        }
        // ---- load vT chunk (pre-swizzled fp16 blobs) ----
        {
            const uint4* sh = (const uint4*)(g_vThi + (size_t)(h * 32 + c) * 32768 + cn * 8192);
            const uint4* sl = (const uint4*)(g_vTlo + (size_t)(h * 32 + c) * 32768 + cn * 8192);
            uint4* dh = (uint4*)(smem + VHI);
            uint4* dl = (uint4*)(smem + VLO);
            #pragma unroll
            for (int it = 0; it < 4; it++) {
                int j = it * 256 + tid;
                dh[j] = sh[j];
                dl[j] = sl[j];
            }
        }
        FENCE_ASYNC_SHARED();
        __syncthreads();
        // ---- MMA_S: S = q·(k_hi + k_lo)^T ----
        if (tid < 32) {
            uint64_t dQ = MAKE_SMEM_DESC(sb + QH);
            uint64_t dKh = MAKE_SMEM_DESC(sb + KHI), dKl = MAKE_SMEM_DESC(sb + KLO);
            if (elect_one_pred()) {
                #pragma unroll
                for (int st = 0; st < 8; st++) {
                    uint32_t uq = ((st >> 2) << 10) + ((st & 3) << 1);
                    uint32_t uk = ((st >> 2) << 9) + ((st & 3) << 1);
                    mma_f16_ss(ST, dQ + uq, dKh + uk, IDESC64F, st != 0);
                    mma_f16_ss(ST, dQ + uq, dKl + uk, IDESC64F, true);
                }
                TCGEN05_COMMIT(mb);
            }
        }
        MBARRIER_WAIT_PARITY(mb, ph & 1); ph++;
        TCGEN05_FENCE_AFTER();
        // ---- read S, apply decay, single fp16 store ----
        if (tid < 128) {
            int w = tid >> 5, l = tid & 31, m = w * 32 + l;
            int gm = mi * 128 + m;
            uint32_t r0[32], r1[32];
            TCGEN05_LD_X32(r0, ST);
            TCGEN05_WAIT_LD();
            TCGEN05_LD_X32(r1, ST + 32);
            TCGEN05_WAIT_LD();
            #pragma unroll
            for (int g = 0; g < 8; g++) {
                uint32_t hp[4];
                #pragma unroll
                for (int jj = 0; jj < 4; jj++) {
                    int j0 = g * 8 + jj * 2;
                    float v0 = __uint_as_float(j0 < 32 ? r0[j0] : r1[j0 - 32]);
                    float v1 = __uint_as_float((j0 + 1) < 32 ? r0[j0 + 1] : r1[j0 - 31]);
                    int gn0 = cn * 64 + j0;
                    v0 = (gm >= gn0)     ? v0 * decay_tab[gm - gn0]     : 0.f;
                    v1 = (gm >= gn0 + 1) ? v1 * decay_tab[gm - gn0 - 1] : 0.f;
                    hp[jj] = pkh(__float2half_rn(v0), __float2half_rn(v1));
                }
                uint32_t o = bswz(m, g * 8, 16);
                *(uint4*)(smem + SH + o) = make_uint4(hp[0], hp[1], hp[2], hp[3]);
            }
        }
        FENCE_ASYNC_SHARED();
        __syncthreads();
        // ---- MMA_O: O2 += S·(vT_hi + vT_lo)^T ----
        if (tid < 32) {
            uint64_t dS = MAKE_SMEM_DESC(sb + SH);
            uint64_t dVh = MAKE_SMEM_DESC(sb + VHI), dVl = MAKE_SMEM_DESC(sb + VLO);
            if (elect_one_pred()) {
                #pragma unroll
                for (int st = 0; st < 4; st++) {
                    uint32_t u = (uint32_t)st << 1;
                    bool first = (cn == 0 && st == 0);
                    mma_f16_ss(O2T, dS + u, dVh + u, IDESC128F, !first);
                    mma_f16_ss(O2T, dS + u, dVl + u, IDESC128F, true);
                }
                TCGEN05_COMMIT(mb);
            }
        }
        MBARRIER_WAIT_PARITY(mb, ph & 1); ph++;
    }
    TCGEN05_FENCE_AFTER();
    if (tid < 128) {
        int w = tid >> 5, l = tid & 31, m = w * 32 + l;
        int gm = mi * 128 + m;
        float qd = decay_tab[gm + 1];
        float* dst = g_attn + (size_t)(c * 256 + gm) * HIDDEN + (size_t)h * DH;
        #pragma unroll
        for (int cb = 0; cb < 4; cb++) {
            uint32_t a[32], b[32];
            TCGEN05_LD_X32(a, O1T + cb * 32);
            TCGEN05_WAIT_LD();
            TCGEN05_LD_X32(b, O2T + cb * 32);
            TCGEN05_WAIT_LD();
            #pragma unroll
            for (int j = 0; j < 32; j += 4)
                *(float4*)&dst[cb * 32 + j] = make_float4(
                    qd * __uint_as_float(a[j])     + __uint_as_float(b[j]),
                    qd * __uint_as_float(a[j + 1]) + __uint_as_float(b[j + 1]),
                    qd * __uint_as_float(a[j + 2]) + __uint_as_float(b[j + 2]),
                    qd * __uint_as_float(a[j + 3]) + __uint_as_float(b[j + 3]));
        }
    }
    __syncthreads();
    if (tid < 32) TCGEN05_DEALLOC(tmem, 512);
#else
    int mi = blockIdx.x & 1, c = (blockIdx.x >> 1) & 31, h = blockIdx.x >> 6;
    float s = g_slopes[h];
    const float* kvst = g_kvstate + (size_t)(h * 32 + c) * 16384;
    for (int idx = threadIdx.x; idx < 16384; idx += 256) {
        int m = idx >> 7, e = idx & 127;
        int gm = mi * 128 + m;
        size_t tq = (size_t)(c * 256 + gm) * QKVW + (size_t)h * DH;
        float o = 0.f;
        for (int d = 0; d < 128; d++) o += g_qkv[tq + d] * kvst[(size_t)e * 128 + d];
        o *= expf(-s * (float)(gm + 1));
        for (int n = 0; n <= gm; n++) {
            size_t tk = (size_t)(c * 256 + n) * QKVW + (size_t)h * DH;
            float qk = 0.f;
            for (int d = 0; d < 128; d++) qk += g_qkv[tq + d] * g_qkv[tk + 2048 + d];
            o += expf(-s * (float)(gm - n)) * qk * g_qkv[tk + 4096 + e];
        }
        g_attn[(size_t)(c * 256 + gm) * HIDDEN + (size_t)h * DH + e] = o;
    }
#endif
}

// ============ RMS norm + sigmoid gate -> fp16 output ========================
__global__ void rmsgate_kernel(const float* __restrict__ gnw) {
    int t = blockIdx.x;
    int tid = threadIdx.x;
    const float* a = g_attn + (size_t)t * HIDDEN;
    const float* g = g_gate + (size_t)t * HIDDEN;
    float ss = 0.f;
    for (int j = tid; j < HIDDEN; j += 256) { float v = a[j]; ss += v * v; }
    #pragma unroll
    for (int o = 16; o; o >>= 1) ss += __shfl_xor_sync(0xffffffffu, ss, o);
    __shared__ float red[8];
    __shared__ float tot;
    if ((tid & 31) == 0) red[tid >> 5] = ss;
    __syncthreads();
    if (tid == 0) {
        float tsum = 0.f;
        #pragma unroll
        for (int w = 0; w < 8; w++) tsum += red[w];
        tot = tsum;
    }
    __syncthreads();
    float rms = rsqrtf(tot * (1.0f / HIDDEN) + 1e-5f);
    for (int j = tid; j < HIDDEN; j += 256) {
        float gv = g[j];
        float sig = 1.0f / (1.0f + expf(-gv));
        float val = a[j] * rms * gnw[j] * sig;
        g_yh[(size_t)t * HIDDEN + j] = __float2half_rn(val);
    }
}

// ================= launch =====================================================
extern "C" void kernel_launch(void* const* d_in, const int* in_sizes, int n_in,
                              void* d_out, int out_size) {
    const float* hidden    = (const float*)d_in[0];
    const int*   positions = (const int*)d_in[1];
    const float* Wqkv      = (const float*)d_in[2];
    const float* Wg        = (const float*)d_in[3];
    const float* Wd        = (const float*)d_in[4];
    const float* gnw       = (const float*)d_in[5];
    float* out = (float*)d_out;

    void *ah_p, *yh_p;
    void *bqh_p, *bql_p, *bgh_p, *bgl_p, *bdh_p, *bdl_p;
    cudaGetSymbolAddress(&ah_p, g_ah);
    cudaGetSymbolAddress(&yh_p, g_yh);
    cudaGetSymbolAddress(&bqh_p, g_bqkv_hi); cudaGetSymbolAddress(&bql_p, g_bqkv_lo);
    cudaGetSymbolAddress(&bgh_p, g_bg_hi);   cudaGetSymbolAddress(&bgl_p, g_bg_lo);
    cudaGetSymbolAddress(&bdh_p, g_bd_hi);   cudaGetSymbolAddress(&bdl_p, g_bd_lo);

    cudaFuncSetAttribute(gemm_qkvgate, cudaFuncAttributeMaxDynamicSharedMemorySize, CG2_SMEM);
    cudaFuncSetAttribute(gemm_down, cudaFuncAttributeMaxDynamicSharedMemorySize, CG2_SMEM);
    const int kvblk_smem = 2048 + 67584 + 4 * 32768;
    cudaFuncSetAttribute(kvblkT_kernel, cudaFuncAttributeMaxDynamicSharedMemorySize, kvblk_smem);
    const int attn_smem = 100352 + 16384;   // 116736
    cudaFuncSetAttribute(attn_tensor_kernel, cudaFuncAttributeMaxDynamicSharedMemorySize, attn_smem);

    init_tables<<<1, 64>>>();
    conv_act<<<(NTOK * HIDDEN / 4 + 255) / 256, 256>>>(hidden, (__half*)ah_p,
                                                       NTOK * HIDDEN / 4);
    transposeW<<<dim3(QKVW / 32, HIDDEN / 32), 256>>>(Wqkv,
        (__half*)bqh_p, (__half*)bql_p, HIDDEN, QKVW);
    transposeW<<<dim3(HIDDEN / 32, HIDDEN / 32), 256>>>(Wg,
        (__half*)bgh_p, (__half*)bgl_p, HIDDEN, HIDDEN);
    transposeW<<<dim3(HIDDEN / 32, HIDDEN / 32), 256>>>(Wd,
        (__half*)bdh_p, (__half*)bdl_p, HIDDEN, HIDDEN);
    gemm_qkvgate<<<dim3(((QKVW + HIDDEN) / 256) * 2, NTOK / 256), 256, CG2_SMEM>>>(
        (const __half*)ah_p, positions);
    kvblkT_kernel<<<HEADS * NCHUNK, 256, kvblk_smem>>>();
    kvscan_kernel<<<HEADS * 16, 256>>>();
    attn_tensor_kernel<<<HEADS * NCHUNK * 2, 256, attn_smem>>>();
    rmsgate_kernel<<<NTOK, 256>>>(gnw);
    gemm_down<<<dim3((HIDDEN / 256) * 2, NTOK / 256), 256, CG2_SMEM>>>(
        (const __half*)yh_p,
        (const __half*)bdh_p, (const __half*)bdl_p,
        out, HIDDEN, HIDDEN);
}

// round 13
// speedup vs baseline: 1.1393x; 1.0222x over previous
#include <cuda_runtime.h>
#include <cuda_bf16.h>
#include <cuda_fp16.h>
#include <math.h>
#include <cstdint>

#define NTOK 8192
#define HIDDEN 2048
#define HEADS 16
#define DH 128
#define BLK 256
#define NCHUNK 32
#define QKVW 6144

#if defined(__CUDA_ARCH_FEAT_SM103_ALL) || \
    (defined(__CUDA_ARCH_SPECIFIC__) && (__CUDA_ARCH_SPECIFIC__ == 1030)) || \
    (defined(__CUDA_ARCH_FAMILY_SPECIFIC__) && (__CUDA_ARCH_FAMILY_SPECIFIC__ == 1030))
#define HAS_TCGEN05 1
#else
#define HAS_TCGEN05 0
#endif

// ================= PTX helpers ==============================================
__device__ __forceinline__ uint32_t elect_one_pred() {
    uint32_t pred;
    asm volatile("{\n\t.reg .pred p;\n\telect.sync _|p, 0xFFFFFFFF;\n\t"
                 "selp.b32 %0, 1, 0, p;\n\t}" : "=r"(pred));
    return pred;
}
__device__ __forceinline__ uint32_t smem_to_u32(const void* p) {
    uint32_t a;
    asm("{ .reg .u64 t; cvta.to.shared.u64 t, %1; cvt.u32.u64 %0, t; }"
        : "=r"(a) : "l"(p));
    return a;
}
__device__ __forceinline__ uint32_t cluster_rank() {
    uint32_t r;
    asm("mov.u32 %0, %%cluster_ctarank;" : "=r"(r));
    return r;
}
#define CLUSTER_SYNC() do { \
    asm volatile("barrier.cluster.arrive.aligned;" ::: "memory"); \
    asm volatile("barrier.cluster.wait.aligned;" ::: "memory"); \
} while (0)
#define MBARRIER_INIT(addr, cnt) \
    asm volatile("mbarrier.init.shared.b64 [%0], %1;" :: "r"((uint32_t)(addr)), "r"((uint32_t)(cnt)) : "memory")
#define MBARRIER_WAIT_PARITY(addr, par) do { \
    uint32_t _m = (uint32_t)(addr); uint32_t _p = (uint32_t)(par); uint32_t _d; \
    asm volatile("{\n\t.reg .pred p;\n\t" \
        "mbarrier.try_wait.parity.acquire.cta.shared::cta.b64 p, [%1], %2;\n\t" \
        "selp.b32 %0, 1, 0, p;\n\t}" : "=r"(_d) : "r"(_m), "r"(_p) : "memory"); \
    if (!_d) { \
        asm volatile("{\n\t.reg .pred P1;\n\t" \
            "WL_%=:\n\t" \
            "mbarrier.try_wait.parity.acquire.cta.shared::cta.b64 P1, [%0], %1, 0x989680;\n\t" \
            "@P1 bra.uni WD_%=;\n\tbra.uni WL_%=;\n\tWD_%=:\n\t}" \
            :: "r"(_m), "r"(_p) : "memory"); \
    } } while (0)
#define MBARRIER_WAIT_PARITY_CL(addr, par) do { \
    uint32_t _m = (uint32_t)(addr); uint32_t _p = (uint32_t)(par); uint32_t _d; \
    asm volatile("{\n\t.reg .pred p;\n\t" \
        "mbarrier.try_wait.parity.acquire.cluster.shared::cta.b64 p, [%1], %2;\n\t" \
        "selp.b32 %0, 1, 0, p;\n\t}" : "=r"(_d) : "r"(_m), "r"(_p) : "memory"); \
    if (!_d) { \
        asm volatile("{\n\t.reg .pred P1;\n\t" \
            "WL_%=:\n\t" \
            "mbarrier.try_wait.parity.acquire.cluster.shared::cta.b64 P1, [%0], %1, 0x989680;\n\t" \
            "@P1 bra.uni WD_%=;\n\tbra.uni WL_%=;\n\tWD_%=:\n\t}" \
            :: "r"(_m), "r"(_p) : "memory"); \
    } } while (0)
#define MBARRIER_ARRIVE_CLUSTER(local_addr, target_rank) \
    asm volatile( \
        "{\n\t.reg .b32 remAddr32;\n\t" \
        "mapa.shared::cluster.u32 remAddr32, %0, %1;\n\t" \
        "mbarrier.arrive.release.cluster.shared::cluster.b64 _, [remAddr32];\n\t}" \
        :: "r"((uint32_t)(local_addr)), "r"((uint32_t)(target_rank)) : "memory")
#define TCGEN05_ALLOC(smem_addr, n) \
    asm volatile("tcgen05.alloc.cta_group::1.sync.aligned.shared::cta.b32 [%0], %1;" \
        :: "r"((uint32_t)(smem_addr)), "r"((uint32_t)(n)) : "memory")
#define TCGEN05_DEALLOC(tmem, n) \
    asm volatile("tcgen05.dealloc.cta_group::1.sync.aligned.b32 %0, %1;" :: "r"(tmem), "r"((uint32_t)(n)))
#define TCGEN05_RELINQ() \
    asm volatile("tcgen05.relinquish_alloc_permit.cta_group::1.sync.aligned;")
#define TCGEN05_ALLOC_CG2(smem_addr, n) \
    asm volatile("tcgen05.alloc.cta_group::2.sync.aligned.shared::cta.b32 [%0], %1;" \
        :: "r"((uint32_t)(smem_addr)), "r"((uint32_t)(n)) : "memory")
#define TCGEN05_DEALLOC_CG2(tmem, n) \
    asm volatile("tcgen05.dealloc.cta_group::2.sync.aligned.b32 %0, %1;" :: "r"(tmem), "r"((uint32_t)(n)))
#define TCGEN05_RELINQ_CG2() \
    asm volatile("tcgen05.relinquish_alloc_permit.cta_group::2.sync.aligned;")
#define TCGEN05_COMMIT(mbar) \
    asm volatile("tcgen05.commit.cta_group::1.mbarrier::arrive::one.shared::cluster.b64 [%0];" \
        :: "r"((uint32_t)(mbar)) : "memory")
#define TCGEN05_COMMIT_MC_CG2(mbar, mask) \
    asm volatile("tcgen05.commit.cta_group::2.mbarrier::arrive::one.shared::cluster.multicast::cluster.b64 [%0], %1;" \
        :: "r"((uint32_t)(mbar)), "h"((uint16_t)(mask)) : "memory")
#define TCGEN05_FENCE_AFTER() asm volatile("tcgen05.fence::after_thread_sync;" ::: "memory")
#define TCGEN05_WAIT_LD() asm volatile("tcgen05.wait::ld.sync.aligned;" ::: "memory")
#define FENCE_ASYNC_SHARED() asm volatile("fence.proxy.async.shared::cta;" ::: "memory")
#define TCGEN05_LD_X32(r, addr) \
    asm volatile("tcgen05.ld.sync.aligned.32x32b.x32.b32 " \
        "{%0, %1, %2, %3, %4, %5, %6, %7, %8, %9, %10, %11, %12, %13, %14, %15, " \
        " %16, %17, %18, %19, %20, %21, %22, %23, %24, %25, %26, %27, %28, %29, %30, %31}, [%32];" \
        : "=r"((r)[0]),  "=r"((r)[1]),  "=r"((r)[2]),  "=r"((r)[3]), \
          "=r"((r)[4]),  "=r"((r)[5]),  "=r"((r)[6]),  "=r"((r)[7]), \
          "=r"((r)[8]),  "=r"((r)[9]),  "=r"((r)[10]), "=r"((r)[11]), \
          "=r"((r)[12]), "=r"((r)[13]), "=r"((r)[14]), "=r"((r)[15]), \
          "=r"((r)[16]), "=r"((r)[17]), "=r"((r)[18]), "=r"((r)[19]), \
          "=r"((r)[20]), "=r"((r)[21]), "=r"((r)[22]), "=r"((r)[23]), \
          "=r"((r)[24]), "=r"((r)[25]), "=r"((r)[26]), "=r"((r)[27]), \
          "=r"((r)[28]), "=r"((r)[29]), "=r"((r)[30]), "=r"((r)[31]) \
        : "r"(addr))

static constexpr uint64_t SMEM_DESC_BASE_SW128 =
    (uint64_t(2) << 61) | (uint64_t(1) << 46) | (uint64_t(64) << 32) | (uint64_t(1) << 16);
#define MAKE_SMEM_DESC(a) (SMEM_DESC_BASE_SW128 | ((uint64_t)((a) >> 4) & 0x3FFF))

#if HAS_TCGEN05
__device__ __forceinline__ void mma_f16_ss(uint32_t d_tmem, uint64_t a_desc,
                                           uint64_t b_desc, uint32_t idesc, bool acc) {
    uint32_t en = acc ? 1u : 0u;
    asm volatile(
        "{\n\t.reg .pred p;\n\tsetp.ne.u32 p, %5, 0;\n\t"
        "tcgen05.mma.cta_group::1.kind::f16 [%0], %1, %2, %3, {%4, %4, %4, %4}, p;\n\t}"
        :: "r"(d_tmem), "l"(a_desc), "l"(b_desc), "r"(idesc), "r"(0u), "r"(en)
        : "memory");
}
__device__ __forceinline__ void mma_f16_ss_cg2(uint32_t d_tmem, uint64_t a_desc,
                                               uint64_t b_desc, uint32_t idesc, bool acc) {
    uint32_t en = acc ? 1u : 0u;
    asm volatile(
        "{\n\t.reg .pred p;\n\tsetp.ne.u32 p, %5, 0;\n\t"
        "tcgen05.mma.cta_group::2.kind::f16 [%0], %1, %2, %3, "
        "{%4, %4, %4, %4, %4, %4, %4, %4}, p;\n\t}"
        :: "r"(d_tmem), "l"(a_desc), "l"(b_desc), "r"(idesc), "r"(0u), "r"(en)
        : "memory");
}
#endif

__device__ __forceinline__ uint32_t bswz(int row, int col, int atomrows) {
    uint32_t off = (uint32_t)(((row >> 3) + (col >> 6) * atomrows) << 10)
                 + ((row & 7) << 7) + ((col & 63) << 1);
    return off ^ ((off >> 3) & 0x70);
}
__device__ __forceinline__ uint32_t pkh(__half a, __half b) {
    __half2 t{a, b};
    return *(uint32_t*)&t;
}

// ================= scratch ===================================================
__device__ float g_qkv[(size_t)NTOK * QKVW];
__device__ float g_gate[(size_t)NTOK * HIDDEN];
__device__ float g_attn[(size_t)NTOK * HIDDEN];
__device__ float g_kvblk[(size_t)HEADS * NCHUNK * DH * DH];
__device__ float g_kvstate[(size_t)HEADS * NCHUNK * DH * DH];
__device__ float g_invf[64];
__device__ float g_slopes[HEADS];
__device__ __half g_vThi[(size_t)HEADS * NCHUNK * 32768];
__device__ __half g_ah[(size_t)NTOK * HIDDEN];
__device__ __half g_yh[(size_t)NTOK * HIDDEN];
__device__ __half g_bqkv_hi[(size_t)QKVW * HIDDEN];
__device__ __half g_bqkv_lo[(size_t)QKVW * HIDDEN];
__device__ __half g_bg_hi[(size_t)HIDDEN * HIDDEN];
__device__ __half g_bg_lo[(size_t)HIDDEN * HIDDEN];
__device__ __half g_bd_hi[(size_t)HIDDEN * HIDDEN];
__device__ __half g_bd_lo[(size_t)HIDDEN * HIDDEN];

// ================= init tables ================================================
__global__ void init_tables() {
    int t = threadIdx.x;
    if (t < 64) g_invf[t] = (float)pow(600000.0, -(double)t / 64.0);
    if (t < HEADS) {
        double start = pow(2.0, -pow(2.0, -(log2(16.0) - 3.0)));
        g_slopes[t] = (float)(start * pow(start, (double)t) * (1.0 + 1e-5));
    }
}

// ================= convert fp32 -> fp16 (A operand, single) =================
__global__ void conv_act(const float* __restrict__ x, __half* __restrict__ h, int n4) {
    int i = blockIdx.x * blockDim.x + threadIdx.x;
    if (i >= n4) return;
    float4 v = ((const float4*)x)[i];
    __half2 a{__float2half_rn(v.x), __float2half_rn(v.y)};
    __half2 b{__float2half_rn(v.z), __float2half_rn(v.w)};
    ((__half2*)h)[i * 2]     = a;
    ((__half2*)h)[i * 2 + 1] = b;
}

// ======= transpose + split W[K,N] fp32 -> Thi/Tlo [N,K] fp16 ================
__global__ void transposeW(const float* __restrict__ W, __half* __restrict__ Thi,
                           __half* __restrict__ Tlo, int K, int N) {
    __shared__ float t[32][33];
    int n0 = blockIdx.x * 32, k0 = blockIdx.y * 32;
    int c = threadIdx.x & 31, r0 = threadIdx.x >> 5;
    #pragma unroll
    for (int rr = r0; rr < 32; rr += 8)
        t[rr][c] = W[(size_t)(k0 + rr) * N + n0 + c];
    __syncthreads();
    #pragma unroll
    for (int rr = r0; rr < 32; rr += 8) {
        float v = t[c][rr];
        __half h = __float2half_rn(v);
        Thi[(size_t)(n0 + rr) * K + k0 + c] = h;
        Tlo[(size_t)(n0 + rr) * K + k0 + c] = __float2half_rn(v - __half2float(h));
    }
}

#if HAS_TCGEN05
template <int ROWS>
__device__ __forceinline__ void load_tile(char* dst, const __half* src, int ld) {
    int tid = threadIdx.x;
    #pragma unroll
    for (int l = 0; l < ROWS / 32; l++) {
        int i = l * 256 + tid;
        int r = i >> 3, sg = i & 7;
        uint4 v = *(const uint4*)(src + (size_t)r * ld + sg * 8);
        uint32_t off = (uint32_t)(r * 128 + sg * 16);
        off ^= (off >> 3) & 0x70;
        *(uint4*)(dst + off) = v;
    }
}
#endif

// ======= cg2 fp16 GEMM constants (K-chunk 64) ================================
#define CG2_BUF 49152
#define CG2_SMEM (1024 + 2 * CG2_BUF)
#define IDESC_CG2 ((1u << 4) | (32u << 17) | (16u << 24))

// ======= fused qkv+gate GEMM (cg2 fp16; gate B-lo skipped) ===================
__global__ __launch_bounds__(256, 1) __cluster_dims__(2, 1, 1)
void gemm_qkvgate(const __half* __restrict__ A, const int* __restrict__ positions) {
    const int K = HIDDEN;
    uint32_t rank = cluster_rank();
    int bm = blockIdx.y * 256;
    int bn = (blockIdx.x >> 1) * 256;
    int gcs = bn + (int)rank * 128;
    bool isGate = (bn >= QKVW);
    const __half* Bhi = (gcs < QKVW) ? g_bqkv_hi + (size_t)gcs * K
                                     : g_bg_hi + (size_t)(gcs - QKVW) * K;
    const __half* Blo = (gcs < QKVW) ? g_bqkv_lo + (size_t)gcs * K
                                     : g_bg_lo + (size_t)(gcs - QKVW) * K;
#if HAS_TCGEN05
    extern __shared__ char smem[];
    uint32_t sb = smem_to_u32(smem);
    int tid = threadIdx.x;
    const uint32_t dn0 = sb + 8,  dn1 = sb + 16;
    const uint32_t rd0 = sb + 24, rd1 = sb + 32;
    if (tid < 32) TCGEN05_ALLOC_CG2(sb, 256);
    if (tid == 0) {
        MBARRIER_INIT(dn0, 1); MBARRIER_INIT(dn1, 1);
        MBARRIER_INIT(rd0, 2); MBARRIER_INIT(rd1, 2);
    }
    __syncthreads();
    uint32_t tmem;
    asm volatile("ld.shared.b32 %0, [%1];" : "=r"(tmem) : "r"(sb));
    if (tid < 32) TCGEN05_RELINQ_CG2();
    CLUSTER_SYNC();

    const __half* pA = A + (size_t)(bm + rank * 128) * K;

    int phd[2] = {0, 0};
    int phr[2] = {0, 0};
    for (int ch = 0; ch < 32; ch++) {
        int b = ch & 1;
        char* st = smem + 1024 + b * CG2_BUF;
        if (ch >= 2) {
            MBARRIER_WAIT_PARITY_CL(b ? dn1 : dn0, phd[b]);
            phd[b] ^= 1;
        }
        int k0 = ch << 6;
        load_tile<128>(st,         pA + k0,  K);
        load_tile<128>(st + 16384, Bhi + k0, K);
        if (!isGate) load_tile<128>(st + 32768, Blo + k0, K);
        FENCE_ASYNC_SHARED();
        __syncthreads();
        if (tid == 0) MBARRIER_ARRIVE_CLUSTER(b ? rd1 : rd0, 0);
        if (rank == 0 && tid < 32) {
            MBARRIER_WAIT_PARITY_CL(b ? rd1 : rd0, phr[b]);
            phr[b] ^= 1;
            uint32_t sa = sb + 1024 + b * CG2_BUF;
            uint64_t dA  = MAKE_SMEM_DESC(sa);
            uint64_t dBh = MAKE_SMEM_DESC(sa + 16384);
            uint64_t dBl = MAKE_SMEM_DESC(sa + 32768);
            if (elect_one_pred()) {
                #pragma unroll
                for (int k = 0; k < 4; k++) {
                    bool first = (ch == 0) && (k == 0);
                    mma_f16_ss_cg2(tmem, dA + k * 2, dBh + k * 2, IDESC_CG2, !first);
                    if (!isGate)
                        mma_f16_ss_cg2(tmem, dA + k * 2, dBl + k * 2, IDESC_CG2, true);
                }
                TCGEN05_COMMIT_MC_CG2(b ? dn1 : dn0, 0x3);
            }
        }
    }
    MBARRIER_WAIT_PARITY_CL(dn0, phd[0]);
    MBARRIER_WAIT_PARITY_CL(dn1, phd[1]);
    TCGEN05_FENCE_AFTER();
    __syncthreads();

    int w = tid >> 5, l = tid & 31;
    int sub = w & 3;
    int colbase = (w >> 2) * 128;
    int row = bm + (int)rank * 128 + sub * 32 + l;
    int gc0 = bn + colbase;
    bool isQ = gc0 < 2048;
    bool isK = (gc0 >= 2048) && (gc0 < 4096);
    float* dst = (gc0 < QKVW) ? g_qkv + (size_t)row * QKVW + gc0
                              : g_gate + (size_t)row * HIDDEN + (gc0 - QKVW);
    if (isQ || isK) {
        float pos = (float)positions[row];
        float qs = isQ ? 0.08838834764831845f : 1.0f;
        #pragma unroll
        for (int half = 0; half < 2; half++) {
            uint32_t a[32], b[32];
            TCGEN05_LD_X32(a, tmem + colbase + half * 32);
            TCGEN05_WAIT_LD();
            TCGEN05_LD_X32(b, tmem + colbase + half * 32 + 64);
            TCGEN05_WAIT_LD();
            #pragma unroll
            for (int j0 = 0; j0 < 32; j0 += 4) {
                float o1[4], o2[4];
                #pragma unroll
                for (int j = 0; j < 4; j++) {
                    int jin = half * 32 + j0 + j;
                    float f = pos * g_invf[jin];
                    float sv, cv;
                    sincosf(f, &sv, &cv);
                    float x1 = __uint_as_float(a[j0 + j]);
                    float x2 = __uint_as_float(b[j0 + j]);
                    o1[j] = (x1 * cv - x2 * sv) * qs;
                    o2[j] = (x2 * cv + x1 * sv) * qs;
                }
                *(float4*)&dst[half * 32 + j0]      = make_float4(o1[0], o1[1], o1[2], o1[3]);
                *(float4*)&dst[half * 32 + 64 + j0] = make_float4(o2[0], o2[1], o2[2], o2[3]);
            }
        }
    } else {
        #pragma unroll
        for (int cb = 0; cb < 128; cb += 32) {
            uint32_t r[32];
            TCGEN05_LD_X32(r, tmem + colbase + cb);
            TCGEN05_WAIT_LD();
            #pragma unroll
            for (int j = 0; j < 32; j += 4)
                *(float4*)&dst[cb + j] = make_float4(
                    __uint_as_float(r[j]), __uint_as_float(r[j + 1]),
                    __uint_as_float(r[j + 2]), __uint_as_float(r[j + 3]));
        }
    }
    __syncthreads();
    if (tid < 32) TCGEN05_DEALLOC_CG2(tmem, 256);
    CLUSTER_SYNC();
#else
    extern __shared__ char smemraw[];
    float* As = (float*)smemraw;
    float* Bs = As + 16 * 128;
    int tid = threadIdx.x;
    int bmr = bm + (int)rank * 128;
    int ty = tid >> 4, tx = tid & 15;
    float acc[8][16];
    #pragma unroll
    for (int i = 0; i < 8; i++)
        #pragma unroll
        for (int j = 0; j < 16; j++) acc[i][j] = 0.f;
    for (int k0 = 0; k0 < K; k0 += 16) {
        #pragma unroll
        for (int l = 0; l < 8; l++) {
            int i = l * 256 + tid;
            int k = i & 15, m = i >> 4;
            As[k * 128 + m] = __half2float(A[(size_t)(bmr + m) * K + k0 + k]);
        }
        #pragma unroll
        for (int l = 0; l < 16; l++) {
            int i = l * 256 + tid;
            int k = i & 15, n = i >> 4;
            int gc = bn + n;
            const __half* bh = (gc < QKVW) ? g_bqkv_hi + (size_t)gc * K
                                           : g_bg_hi + (size_t)(gc - QKVW) * K;
            const __half* bl = (gc < QKVW) ? g_bqkv_lo + (size_t)gc * K
                                           : g_bg_lo + (size_t)(gc - QKVW) * K;
            float bv = __half2float(bh[k0 + k]);
            if (!isGate) bv += __half2float(bl[k0 + k]);
            Bs[k * 256 + n] = bv;
        }
        __syncthreads();
        #pragma unroll
        for (int kk = 0; kk < 16; kk++) {
            float a[8], b[16];
            #pragma unroll
            for (int i = 0; i < 8; i++) a[i] = As[kk * 128 + ty * 8 + i];
            #pragma unroll
            for (int j = 0; j < 16; j++) b[j] = Bs[kk * 256 + tx * 16 + j];
            #pragma unroll
            for (int i = 0; i < 8; i++)
                #pragma unroll
                for (int j = 0; j < 16; j++) acc[i][j] += a[i] * b[j];
        }
        __syncthreads();
    }
    float* tileS = (float*)smemraw;
    #pragma unroll
    for (int i = 0; i < 8; i++)
        #pragma unroll
        for (int j = 0; j < 16; j++)
            tileS[(ty * 8 + i) * 257 + tx * 16 + j] = acc[i][j];
    __syncthreads();
    {
        int r = tid >> 1, sp = tid & 1;
        int row = bmr + r;
        int gc0 = bn + sp * 128;
        bool isQ = gc0 < 2048;
        bool isK = (gc0 >= 2048) && (gc0 < 4096);
        float* dst = (gc0 < QKVW) ? g_qkv + (size_t)row * QKVW + gc0
                                  : g_gate + (size_t)row * HIDDEN + (gc0 - QKVW);
        const float* src = &tileS[r * 257 + sp * 128];
        if (isQ || isK) {
            float pos = (float)positions[row];
            float qs = isQ ? 0.08838834764831845f : 1.0f;
            for (int j = 0; j < 64; j++) {
                float f = pos * g_invf[j];
                float sv, cv;
                sincosf(f, &sv, &cv);
                float x1 = src[j], x2 = src[j + 64];
                dst[j]      = (x1 * cv - x2 * sv) * qs;
                dst[j + 64] = (x2 * cv + x1 * sv) * qs;
            }
        } else {
            for (int j = 0; j < 128; j++) dst[j] = src[j];
        }
    }
#endif
}

// ================= cg2 fp16 2-term down-projection GEMM ======================
__global__ __launch_bounds__(256, 1) __cluster_dims__(2, 1, 1)
void gemm_down(const __half* __restrict__ A,
               const __half* __restrict__ Bhi, const __half* __restrict__ Blo,
               float* __restrict__ C, int Nn, int K) {
    uint32_t rank = cluster_rank();
    int bm = blockIdx.y * 256;
    int bn = (blockIdx.x >> 1) * 256;
#if HAS_TCGEN05
    extern __shared__ char smem[];
    uint32_t sb = smem_to_u32(smem);
    int tid = threadIdx.x;
    const uint32_t dn0 = sb + 8,  dn1 = sb + 16;
    const uint32_t rd0 = sb + 24, rd1 = sb + 32;
    if (tid < 32) TCGEN05_ALLOC_CG2(sb, 256);
    if (tid == 0) {
        MBARRIER_INIT(dn0, 1); MBARRIER_INIT(dn1, 1);
        MBARRIER_INIT(rd0, 2); MBARRIER_INIT(rd1, 2);
    }
    __syncthreads();
    uint32_t tmem;
    asm volatile("ld.shared.b32 %0, [%1];" : "=r"(tmem) : "r"(sb));
    if (tid < 32) TCGEN05_RELINQ_CG2();
    CLUSTER_SYNC();

    const __half* pA   = A   + (size_t)(bm + rank * 128) * K;
    const __half* pBhi = Bhi + (size_t)(bn + rank * 128) * K;
    const __half* pBlo = Blo + (size_t)(bn + rank * 128) * K;

    int phd[2] = {0, 0};
    int phr[2] = {0, 0};
    const int nch = K >> 6;
    for (int ch = 0; ch < nch; ch++) {
        int b = ch & 1;
        char* st = smem + 1024 + b * CG2_BUF;
        if (ch >= 2) {
            MBARRIER_WAIT_PARITY_CL(b ? dn1 : dn0, phd[b]);
            phd[b] ^= 1;
        }
        int k0 = ch << 6;
        load_tile<128>(st,         pA + k0,   K);
        load_tile<128>(st + 16384, pBhi + k0, K);
        load_tile<128>(st + 32768, pBlo + k0, K);
        FENCE_ASYNC_SHARED();
        __syncthreads();
        if (tid == 0) MBARRIER_ARRIVE_CLUSTER(b ? rd1 : rd0, 0);
        if (rank == 0 && tid < 32) {
            MBARRIER_WAIT_PARITY_CL(b ? rd1 : rd0, phr[b]);
            phr[b] ^= 1;
            uint32_t sa = sb + 1024 + b * CG2_BUF;
            uint64_t dA  = MAKE_SMEM_DESC(sa);
            uint64_t dBh = MAKE_SMEM_DESC(sa + 16384);
            uint64_t dBl = MAKE_SMEM_DESC(sa + 32768);
            if (elect_one_pred()) {
                #pragma unroll
                for (int k = 0; k < 4; k++) {
                    bool first = (ch == 0) && (k == 0);
                    mma_f16_ss_cg2(tmem, dA + k * 2, dBh + k * 2, IDESC_CG2, !first);
                    mma_f16_ss_cg2(tmem, dA + k * 2, dBl + k * 2, IDESC_CG2, true);
                }
                TCGEN05_COMMIT_MC_CG2(b ? dn1 : dn0, 0x3);
            }
        }
    }
    MBARRIER_WAIT_PARITY_CL(dn0, phd[0]);
    MBARRIER_WAIT_PARITY_CL(dn1, phd[1]);
    TCGEN05_FENCE_AFTER();
    __syncthreads();

    int w = tid >> 5, l = tid & 31;
    int sub = w & 3;
    int colbase = (w >> 2) * 128;
    int row = bm + (int)rank * 128 + sub * 32 + l;
    float* dst_row = C + (size_t)row * Nn + bn + colbase;
    #pragma unroll
    for (int cb = 0; cb < 128; cb += 32) {
        uint32_t r[32];
        TCGEN05_LD_X32(r, tmem + colbase + cb);
        TCGEN05_WAIT_LD();
        #pragma unroll
        for (int j = 0; j < 32; j += 4)
            *(float4*)(dst_row + cb + j) = make_float4(
                __uint_as_float(r[j]), __uint_as_float(r[j + 1]),
                __uint_as_float(r[j + 2]), __uint_as_float(r[j + 3]));
    }
    __syncthreads();
    if (tid < 32) TCGEN05_DEALLOC_CG2(tmem, 256);
    CLUSTER_SYNC();
#else
    extern __shared__ char smemraw[];
    float* As = (float*)smemraw;
    float* Bs = As + 16 * 128;
    int tid = threadIdx.x;
    int bmr = bm + (int)rank * 128;
    int ty = tid >> 4, tx = tid & 15;
    float acc[8][16];
    #pragma unroll
    for (int i = 0; i < 8; i++)
        #pragma unroll
        for (int j = 0; j < 16; j++) acc[i][j] = 0.f;
    for (int k0 = 0; k0 < K; k0 += 16) {
        #pragma unroll
        for (int l = 0; l < 8; l++) {
            int i = l * 256 + tid;
            int k = i & 15, m = i >> 4;
            As[k * 128 + m] = __half2float(A[(size_t)(bmr + m) * K + k0 + k]);
        }
        #pragma unroll
        for (int l = 0; l < 16; l++) {
            int i = l * 256 + tid;
            int k = i & 15, n = i >> 4;
            size_t off = (size_t)(bn + n) * K + k0 + k;
            Bs[k * 256 + n] = __half2float(Bhi[off]) + __half2float(Blo[off]);
        }
        __syncthreads();
        #pragma unroll
        for (int kk = 0; kk < 16; kk++) {
            float a[8], b[16];
            #pragma unroll
            for (int i = 0; i < 8; i++) a[i] = As[kk * 128 + ty * 8 + i];
            #pragma unroll
            for (int j = 0; j < 16; j++) b[j] = Bs[kk * 256 + tx * 16 + j];
            #pragma unroll
            for (int i = 0; i < 8; i++)
                #pragma unroll
                for (int j = 0; j < 16; j++) acc[i][j] += a[i] * b[j];
        }
        __syncthreads();
    }
    #pragma unroll
    for (int i = 0; i < 8; i++) {
        size_t off = (size_t)(bmr + ty * 8 + i) * Nn + bn + tx * 16;
        #pragma unroll
        for (int j = 0; j < 16; j += 4)
            *(float4*)&C[off + j] = make_float4(acc[i][j], acc[i][j + 1],
                                                acc[i][j + 2], acc[i][j + 3]);
    }
#endif
}

// ============ Phase A: kvblkT (tensor, fp16 2-term; V single) ===============
__global__ __launch_bounds__(256, 1) void kvblkT_kernel() {
#if HAS_TCGEN05
    extern __shared__ char smem[];
    uint32_t sb = smem_to_u32(smem);
    int tid = threadIdx.x;
    int h = blockIdx.x & 15, c = blockIdx.x >> 4;
    float s = g_slopes[h];
    float* decay_tab = (float*)(smem + 16);
    const int STG = 2048;
    const int KTHI = STG + 67584;
    const int KTLO = KTHI + 32768;
    const int VTHI = KTLO + 32768;
    uint32_t mb = sb + 8;
    if (tid < 32) TCGEN05_ALLOC(sb, 128);
    if (tid == 0) MBARRIER_INIT(mb, 1);
    for (int i = tid; i < 257; i += 256) decay_tab[i] = expf(-s * (float)i);
    __syncthreads();
    uint32_t tmem;
    asm volatile("ld.shared.b32 %0, [%1];" : "=r"(tmem) : "r"(sb));
    if (tid < 32) TCGEN05_RELINQ();
    float* stg = (float*)(smem + STG);
    const uint32_t IDESC128F = (1u << 4) | (16u << 17) | (8u << 24);

    for (int half = 0; half < 2; half++) {
        if (half == 1) MBARRIER_WAIT_PARITY(mb, 0);
        // ---- stage + transpose K (with decay), fp16 hi/lo ----
        const float* kb = g_qkv + (size_t)(c * 256 + half * 128) * QKVW + 2048 + (size_t)h * DH;
        #pragma unroll
        for (int it = 0; it < 16; it++) {
            int j = it * 256 + tid;
            int r = j >> 5, dq = (j & 31) << 2;
            *(float4*)&stg[r * 132 + dq] = *(const float4*)&kb[(size_t)r * QKVW + dq];
        }
        __syncthreads();
        #pragma unroll
        for (int it = 0; it < 8; it++) {
            int t = it * 256 + tid;
            int d = t & 127, g = t >> 7;
            uint32_t hp[4], lp[4];
            #pragma unroll
            for (int jj = 0; jj < 4; jj++) {
                int n0 = g * 8 + jj * 2;
                float v0 = stg[n0 * 132 + d]       * decay_tab[255 - (half * 128 + n0)];
                float v1 = stg[(n0 + 1) * 132 + d] * decay_tab[255 - (half * 128 + n0 + 1)];
                __half h0 = __float2half_rn(v0), h1 = __float2half_rn(v1);
                hp[jj] = pkh(h0, h1);
                lp[jj] = pkh(__float2half_rn(v0 - __half2float(h0)),
                             __float2half_rn(v1 - __half2float(h1)));
            }
            uint32_t o = bswz(d, g * 8, 16);
            *(uint4*)(smem + KTHI + o) = make_uint4(hp[0], hp[1], hp[2], hp[3]);
            *(uint4*)(smem + KTLO + o) = make_uint4(lp[0], lp[1], lp[2], lp[3]);
        }
        __syncthreads();
        // ---- stage + transpose V, fp16 single ----
        const float* vb = g_qkv + (size_t)(c * 256 + half * 128) * QKVW + 4096 + (size_t)h * DH;
        #pragma unroll
        for (int it = 0; it < 16; it++) {
            int j = it * 256 + tid;
            int r = j >> 5, dq = (j & 31) << 2;
            *(float4*)&stg[r * 132 + dq] = *(const float4*)&vb[(size_t)r * QKVW + dq];
        }
        __syncthreads();
        #pragma unroll
        for (int it = 0; it < 8; it++) {
            int t = it * 256 + tid;
            int d = t & 127, g = t >> 7;
            uint32_t hp[4];
            #pragma unroll
            for (int jj = 0; jj < 4; jj++) {
                int n0 = g * 8 + jj * 2;
                hp[jj] = pkh(__float2half_rn(stg[n0 * 132 + d]),
                             __float2half_rn(stg[(n0 + 1) * 132 + d]));
            }
            uint32_t o = bswz(d, g * 8, 16);
            *(uint4*)(smem + VTHI + o) = make_uint4(hp[0], hp[1], hp[2], hp[3]);
        }
        __syncthreads();
        {
            uint4* dh = (uint4*)(g_vThi + ((size_t)(h * 32 + c)) * 32768 + half * 16384);
            const uint4* sh = (const uint4*)(smem + VTHI);
            #pragma unroll
            for (int it = 0; it < 8; it++) {
                int j = it * 256 + tid;
                dh[j] = sh[j];
            }
        }
        FENCE_ASYNC_SHARED();
        __syncthreads();
        // ---- MMA: D += vThi·(kThi + kTlo)^T — 2 terms ----
        if (tid < 32) {
            uint64_t dVh = MAKE_SMEM_DESC(sb + VTHI);
            uint64_t dKh = MAKE_SMEM_DESC(sb + KTHI), dKl = MAKE_SMEM_DESC(sb + KTLO);
            if (elect_one_pred()) {
                #pragma unroll
                for (int st = 0; st < 8; st++) {
                    uint32_t u = ((st >> 2) << 10) + ((st & 3) << 1);
                    bool first = (half == 0 && st == 0);
                    mma_f16_ss(tmem, dVh + u, dKh + u, IDESC128F, !first);
                    mma_f16_ss(tmem, dVh + u, dKl + u, IDESC128F, true);
                }
                TCGEN05_COMMIT(mb);
            }
        }
    }
    MBARRIER_WAIT_PARITY(mb, 1);
    TCGEN05_FENCE_AFTER();
    __syncthreads();
    if (tid < 128) {
        int w = tid >> 5, l = tid & 31, e = w * 32 + l;
        float* dst = g_kvblk + ((size_t)(h * 32 + c)) * 16384 + (size_t)e * 128;
        #pragma unroll
        for (int cb = 0; cb < 4; cb++) {
            uint32_t r[32];
            TCGEN05_LD_X32(r, tmem + cb * 32);
            TCGEN05_WAIT_LD();
            #pragma unroll
            for (int j = 0; j < 32; j += 4)
                *(float4*)&dst[cb * 32 + j] = make_float4(
                    __uint_as_float(r[j]), __uint_as_float(r[j + 1]),
                    __uint_as_float(r[j + 2]), __uint_as_float(r[j + 3]));
        }
    }
    __syncthreads();
    if (tid < 32) TCGEN05_DEALLOC(tmem, 128);
#else
    int h = blockIdx.x & 15, c = blockIdx.x >> 4;
    float s = g_slopes[h];
    for (int idx = threadIdx.x; idx < 16384; idx += 256) {
        int e = idx >> 7, d = idx & 127;
        float acc = 0.f;
        for (int n = 0; n < 256; n++) {
            size_t t = (size_t)(c * 256 + n) * QKVW + (size_t)h * DH;
            acc += expf(-s * (float)(255 - n)) * g_qkv[t + 2048 + d] * g_qkv[t + 4096 + e];
        }
        g_kvblk[((size_t)(h * 32 + c)) * 16384 + (size_t)e * 128 + d] = acc;
    }
#endif
}

// ============ Phase B: decay scan — 256 CTAs ================================
__global__ void kvscan_kernel() {
    int h = blockIdx.x >> 4;
    int seg = blockIdx.x & 15;
    float bdec = expf(-g_slopes[h] * 256.0f);
    int e = seg * 1024 + threadIdx.x;
    #pragma unroll
    for (int r = 0; r < 4; r++, e += 256) {
        float acc = 0.f;
        size_t base = (size_t)h * NCHUNK * 16384 + e;
        #pragma unroll
        for (int c = 0; c < NCHUNK; c++) {
            g_kvstate[base + (size_t)c * 16384] = acc;
            acc = bdec * acc + g_kvblk[base + (size_t)c * 16384];
        }
    }
}

// ============ Phase C: attention (single O accumulator, 2 CTAs/SM) ==========
__global__ __launch_bounds__(256, 2) void attn_tensor_kernel() {
#if HAS_TCGEN05
    extern __shared__ char smem[];
    uint32_t sb = smem_to_u32(smem);
    int tid = threadIdx.x;
    int mi = blockIdx.x & 1, c = (blockIdx.x >> 1) & 31, h = blockIdx.x >> 6;
    float s = g_slopes[h];
    float* decay_tab = (float*)(smem + 16);
    const int QH   = 2048;                 // q single fp16 [128,128] 32KB
    const int KHI  = 34816, KLO = 51200;   // k chunk hi/lo 16KB each
    const int VH   = 67584;                // vT chunk single 16KB
    const int SH   = 83968;                // S single fp16 [128,64] 16KB
    const int KVHI = 34816, KVLO = 67584;  // final: kvstT hi/lo 32KB each
    uint32_t mb = sb + 8;
    if (tid < 32) TCGEN05_ALLOC(sb, 256);
    if (tid == 0) MBARRIER_INIT(mb, 1);
    for (int i = tid; i < 257; i += 256) decay_tab[i] = expf(-s * (float)i);
    __syncthreads();
    uint32_t tmem;
    asm volatile("ld.shared.b32 %0, [%1];" : "=r"(tmem) : "r"(sb));
    if (tid < 32) TCGEN05_RELINQ();
    const uint32_t OT = tmem, ST = tmem + 128;
    const uint32_t IDESC128F = (1u << 4) | (16u << 17) | (8u << 24);
    const uint32_t IDESC64F  = (1u << 4) | (8u  << 17) | (8u << 24);

    // ---- load q (single fp16, blocked) ----
    const float* qb = g_qkv + (size_t)(c * 256 + mi * 128) * QKVW + (size_t)h * DH;
    #pragma unroll
    for (int it = 0; it < 16; it++) {
        int j = it * 256 + tid;
        int r = j >> 5, dq = (j & 31) << 2;
        float4 v = *(const float4*)&qb[(size_t)r * QKVW + dq];
        uint32_t o = bswz(r, dq, 16);
        *(uint2*)(smem + QH + o) = make_uint2(
            pkh(__float2half_rn(v.x), __float2half_rn(v.y)),
            pkh(__float2half_rn(v.z), __float2half_rn(v.w)));
    }
    int ph = 0;
    const int nch = 2 * mi + 2;
    for (int cn = 0; cn < nch; cn++) {
        // ---- load k chunk [64,128] fp16 hi/lo ----
        const float* kb = g_qkv + (size_t)(c * 256 + cn * 64) * QKVW + 2048 + (size_t)h * DH;
        #pragma unroll
        for (int it = 0; it < 8; it++) {
            int j = it * 256 + tid;
            int r = j >> 5, dq = (j & 31) << 2;
            float4 v = *(const float4*)&kb[(size_t)r * QKVW + dq];
            __half h0 = __float2half_rn(v.x), h1 = __float2half_rn(v.y);
            __half h2 = __float2half_rn(v.z), h3 = __float2half_rn(v.w);
            uint32_t o = bswz(r, dq, 8);
            *(uint2*)(smem + KHI + o) = make_uint2(pkh(h0, h1), pkh(h2, h3));
            *(uint2*)(smem + KLO + o) = make_uint2(
                pkh(__float2half_rn(v.x - __half2float(h0)), __float2half_rn(v.y - __half2float(h1))),
                pkh(__float2half_rn(v.z - __half2float(h2)), __float2half_rn(v.w - __half2float(h3))));
        }
        // ---- load vT chunk (pre-swizzled fp16 blob, single) ----
        {
            const uint4* sh = (const uint4*)(g_vThi + (size_t)(h * 32 + c) * 32768 + cn * 8192);
            uint4* dh = (uint4*)(smem + VH);
            #pragma unroll
            for (int it = 0; it < 4; it++) {
                int j = it * 256 + tid;
                dh[j] = sh[j];
            }
        }
        FENCE_ASYNC_SHARED();
        __syncthreads();
        // ---- MMA_S: S = q·(k_hi + k_lo)^T ----
        if (tid < 32) {
            uint64_t dQ = MAKE_SMEM_DESC(sb + QH);
            uint64_t dKh = MAKE_SMEM_DESC(sb + KHI), dKl = MAKE_SMEM_DESC(sb + KLO);
            if (elect_one_pred()) {
                #pragma unroll
                for (int st = 0; st < 8; st++) {
                    uint32_t uq = ((st >> 2) << 10) + ((st & 3) << 1);
                    uint32_t uk = ((st >> 2) << 9) + ((st & 3) << 1);
                    mma_f16_ss(ST, dQ + uq, dKh + uk, IDESC64F, st != 0);
                    mma_f16_ss(ST, dQ + uq, dKl + uk, IDESC64F, true);
                }
                TCGEN05_COMMIT(mb);
            }
        }
        MBARRIER_WAIT_PARITY(mb, ph & 1); ph++;
        TCGEN05_FENCE_AFTER();
        // ---- read S, apply decay, single fp16 store ----
        if (tid < 128) {
            int w = tid >> 5, l = tid & 31, m = w * 32 + l;
            int gm = mi * 128 + m;
            uint32_t r0[32], r1[32];
            TCGEN05_LD_X32(r0, ST);
            TCGEN05_WAIT_LD();
            TCGEN05_LD_X32(r1, ST + 32);
            TCGEN05_WAIT_LD();
            #pragma unroll
            for (int g = 0; g < 8; g++) {
                uint32_t hp[4];
                #pragma unroll
                for (int jj = 0; jj < 4; jj++) {
                    int j0 = g * 8 + jj * 2;
                    float v0 = __uint_as_float(j0 < 32 ? r0[j0] : r1[j0 - 32]);
                    float v1 = __uint_as_float((j0 + 1) < 32 ? r0[j0 + 1] : r1[j0 - 31]);
                    int gn0 = cn * 64 + j0;
                    v0 = (gm >= gn0)     ? v0 * decay_tab[gm - gn0]     : 0.f;
                    v1 = (gm >= gn0 + 1) ? v1 * decay_tab[gm - gn0 - 1] : 0.f;
                    hp[jj] = pkh(__float2half_rn(v0), __float2half_rn(v1));
                }
                uint32_t o = bswz(m, g * 8, 16);
                *(uint4*)(smem + SH + o) = make_uint4(hp[0], hp[1], hp[2], hp[3]);
            }
        }
        FENCE_ASYNC_SHARED();
        __syncthreads();
        // ---- MMA_O: O += S·vT^T (single term) ----
        if (tid < 32) {
            uint64_t dS = MAKE_SMEM_DESC(sb + SH);
            uint64_t dV = MAKE_SMEM_DESC(sb + VH);
            if (elect_one_pred()) {
                #pragma unroll
                for (int st = 0; st < 4; st++) {
                    uint32_t u = (uint32_t)st << 1;
                    bool first = (cn == 0 && st == 0);
                    mma_f16_ss(OT, dS + u, dV + u, IDESC128F, !first);
                }
                TCGEN05_COMMIT(mb);
            }
        }
        MBARRIER_WAIT_PARITY(mb, ph & 1); ph++;
    }
    // ---- final: O += (qd·q)·kvstT  (inter-block term) ----
    // overwrite QH with qd-scaled q; load kvstT hi/lo into work region
    {
        #pragma unroll
        for (int it = 0; it < 16; it++) {
            int j = it * 256 + tid;
            int r = j >> 5, dq = (j & 31) << 2;
            float qd = decay_tab[mi * 128 + r + 1];
            float4 v = *(const float4*)&qb[(size_t)r * QKVW + dq];
            uint32_t o = bswz(r, dq, 16);
            *(uint2*)(smem + QH + o) = make_uint2(
                pkh(__float2half_rn(v.x * qd), __float2half_rn(v.y * qd)),
                pkh(__float2half_rn(v.z * qd), __float2half_rn(v.w * qd)));
        }
        const float* kvb = g_kvstate + (size_t)(h * 32 + c) * 16384;
        #pragma unroll
        for (int it = 0; it < 16; it++) {
            int j = it * 256 + tid;
            int r = j >> 5, dq = (j & 31) << 2;
            float4 v = *(const float4*)&kvb[(size_t)r * 128 + dq];
            __half h0 = __float2half_rn(v.x), h1 = __float2half_rn(v.y);
            __half h2 = __float2half_rn(v.z), h3 = __float2half_rn(v.w);
            uint32_t o = bswz(r, dq, 16);
            *(uint2*)(smem + KVHI + o) = make_uint2(pkh(h0, h1), pkh(h2, h3));
            *(uint2*)(smem + KVLO + o) = make_uint2(
                pkh(__float2half_rn(v.x - __half2float(h0)), __float2half_rn(v.y - __half2float(h1))),
                pkh(__float2half_rn(v.z - __half2float(h2)), __float2half_rn(v.w - __half2float(h3))));
        }
        FENCE_ASYNC_SHARED();
        __syncthreads();
        if (tid < 32) {
            uint64_t dQ = MAKE_SMEM_DESC(sb + QH);
            uint64_t dKh = MAKE_SMEM_DESC(sb + KVHI), dKl = MAKE_SMEM_DESC(sb + KVLO);
            if (elect_one_pred()) {
                #pragma unroll
                for (int st = 0; st < 8; st++) {
                    uint32_t u = ((st >> 2) << 10) + ((st & 3) << 1);
                    mma_f16_ss(OT, dQ + u, dKh + u, IDESC128F, true);
                    mma_f16_ss(OT, dQ + u, dKl + u, IDESC128F, true);
                }
                TCGEN05_COMMIT(mb);
            }
        }
        MBARRIER_WAIT_PARITY(mb, ph & 1); ph++;
    }
    TCGEN05_FENCE_AFTER();
    if (tid < 128) {
        int w = tid >> 5, l = tid & 31, m = w * 32 + l;
        int gm = mi * 128 + m;
        float* dst = g_attn + (size_t)(c * 256 + gm) * HIDDEN + (size_t)h * DH;
        #pragma unroll
        for (int cb = 0; cb < 4; cb++) {
            uint32_t a[32];
            TCGEN05_LD_X32(a, OT + cb * 32);
            TCGEN05_WAIT_LD();
            #pragma unroll
            for (int j = 0; j < 32; j += 4)
                *(float4*)&dst[cb * 32 + j] = make_float4(
                    __uint_as_float(a[j]),     __uint_as_float(a[j + 1]),
                    __uint_as_float(a[j + 2]), __uint_as_float(a[j + 3]));
        }
    }
    __syncthreads();
    if (tid < 32) TCGEN05_DEALLOC(tmem, 256);
#else
    int mi = blockIdx.x & 1, c = (blockIdx.x >> 1) & 31, h = blockIdx.x >> 6;
    float s = g_slopes[h];
    const float* kvst = g_kvstate + (size_t)(h * 32 + c) * 16384;
    for (int idx = threadIdx.x; idx < 16384; idx += 256) {
        int m = idx >> 7, e = idx & 127;
        int gm = mi * 128 + m;
        size_t tq = (size_t)(c * 256 + gm) * QKVW + (size_t)h * DH;
        float o = 0.f;
        for (int d = 0; d < 128; d++) o += g_qkv[tq + d] * kvst[(size_t)e * 128 + d];
        o *= expf(-s * (float)(gm + 1));
        for (int n = 0; n <= gm; n++) {
            size_t tk = (size_t)(c * 256 + n) * QKVW + (size_t)h * DH;
            float qk = 0.f;
            for (int d = 0; d < 128; d++) qk += g_qkv[tq + d] * g_qkv[tk + 2048 + d];
            o += expf(-s * (float)(gm - n)) * qk * g_qkv[tk + 4096 + e];
        }
        g_attn[(size_t)(c * 256 + gm) * HIDDEN + (size_t)h * DH + e] = o;
    }
#endif
}

// ============ RMS norm + sigmoid gate -> fp16 output ========================
__global__ void rmsgate_kernel(const float* __restrict__ gnw) {
    int t = blockIdx.x;
    int tid = threadIdx.x;
    const float* a = g_attn + (size_t)t * HIDDEN;
    const float* g = g_gate + (size_t)t * HIDDEN;
    float ss = 0.f;
    for (int j = tid; j < HIDDEN; j += 256) { float v = a[j]; ss += v * v; }
    #pragma unroll
    for (int o = 16; o; o >>= 1) ss += __shfl_xor_sync(0xffffffffu, ss, o);
    __shared__ float red[8];
    __shared__ float tot;
    if ((tid & 31) == 0) red[tid >> 5] = ss;
    __syncthreads();
    if (tid == 0) {
        float tsum = 0.f;
        #pragma unroll
        for (int w = 0; w < 8; w++) tsum += red[w];
        tot = tsum;
    }
    __syncthreads();
    float rms = rsqrtf(tot * (1.0f / HIDDEN) + 1e-5f);
    for (int j = tid; j < HIDDEN; j += 256) {
        float gv = g[j];
        float sig = 1.0f / (1.0f + expf(-gv));
        float val = a[j] * rms * gnw[j] * sig;
        g_yh[(size_t)t * HIDDEN + j] = __float2half_rn(val);
    }
}

// ================= launch =====================================================
extern "C" void kernel_launch(void* const* d_in, const int* in_sizes, int n_in,
                              void* d_out, int out_size) {
    const float* hidden    = (const float*)d_in[0];
    const int*   positions = (const int*)d_in[1];
    const float* Wqkv      = (const float*)d_in[2];
    const float* Wg        = (const float*)d_in[3];
    const float* Wd        = (const float*)d_in[4];
    const float* gnw       = (const float*)d_in[5];
    float* out = (float*)d_out;

    void *ah_p, *yh_p;
    void *bqh_p, *bql_p, *bgh_p, *bgl_p, *bdh_p, *bdl_p;
    cudaGetSymbolAddress(&ah_p, g_ah);
    cudaGetSymbolAddress(&yh_p, g_yh);
    cudaGetSymbolAddress(&bqh_p, g_bqkv_hi); cudaGetSymbolAddress(&bql_p, g_bqkv_lo);
    cudaGetSymbolAddress(&bgh_p, g_bg_hi);   cudaGetSymbolAddress(&bgl_p, g_bg_lo);
    cudaGetSymbolAddress(&bdh_p, g_bd_hi);   cudaGetSymbolAddress(&bdl_p, g_bd_lo);

    cudaFuncSetAttribute(gemm_qkvgate, cudaFuncAttributeMaxDynamicSharedMemorySize, CG2_SMEM);
    cudaFuncSetAttribute(gemm_down, cudaFuncAttributeMaxDynamicSharedMemorySize, CG2_SMEM);
    const int kvblk_smem = 2048 + 67584 + 3 * 32768;   // 167936
    cudaFuncSetAttribute(kvblkT_kernel, cudaFuncAttributeMaxDynamicSharedMemorySize, kvblk_smem);
    const int attn_smem = 100352;                      // 98 KB -> 2 CTAs/SM
    cudaFuncSetAttribute(attn_tensor_kernel, cudaFuncAttributeMaxDynamicSharedMemorySize, attn_smem);

    init_tables<<<1, 64>>>();
    conv_act<<<(NTOK * HIDDEN / 4 + 255) / 256, 256>>>(hidden, (__half*)ah_p,
                                                       NTOK * HIDDEN / 4);
    transposeW<<<dim3(QKVW / 32, HIDDEN / 32), 256>>>(Wqkv,
        (__half*)bqh_p, (__half*)bql_p, HIDDEN, QKVW);
    transposeW<<<dim3(HIDDEN / 32, HIDDEN / 32), 256>>>(Wg,
        (__half*)bgh_p, (__half*)bgl_p, HIDDEN, HIDDEN);
    transposeW<<<dim3(HIDDEN / 32, HIDDEN / 32), 256>>>(Wd,
        (__half*)bdh_p, (__half*)bdl_p, HIDDEN, HIDDEN);
    gemm_qkvgate<<<dim3(((QKVW + HIDDEN) / 256) * 2, NTOK / 256), 256, CG2_SMEM>>>(
        (const __half*)ah_p, positions);
    kvblkT_kernel<<<HEADS * NCHUNK, 256, kvblk_smem>>>();
    kvscan_kernel<<<HEADS * 16, 256>>>();
    attn_tensor_kernel<<<HEADS * NCHUNK * 2, 256, attn_smem>>>();
    rmsgate_kernel<<<NTOK, 256>>>(gnw);
    gemm_down<<<dim3((HIDDEN / 256) * 2, NTOK / 256), 256, CG2_SMEM>>>(
        (const __half*)yh_p,
        (const __half*)bdh_p, (const __half*)bdl_p,
        out, HIDDEN, HIDDEN);
}

// round 14
// speedup vs baseline: 1.1949x; 1.0488x over previous
#include <cuda_runtime.h>
#include <cuda_bf16.h>
#include <cuda_fp16.h>
#include <math.h>
#include <cstdint>

#define NTOK 8192
#define HIDDEN 2048
#define HEADS 16
#define DH 128
#define BLK 256
#define NCHUNK 32
#define QKVW 6144

#if defined(__CUDA_ARCH_FEAT_SM103_ALL) || \
    (defined(__CUDA_ARCH_SPECIFIC__) && (__CUDA_ARCH_SPECIFIC__ == 1030)) || \
    (defined(__CUDA_ARCH_FAMILY_SPECIFIC__) && (__CUDA_ARCH_FAMILY_SPECIFIC__ == 1030))
#define HAS_TCGEN05 1
#else
#define HAS_TCGEN05 0
#endif

// ================= PTX helpers ==============================================
__device__ __forceinline__ uint32_t elect_one_pred() {
    uint32_t pred;
    asm volatile("{\n\t.reg .pred p;\n\telect.sync _|p, 0xFFFFFFFF;\n\t"
                 "selp.b32 %0, 1, 0, p;\n\t}" : "=r"(pred));
    return pred;
}
__device__ __forceinline__ uint32_t smem_to_u32(const void* p) {
    uint32_t a;
    asm("{ .reg .u64 t; cvta.to.shared.u64 t, %1; cvt.u32.u64 %0, t; }"
        : "=r"(a) : "l"(p));
    return a;
}
__device__ __forceinline__ uint32_t cluster_rank() {
    uint32_t r;
    asm("mov.u32 %0, %%cluster_ctarank;" : "=r"(r));
    return r;
}
#define CLUSTER_SYNC() do { \
    asm volatile("barrier.cluster.arrive.aligned;" ::: "memory"); \
    asm volatile("barrier.cluster.wait.aligned;" ::: "memory"); \
} while (0)
#define MBARRIER_INIT(addr, cnt) \
    asm volatile("mbarrier.init.shared.b64 [%0], %1;" :: "r"((uint32_t)(addr)), "r"((uint32_t)(cnt)) : "memory")
#define MBARRIER_WAIT_PARITY(addr, par) do { \
    uint32_t _m = (uint32_t)(addr); uint32_t _p = (uint32_t)(par); uint32_t _d; \
    asm volatile("{\n\t.reg .pred p;\n\t" \
        "mbarrier.try_wait.parity.acquire.cta.shared::cta.b64 p, [%1], %2;\n\t" \
        "selp.b32 %0, 1, 0, p;\n\t}" : "=r"(_d) : "r"(_m), "r"(_p) : "memory"); \
    if (!_d) { \
        asm volatile("{\n\t.reg .pred P1;\n\t" \
            "WL_%=:\n\t" \
            "mbarrier.try_wait.parity.acquire.cta.shared::cta.b64 P1, [%0], %1, 0x989680;\n\t" \
            "@P1 bra.uni WD_%=;\n\tbra.uni WL_%=;\n\tWD_%=:\n\t}" \
            :: "r"(_m), "r"(_p) : "memory"); \
    } } while (0)
#define MBARRIER_WAIT_PARITY_CL(addr, par) do { \
    uint32_t _m = (uint32_t)(addr); uint32_t _p = (uint32_t)(par); uint32_t _d; \
    asm volatile("{\n\t.reg .pred p;\n\t" \
        "mbarrier.try_wait.parity.acquire.cluster.shared::cta.b64 p, [%1], %2;\n\t" \
        "selp.b32 %0, 1, 0, p;\n\t}" : "=r"(_d) : "r"(_m), "r"(_p) : "memory"); \
    if (!_d) { \
        asm volatile("{\n\t.reg .pred P1;\n\t" \
            "WL_%=:\n\t" \
            "mbarrier.try_wait.parity.acquire.cluster.shared::cta.b64 P1, [%0], %1, 0x989680;\n\t" \
            "@P1 bra.uni WD_%=;\n\tbra.uni WL_%=;\n\tWD_%=:\n\t}" \
            :: "r"(_m), "r"(_p) : "memory"); \
    } } while (0)
#define MBARRIER_ARRIVE_CLUSTER(local_addr, target_rank) \
    asm volatile( \
        "{\n\t.reg .b32 remAddr32;\n\t" \
        "mapa.shared::cluster.u32 remAddr32, %0, %1;\n\t" \
        "mbarrier.arrive.release.cluster.shared::cluster.b64 _, [remAddr32];\n\t}" \
        :: "r"((uint32_t)(local_addr)), "r"((uint32_t)(target_rank)) : "memory")
#define TCGEN05_ALLOC(smem_addr, n) \
    asm volatile("tcgen05.alloc.cta_group::1.sync.aligned.shared::cta.b32 [%0], %1;" \
        :: "r"((uint32_t)(smem_addr)), "r"((uint32_t)(n)) : "memory")
#define TCGEN05_DEALLOC(tmem, n) \
    asm volatile("tcgen05.dealloc.cta_group::1.sync.aligned.b32 %0, %1;" :: "r"(tmem), "r"((uint32_t)(n)))
#define TCGEN05_RELINQ() \
    asm volatile("tcgen05.relinquish_alloc_permit.cta_group::1.sync.aligned;")
#define TCGEN05_ALLOC_CG2(smem_addr, n) \
    asm volatile("tcgen05.alloc.cta_group::2.sync.aligned.shared::cta.b32 [%0], %1;" \
        :: "r"((uint32_t)(smem_addr)), "r"((uint32_t)(n)) : "memory")
#define TCGEN05_DEALLOC_CG2(tmem, n) \
    asm volatile("tcgen05.dealloc.cta_group::2.sync.aligned.b32 %0, %1;" :: "r"(tmem), "r"((uint32_t)(n)))
#define TCGEN05_RELINQ_CG2() \
    asm volatile("tcgen05.relinquish_alloc_permit.cta_group::2.sync.aligned;")
#define TCGEN05_COMMIT(mbar) \
    asm volatile("tcgen05.commit.cta_group::1.mbarrier::arrive::one.shared::cluster.b64 [%0];" \
        :: "r"((uint32_t)(mbar)) : "memory")
#define TCGEN05_COMMIT_MC_CG2(mbar, mask) \
    asm volatile("tcgen05.commit.cta_group::2.mbarrier::arrive::one.shared::cluster.multicast::cluster.b64 [%0], %1;" \
        :: "r"((uint32_t)(mbar)), "h"((uint16_t)(mask)) : "memory")
#define TCGEN05_FENCE_AFTER() asm volatile("tcgen05.fence::after_thread_sync;" ::: "memory")
#define TCGEN05_WAIT_LD() asm volatile("tcgen05.wait::ld.sync.aligned;" ::: "memory")
#define FENCE_ASYNC_SHARED() asm volatile("fence.proxy.async.shared::cta;" ::: "memory")
#define TCGEN05_LD_X32(r, addr) \
    asm volatile("tcgen05.ld.sync.aligned.32x32b.x32.b32 " \
        "{%0, %1, %2, %3, %4, %5, %6, %7, %8, %9, %10, %11, %12, %13, %14, %15, " \
        " %16, %17, %18, %19, %20, %21, %22, %23, %24, %25, %26, %27, %28, %29, %30, %31}, [%32];" \
        : "=r"((r)[0]),  "=r"((r)[1]),  "=r"((r)[2]),  "=r"((r)[3]), \
          "=r"((r)[4]),  "=r"((r)[5]),  "=r"((r)[6]),  "=r"((r)[7]), \
          "=r"((r)[8]),  "=r"((r)[9]),  "=r"((r)[10]), "=r"((r)[11]), \
          "=r"((r)[12]), "=r"((r)[13]), "=r"((r)[14]), "=r"((r)[15]), \
          "=r"((r)[16]), "=r"((r)[17]), "=r"((r)[18]), "=r"((r)[19]), \
          "=r"((r)[20]), "=r"((r)[21]), "=r"((r)[22]), "=r"((r)[23]), \
          "=r"((r)[24]), "=r"((r)[25]), "=r"((r)[26]), "=r"((r)[27]), \
          "=r"((r)[28]), "=r"((r)[29]), "=r"((r)[30]), "=r"((r)[31]) \
        : "r"(addr))

static constexpr uint64_t SMEM_DESC_BASE_SW128 =
    (uint64_t(2) << 61) | (uint64_t(1) << 46) | (uint64_t(64) << 32) | (uint64_t(1) << 16);
#define MAKE_SMEM_DESC(a) (SMEM_DESC_BASE_SW128 | ((uint64_t)((a) >> 4) & 0x3FFF))

#if HAS_TCGEN05
__device__ __forceinline__ void mma_f16_ss(uint32_t d_tmem, uint64_t a_desc,
                                           uint64_t b_desc, uint32_t idesc, bool acc) {
    uint32_t en = acc ? 1u : 0u;
    asm volatile(
        "{\n\t.reg .pred p;\n\tsetp.ne.u32 p, %5, 0;\n\t"
        "tcgen05.mma.cta_group::1.kind::f16 [%0], %1, %2, %3, {%4, %4, %4, %4}, p;\n\t}"
        :: "r"(d_tmem), "l"(a_desc), "l"(b_desc), "r"(idesc), "r"(0u), "r"(en)
        : "memory");
}
__device__ __forceinline__ void mma_f16_ss_cg2(uint32_t d_tmem, uint64_t a_desc,
                                               uint64_t b_desc, uint32_t idesc, bool acc) {
    uint32_t en = acc ? 1u : 0u;
    asm volatile(
        "{\n\t.reg .pred p;\n\tsetp.ne.u32 p, %5, 0;\n\t"
        "tcgen05.mma.cta_group::2.kind::f16 [%0], %1, %2, %3, "
        "{%4, %4, %4, %4, %4, %4, %4, %4}, p;\n\t}"
        :: "r"(d_tmem), "l"(a_desc), "l"(b_desc), "r"(idesc), "r"(0u), "r"(en)
        : "memory");
}
#endif

__device__ __forceinline__ uint32_t bswz(int row, int col, int atomrows) {
    uint32_t off = (uint32_t)(((row >> 3) + (col >> 6) * atomrows) << 10)
                 + ((row & 7) << 7) + ((col & 63) << 1);
    return off ^ ((off >> 3) & 0x70);
}
__device__ __forceinline__ uint32_t pkh(__half a, __half b) {
    __half2 t{a, b};
    return *(uint32_t*)&t;
}

// ================= scratch ===================================================
__device__ float g_qkv[(size_t)NTOK * QKVW];
__device__ float g_gate[(size_t)NTOK * HIDDEN];
__device__ float g_attn[(size_t)NTOK * HIDDEN];
__device__ float g_kvblk[(size_t)HEADS * NCHUNK * DH * DH];
__device__ float g_kvstate[(size_t)HEADS * NCHUNK * DH * DH];
__device__ float g_invf[64];
__device__ float g_slopes[HEADS];
__device__ __half g_vThi[(size_t)HEADS * NCHUNK * 32768];
__device__ __half g_ah[(size_t)NTOK * HIDDEN];
__device__ __half g_yh[(size_t)NTOK * HIDDEN];
__device__ __half g_bqkv_hi[(size_t)QKVW * HIDDEN];
__device__ __half g_bqkv_lo[(size_t)QKVW * HIDDEN];
__device__ __half g_bg_hi[(size_t)HIDDEN * HIDDEN];
__device__ __half g_bg_lo[(size_t)HIDDEN * HIDDEN];
__device__ __half g_bd_hi[(size_t)HIDDEN * HIDDEN];
__device__ __half g_bd_lo[(size_t)HIDDEN * HIDDEN];

// ================= init tables ================================================
__global__ void init_tables() {
    int t = threadIdx.x;
    if (t < 64) g_invf[t] = (float)pow(600000.0, -(double)t / 64.0);
    if (t < HEADS) {
        double start = pow(2.0, -pow(2.0, -(log2(16.0) - 3.0)));
        g_slopes[t] = (float)(start * pow(start, (double)t) * (1.0 + 1e-5));
    }
}

// ================= convert fp32 -> fp16 (A operand, single) =================
__global__ void conv_act(const float* __restrict__ x, __half* __restrict__ h, int n4) {
    int i = blockIdx.x * blockDim.x + threadIdx.x;
    if (i >= n4) return;
    float4 v = ((const float4*)x)[i];
    __half2 a{__float2half_rn(v.x), __float2half_rn(v.y)};
    __half2 b{__float2half_rn(v.z), __float2half_rn(v.w)};
    ((__half2*)h)[i * 2]     = a;
    ((__half2*)h)[i * 2 + 1] = b;
}

// ======= transpose + split W[K,N] fp32 -> Thi/Tlo [N,K] fp16 ================
__global__ void transposeW(const float* __restrict__ W, __half* __restrict__ Thi,
                           __half* __restrict__ Tlo, int K, int N) {
    __shared__ float t[32][33];
    int n0 = blockIdx.x * 32, k0 = blockIdx.y * 32;
    int c = threadIdx.x & 31, r0 = threadIdx.x >> 5;
    #pragma unroll
    for (int rr = r0; rr < 32; rr += 8)
        t[rr][c] = W[(size_t)(k0 + rr) * N + n0 + c];
    __syncthreads();
    #pragma unroll
    for (int rr = r0; rr < 32; rr += 8) {
        float v = t[c][rr];
        __half h = __float2half_rn(v);
        Thi[(size_t)(n0 + rr) * K + k0 + c] = h;
        Tlo[(size_t)(n0 + rr) * K + k0 + c] = __float2half_rn(v - __half2float(h));
    }
}

#if HAS_TCGEN05
template <int ROWS>
__device__ __forceinline__ void load_tile(char* dst, const __half* src, int ld) {
    int tid = threadIdx.x;
    #pragma unroll
    for (int l = 0; l < ROWS / 32; l++) {
        int i = l * 256 + tid;
        int r = i >> 3, sg = i & 7;
        uint4 v = *(const uint4*)(src + (size_t)r * ld + sg * 8);
        uint32_t off = (uint32_t)(r * 128 + sg * 16);
        off ^= (off >> 3) & 0x70;
        *(uint4*)(dst + off) = v;
    }
}
#endif

// ======= cg2 fp16 GEMM constants (K-chunk 64) ================================
#define CG2_BUF 49152
#define CG2_SMEM (1024 + 2 * CG2_BUF)
#define IDESC_CG2 ((1u << 4) | (32u << 17) | (16u << 24))

// ======= fused qkv+gate GEMM (cg2 fp16; v & gate B-lo skipped) ===============
__global__ __launch_bounds__(256, 1) __cluster_dims__(2, 1, 1)
void gemm_qkvgate(const __half* __restrict__ A, const int* __restrict__ positions) {
    const int K = HIDDEN;
    uint32_t rank = cluster_rank();
    int bm = blockIdx.y * 256;
    int bn = (blockIdx.x >> 1) * 256;
    int gcs = bn + (int)rank * 128;
    bool oneTerm = (bn >= 4096);      // v columns [4096,6144) + gate [6144,8192)
    const __half* Bhi = (gcs < QKVW) ? g_bqkv_hi + (size_t)gcs * K
                                     : g_bg_hi + (size_t)(gcs - QKVW) * K;
    const __half* Blo = (gcs < QKVW) ? g_bqkv_lo + (size_t)gcs * K
                                     : g_bg_lo + (size_t)(gcs - QKVW) * K;
#if HAS_TCGEN05
    extern __shared__ char smem[];
    uint32_t sb = smem_to_u32(smem);
    int tid = threadIdx.x;
    const uint32_t dn0 = sb + 8,  dn1 = sb + 16;
    const uint32_t rd0 = sb + 24, rd1 = sb + 32;
    if (tid < 32) TCGEN05_ALLOC_CG2(sb, 256);
    if (tid == 0) {
        MBARRIER_INIT(dn0, 1); MBARRIER_INIT(dn1, 1);
        MBARRIER_INIT(rd0, 2); MBARRIER_INIT(rd1, 2);
    }
    __syncthreads();
    uint32_t tmem;
    asm volatile("ld.shared.b32 %0, [%1];" : "=r"(tmem) : "r"(sb));
    if (tid < 32) TCGEN05_RELINQ_CG2();
    CLUSTER_SYNC();

    const __half* pA = A + (size_t)(bm + rank * 128) * K;

    int phd[2] = {0, 0};
    int phr[2] = {0, 0};
    for (int ch = 0; ch < 32; ch++) {
        int b = ch & 1;
        char* st = smem + 1024 + b * CG2_BUF;
        if (ch >= 2) {
            MBARRIER_WAIT_PARITY_CL(b ? dn1 : dn0, phd[b]);
            phd[b] ^= 1;
        }
        int k0 = ch << 6;
        load_tile<128>(st,         pA + k0,  K);
        load_tile<128>(st + 16384, Bhi + k0, K);
        if (!oneTerm) load_tile<128>(st + 32768, Blo + k0, K);
        FENCE_ASYNC_SHARED();
        __syncthreads();
        if (tid == 0) MBARRIER_ARRIVE_CLUSTER(b ? rd1 : rd0, 0);
        if (rank == 0 && tid < 32) {
            MBARRIER_WAIT_PARITY_CL(b ? rd1 : rd0, phr[b]);
            phr[b] ^= 1;
            uint32_t sa = sb + 1024 + b * CG2_BUF;
            uint64_t dA  = MAKE_SMEM_DESC(sa);
            uint64_t dBh = MAKE_SMEM_DESC(sa + 16384);
            uint64_t dBl = MAKE_SMEM_DESC(sa + 32768);
            if (elect_one_pred()) {
                #pragma unroll
                for (int k = 0; k < 4; k++) {
                    bool first = (ch == 0) && (k == 0);
                    mma_f16_ss_cg2(tmem, dA + k * 2, dBh + k * 2, IDESC_CG2, !first);
                    if (!oneTerm)
                        mma_f16_ss_cg2(tmem, dA + k * 2, dBl + k * 2, IDESC_CG2, true);
                }
                TCGEN05_COMMIT_MC_CG2(b ? dn1 : dn0, 0x3);
            }
        }
    }
    MBARRIER_WAIT_PARITY_CL(dn0, phd[0]);
    MBARRIER_WAIT_PARITY_CL(dn1, phd[1]);
    TCGEN05_FENCE_AFTER();
    __syncthreads();

    int w = tid >> 5, l = tid & 31;
    int sub = w & 3;
    int colbase = (w >> 2) * 128;
    int row = bm + (int)rank * 128 + sub * 32 + l;
    int gc0 = bn + colbase;
    bool isQ = gc0 < 2048;
    bool isK = (gc0 >= 2048) && (gc0 < 4096);
    float* dst = (gc0 < QKVW) ? g_qkv + (size_t)row * QKVW + gc0
                              : g_gate + (size_t)row * HIDDEN + (gc0 - QKVW);
    if (isQ || isK) {
        float pos = (float)positions[row];
        float qs = isQ ? 0.08838834764831845f : 1.0f;
        #pragma unroll
        for (int half = 0; half < 2; half++) {
            uint32_t a[32], b[32];
            TCGEN05_LD_X32(a, tmem + colbase + half * 32);
            TCGEN05_WAIT_LD();
            TCGEN05_LD_X32(b, tmem + colbase + half * 32 + 64);
            TCGEN05_WAIT_LD();
            #pragma unroll
            for (int j0 = 0; j0 < 32; j0 += 4) {
                float o1[4], o2[4];
                #pragma unroll
                for (int j = 0; j < 4; j++) {
                    int jin = half * 32 + j0 + j;
                    float f = pos * g_invf[jin];
                    float sv, cv;
                    sincosf(f, &sv, &cv);
                    float x1 = __uint_as_float(a[j0 + j]);
                    float x2 = __uint_as_float(b[j0 + j]);
                    o1[j] = (x1 * cv - x2 * sv) * qs;
                    o2[j] = (x2 * cv + x1 * sv) * qs;
                }
                *(float4*)&dst[half * 32 + j0]      = make_float4(o1[0], o1[1], o1[2], o1[3]);
                *(float4*)&dst[half * 32 + 64 + j0] = make_float4(o2[0], o2[1], o2[2], o2[3]);
            }
        }
    } else {
        #pragma unroll
        for (int cb = 0; cb < 128; cb += 32) {
            uint32_t r[32];
            TCGEN05_LD_X32(r, tmem + colbase + cb);
            TCGEN05_WAIT_LD();
            #pragma unroll
            for (int j = 0; j < 32; j += 4)
                *(float4*)&dst[cb + j] = make_float4(
                    __uint_as_float(r[j]), __uint_as_float(r[j + 1]),
                    __uint_as_float(r[j + 2]), __uint_as_float(r[j + 3]));
        }
    }
    __syncthreads();
    if (tid < 32) TCGEN05_DEALLOC_CG2(tmem, 256);
    CLUSTER_SYNC();
#else
    extern __shared__ char smemraw[];
    float* As = (float*)smemraw;
    float* Bs = As + 16 * 128;
    int tid = threadIdx.x;
    int bmr = bm + (int)rank * 128;
    int ty = tid >> 4, tx = tid & 15;
    float acc[8][16];
    #pragma unroll
    for (int i = 0; i < 8; i++)
        #pragma unroll
        for (int j = 0; j < 16; j++) acc[i][j] = 0.f;
    for (int k0 = 0; k0 < K; k0 += 16) {
        #pragma unroll
        for (int l = 0; l < 8; l++) {
            int i = l * 256 + tid;
            int k = i & 15, m = i >> 4;
            As[k * 128 + m] = __half2float(A[(size_t)(bmr + m) * K + k0 + k]);
        }
        #pragma unroll
        for (int l = 0; l < 16; l++) {
            int i = l * 256 + tid;
            int k = i & 15, n = i >> 4;
            int gc = bn + n;
            const __half* bh = (gc < QKVW) ? g_bqkv_hi + (size_t)gc * K
                                           : g_bg_hi + (size_t)(gc - QKVW) * K;
            const __half* bl = (gc < QKVW) ? g_bqkv_lo + (size_t)gc * K
                                           : g_bg_lo + (size_t)(gc - QKVW) * K;
            float bv = __half2float(bh[k0 + k]);
            if (!oneTerm) bv += __half2float(bl[k0 + k]);
            Bs[k * 256 + n] = bv;
        }
        __syncthreads();
        #pragma unroll
        for (int kk = 0; kk < 16; kk++) {
            float a[8], b[16];
            #pragma unroll
            for (int i = 0; i < 8; i++) a[i] = As[kk * 128 + ty * 8 + i];
            #pragma unroll
            for (int j = 0; j < 16; j++) b[j] = Bs[kk * 256 + tx * 16 + j];
            #pragma unroll
            for (int i = 0; i < 8; i++)
                #pragma unroll
                for (int j = 0; j < 16; j++) acc[i][j] += a[i] * b[j];
        }
        __syncthreads();
    }
    float* tileS = (float*)smemraw;
    #pragma unroll
    for (int i = 0; i < 8; i++)
        #pragma unroll
        for (int j = 0; j < 16; j++)
            tileS[(ty * 8 + i) * 257 + tx * 16 + j] = acc[i][j];
    __syncthreads();
    {
        int r = tid >> 1, sp = tid & 1;
        int row = bmr + r;
        int gc0 = bn + sp * 128;
        bool isQ = gc0 < 2048;
        bool isK = (gc0 >= 2048) && (gc0 < 4096);
        float* dst = (gc0 < QKVW) ? g_qkv + (size_t)row * QKVW + gc0
                                  : g_gate + (size_t)row * HIDDEN + (gc0 - QKVW);
        const float* src = &tileS[r * 257 + sp * 128];
        if (isQ || isK) {
            float pos = (float)positions[row];
            float qs = isQ ? 0.08838834764831845f : 1.0f;
            for (int j = 0; j < 64; j++) {
                float f = pos * g_invf[j];
                float sv, cv;
                sincosf(f, &sv, &cv);
                float x1 = src[j], x2 = src[j + 64];
                dst[j]      = (x1 * cv - x2 * sv) * qs;
                dst[j + 64] = (x2 * cv + x1 * sv) * qs;
            }
        } else {
            for (int j = 0; j < 128; j++) dst[j] = src[j];
        }
    }
#endif
}

// ============ cg2 fp16 single-term down-projection GEMM =====================
__global__ __launch_bounds__(256, 1) __cluster_dims__(2, 1, 1)
void gemm_down(const __half* __restrict__ A,
               const __half* __restrict__ Bhi,
               float* __restrict__ C, int Nn, int K) {
    uint32_t rank = cluster_rank();
    int bm = blockIdx.y * 256;
    int bn = (blockIdx.x >> 1) * 256;
#if HAS_TCGEN05
    extern __shared__ char smem[];
    uint32_t sb = smem_to_u32(smem);
    int tid = threadIdx.x;
    const uint32_t dn0 = sb + 8,  dn1 = sb + 16;
    const uint32_t rd0 = sb + 24, rd1 = sb + 32;
    if (tid < 32) TCGEN05_ALLOC_CG2(sb, 256);
    if (tid == 0) {
        MBARRIER_INIT(dn0, 1); MBARRIER_INIT(dn1, 1);
        MBARRIER_INIT(rd0, 2); MBARRIER_INIT(rd1, 2);
    }
    __syncthreads();
    uint32_t tmem;
    asm volatile("ld.shared.b32 %0, [%1];" : "=r"(tmem) : "r"(sb));
    if (tid < 32) TCGEN05_RELINQ_CG2();
    CLUSTER_SYNC();

    const __half* pA   = A   + (size_t)(bm + rank * 128) * K;
    const __half* pBhi = Bhi + (size_t)(bn + rank * 128) * K;

    int phd[2] = {0, 0};
    int phr[2] = {0, 0};
    const int nch = K >> 6;
    for (int ch = 0; ch < nch; ch++) {
        int b = ch & 1;
        char* st = smem + 1024 + b * CG2_BUF;
        if (ch >= 2) {
            MBARRIER_WAIT_PARITY_CL(b ? dn1 : dn0, phd[b]);
            phd[b] ^= 1;
        }
        int k0 = ch << 6;
        load_tile<128>(st,         pA + k0,   K);
        load_tile<128>(st + 16384, pBhi + k0, K);
        FENCE_ASYNC_SHARED();
        __syncthreads();
        if (tid == 0) MBARRIER_ARRIVE_CLUSTER(b ? rd1 : rd0, 0);
        if (rank == 0 && tid < 32) {
            MBARRIER_WAIT_PARITY_CL(b ? rd1 : rd0, phr[b]);
            phr[b] ^= 1;
            uint32_t sa = sb + 1024 + b * CG2_BUF;
            uint64_t dA  = MAKE_SMEM_DESC(sa);
            uint64_t dBh = MAKE_SMEM_DESC(sa + 16384);
            if (elect_one_pred()) {
                #pragma unroll
                for (int k = 0; k < 4; k++) {
                    bool first = (ch == 0) && (k == 0);
                    mma_f16_ss_cg2(tmem, dA + k * 2, dBh + k * 2, IDESC_CG2, !first);
                }
                TCGEN05_COMMIT_MC_CG2(b ? dn1 : dn0, 0x3);
            }
        }
    }
    MBARRIER_WAIT_PARITY_CL(dn0, phd[0]);
    MBARRIER_WAIT_PARITY_CL(dn1, phd[1]);
    TCGEN05_FENCE_AFTER();
    __syncthreads();

    int w = tid >> 5, l = tid & 31;
    int sub = w & 3;
    int colbase = (w >> 2) * 128;
    int row = bm + (int)rank * 128 + sub * 32 + l;
    float* dst_row = C + (size_t)row * Nn + bn + colbase;
    #pragma unroll
    for (int cb = 0; cb < 128; cb += 32) {
        uint32_t r[32];
        TCGEN05_LD_X32(r, tmem + colbase + cb);
        TCGEN05_WAIT_LD();
        #pragma unroll
        for (int j = 0; j < 32; j += 4)
            *(float4*)(dst_row + cb + j) = make_float4(
                __uint_as_float(r[j]), __uint_as_float(r[j + 1]),
                __uint_as_float(r[j + 2]), __uint_as_float(r[j + 3]));
    }
    __syncthreads();
    if (tid < 32) TCGEN05_DEALLOC_CG2(tmem, 256);
    CLUSTER_SYNC();
#else
    extern __shared__ char smemraw[];
    float* As = (float*)smemraw;
    float* Bs = As + 16 * 128;
    int tid = threadIdx.x;
    int bmr = bm + (int)rank * 128;
    int ty = tid >> 4, tx = tid & 15;
    float acc[8][16];
    #pragma unroll
    for (int i = 0; i < 8; i++)
        #pragma unroll
        for (int j = 0; j < 16; j++) acc[i][j] = 0.f;
    for (int k0 = 0; k0 < K; k0 += 16) {
        #pragma unroll
        for (int l = 0; l < 8; l++) {
            int i = l * 256 + tid;
            int k = i & 15, m = i >> 4;
            As[k * 128 + m] = __half2float(A[(size_t)(bmr + m) * K + k0 + k]);
        }
        #pragma unroll
        for (int l = 0; l < 16; l++) {
            int i = l * 256 + tid;
            int k = i & 15, n = i >> 4;
            size_t off = (size_t)(bn + n) * K + k0 + k;
            Bs[k * 256 + n] = __half2float(Bhi[off]);
        }
        __syncthreads();
        #pragma unroll
        for (int kk = 0; kk < 16; kk++) {
            float a[8], b[16];
            #pragma unroll
            for (int i = 0; i < 8; i++) a[i] = As[kk * 128 + ty * 8 + i];
            #pragma unroll
            for (int j = 0; j < 16; j++) b[j] = Bs[kk * 256 + tx * 16 + j];
            #pragma unroll
            for (int i = 0; i < 8; i++)
                #pragma unroll
                for (int j = 0; j < 16; j++) acc[i][j] += a[i] * b[j];
        }
        __syncthreads();
    }
    #pragma unroll
    for (int i = 0; i < 8; i++) {
        size_t off = (size_t)(bmr + ty * 8 + i) * Nn + bn + tx * 16;
        #pragma unroll
        for (int j = 0; j < 16; j += 4)
            *(float4*)&C[off + j] = make_float4(acc[i][j], acc[i][j + 1],
                                                acc[i][j + 2], acc[i][j + 3]);
    }
#endif
}

// ============ Phase A: kvblkT (tensor, fp16 2-term; V single) ===============
__global__ __launch_bounds__(256, 1) void kvblkT_kernel() {
#if HAS_TCGEN05
    extern __shared__ char smem[];
    uint32_t sb = smem_to_u32(smem);
    int tid = threadIdx.x;
    int h = blockIdx.x & 15, c = blockIdx.x >> 4;
    float s = g_slopes[h];
    float* decay_tab = (float*)(smem + 16);
    const int STG = 2048;
    const int KTHI = STG + 67584;
    const int KTLO = KTHI + 32768;
    const int VTHI = KTLO + 32768;
    uint32_t mb = sb + 8;
    if (tid < 32) TCGEN05_ALLOC(sb, 128);
    if (tid == 0) MBARRIER_INIT(mb, 1);
    for (int i = tid; i < 257; i += 256) decay_tab[i] = expf(-s * (float)i);
    __syncthreads();
    uint32_t tmem;
    asm volatile("ld.shared.b32 %0, [%1];" : "=r"(tmem) : "r"(sb));
    if (tid < 32) TCGEN05_RELINQ();
    float* stg = (float*)(smem + STG);
    const uint32_t IDESC128F = (1u << 4) | (16u << 17) | (8u << 24);

    for (int half = 0; half < 2; half++) {
        if (half == 1) MBARRIER_WAIT_PARITY(mb, 0);
        const float* kb = g_qkv + (size_t)(c * 256 + half * 128) * QKVW + 2048 + (size_t)h * DH;
        #pragma unroll
        for (int it = 0; it < 16; it++) {
            int j = it * 256 + tid;
            int r = j >> 5, dq = (j & 31) << 2;
            *(float4*)&stg[r * 132 + dq] = *(const float4*)&kb[(size_t)r * QKVW + dq];
        }
        __syncthreads();
        #pragma unroll
        for (int it = 0; it < 8; it++) {
            int t = it * 256 + tid;
            int d = t & 127, g = t >> 7;
            uint32_t hp[4], lp[4];
            #pragma unroll
            for (int jj = 0; jj < 4; jj++) {
                int n0 = g * 8 + jj * 2;
                float v0 = stg[n0 * 132 + d]       * decay_tab[255 - (half * 128 + n0)];
                float v1 = stg[(n0 + 1) * 132 + d] * decay_tab[255 - (half * 128 + n0 + 1)];
                __half h0 = __float2half_rn(v0), h1 = __float2half_rn(v1);
                hp[jj] = pkh(h0, h1);
                lp[jj] = pkh(__float2half_rn(v0 - __half2float(h0)),
                             __float2half_rn(v1 - __half2float(h1)));
            }
            uint32_t o = bswz(d, g * 8, 16);
            *(uint4*)(smem + KTHI + o) = make_uint4(hp[0], hp[1], hp[2], hp[3]);
            *(uint4*)(smem + KTLO + o) = make_uint4(lp[0], lp[1], lp[2], lp[3]);
        }
        __syncthreads();
        const float* vb = g_qkv + (size_t)(c * 256 + half * 128) * QKVW + 4096 + (size_t)h * DH;
        #pragma unroll
        for (int it = 0; it < 16; it++) {
            int j = it * 256 + tid;
            int r = j >> 5, dq = (j & 31) << 2;
            *(float4*)&stg[r * 132 + dq] = *(const float4*)&vb[(size_t)r * QKVW + dq];
        }
        __syncthreads();
        #pragma unroll
        for (int it = 0; it < 8; it++) {
            int t = it * 256 + tid;
            int d = t & 127, g = t >> 7;
            uint32_t hp[4];
            #pragma unroll
            for (int jj = 0; jj < 4; jj++) {
                int n0 = g * 8 + jj * 2;
                hp[jj] = pkh(__float2half_rn(stg[n0 * 132 + d]),
                             __float2half_rn(stg[(n0 + 1) * 132 + d]));
            }
            uint32_t o = bswz(d, g * 8, 16);
            *(uint4*)(smem + VTHI + o) = make_uint4(hp[0], hp[1], hp[2], hp[3]);
        }
        __syncthreads();
        {
            uint4* dh = (uint4*)(g_vThi + ((size_t)(h * 32 + c)) * 32768 + half * 16384);
            const uint4* sh = (const uint4*)(smem + VTHI);
            #pragma unroll
            for (int it = 0; it < 8; it++) {
                int j = it * 256 + tid;
                dh[j] = sh[j];
            }
        }
        FENCE_ASYNC_SHARED();
        __syncthreads();
        if (tid < 32) {
            uint64_t dVh = MAKE_SMEM_DESC(sb + VTHI);
            uint64_t dKh = MAKE_SMEM_DESC(sb + KTHI), dKl = MAKE_SMEM_DESC(sb + KTLO);
            if (elect_one_pred()) {
                #pragma unroll
                for (int st = 0; st < 8; st++) {
                    uint32_t u = ((st >> 2) << 10) + ((st & 3) << 1);
                    bool first = (half == 0 && st == 0);
                    mma_f16_ss(tmem, dVh + u, dKh + u, IDESC128F, !first);
                    mma_f16_ss(tmem, dVh + u, dKl + u, IDESC128F, true);
                }
                TCGEN05_COMMIT(mb);
            }
        }
    }
    MBARRIER_WAIT_PARITY(mb, 1);
    TCGEN05_FENCE_AFTER();
    __syncthreads();
    if (tid < 128) {
        int w = tid >> 5, l = tid & 31, e = w * 32 + l;
        float* dst = g_kvblk + ((size_t)(h * 32 + c)) * 16384 + (size_t)e * 128;
        #pragma unroll
        for (int cb = 0; cb < 4; cb++) {
            uint32_t r[32];
            TCGEN05_LD_X32(r, tmem + cb * 32);
            TCGEN05_WAIT_LD();
            #pragma unroll
            for (int j = 0; j < 32; j += 4)
                *(float4*)&dst[cb * 32 + j] = make_float4(
                    __uint_as_float(r[j]), __uint_as_float(r[j + 1]),
                    __uint_as_float(r[j + 2]), __uint_as_float(r[j + 3]));
        }
    }
    __syncthreads();
    if (tid < 32) TCGEN05_DEALLOC(tmem, 128);
#else
    int h = blockIdx.x & 15, c = blockIdx.x >> 4;
    float s = g_slopes[h];
    for (int idx = threadIdx.x; idx < 16384; idx += 256) {
        int e = idx >> 7, d = idx & 127;
        float acc = 0.f;
        for (int n = 0; n < 256; n++) {
            size_t t = (size_t)(c * 256 + n) * QKVW + (size_t)h * DH;
            acc += expf(-s * (float)(255 - n)) * g_qkv[t + 2048 + d] * g_qkv[t + 4096 + e];
        }
        g_kvblk[((size_t)(h * 32 + c)) * 16384 + (size_t)e * 128 + d] = acc;
    }
#endif
}

// ============ Phase B: decay scan — 256 CTAs ================================
__global__ void kvscan_kernel() {
    int h = blockIdx.x >> 4;
    int seg = blockIdx.x & 15;
    float bdec = expf(-g_slopes[h] * 256.0f);
    int e = seg * 1024 + threadIdx.x;
    #pragma unroll
    for (int r = 0; r < 4; r++, e += 256) {
        float acc = 0.f;
        size_t base = (size_t)h * NCHUNK * 16384 + e;
        #pragma unroll
        for (int c = 0; c < NCHUNK; c++) {
            g_kvstate[base + (size_t)c * 16384] = acc;
            acc = bdec * acc + g_kvblk[base + (size_t)c * 16384];
        }
    }
}

// ============ Phase C: attention (single O accumulator, 2 CTAs/SM) ==========
__global__ __launch_bounds__(256, 2) void attn_tensor_kernel() {
#if HAS_TCGEN05
    extern __shared__ char smem[];
    uint32_t sb = smem_to_u32(smem);
    int tid = threadIdx.x;
    int mi = blockIdx.x & 1, c = (blockIdx.x >> 1) & 31, h = blockIdx.x >> 6;
    float s = g_slopes[h];
    float* decay_tab = (float*)(smem + 16);
    const int QH   = 2048;
    const int KHI  = 34816, KLO = 51200;
    const int VH   = 67584;
    const int SH   = 83968;
    const int KVHI = 34816, KVLO = 67584;
    uint32_t mb = sb + 8;
    if (tid < 32) TCGEN05_ALLOC(sb, 256);
    if (tid == 0) MBARRIER_INIT(mb, 1);
    for (int i = tid; i < 257; i += 256) decay_tab[i] = expf(-s * (float)i);
    __syncthreads();
    uint32_t tmem;
    asm volatile("ld.shared.b32 %0, [%1];" : "=r"(tmem) : "r"(sb));
    if (tid < 32) TCGEN05_RELINQ();
    const uint32_t OT = tmem, ST = tmem + 128;
    const uint32_t IDESC128F = (1u << 4) | (16u << 17) | (8u << 24);
    const uint32_t IDESC64F  = (1u << 4) | (8u  << 17) | (8u << 24);

    const float* qb = g_qkv + (size_t)(c * 256 + mi * 128) * QKVW + (size_t)h * DH;
    #pragma unroll
    for (int it = 0; it < 16; it++) {
        int j = it * 256 + tid;
        int r = j >> 5, dq = (j & 31) << 2;
        float4 v = *(const float4*)&qb[(size_t)r * QKVW + dq];
        uint32_t o = bswz(r, dq, 16);
        *(uint2*)(smem + QH + o) = make_uint2(
            pkh(__float2half_rn(v.x), __float2half_rn(v.y)),
            pkh(__float2half_rn(v.z), __float2half_rn(v.w)));
    }
    int ph = 0;
    const int nch = 2 * mi + 2;
    for (int cn = 0; cn < nch; cn++) {
        const float* kb = g_qkv + (size_t)(c * 256 + cn * 64) * QKVW + 2048 + (size_t)h * DH;
        #pragma unroll
        for (int it = 0; it < 8; it++) {
            int j = it * 256 + tid;
            int r = j >> 5, dq = (j & 31) << 2;
            float4 v = *(const float4*)&kb[(size_t)r * QKVW + dq];
            __half h0 = __float2half_rn(v.x), h1 = __float2half_rn(v.y);
            __half h2 = __float2half_rn(v.z), h3 = __float2half_rn(v.w);
            uint32_t o = bswz(r, dq, 8);
            *(uint2*)(smem + KHI + o) = make_uint2(pkh(h0, h1), pkh(h2, h3));
            *(uint2*)(smem + KLO + o) = make_uint2(
                pkh(__float2half_rn(v.x - __half2float(h0)), __float2half_rn(v.y - __half2float(h1))),
                pkh(__float2half_rn(v.z - __half2float(h2)), __float2half_rn(v.w - __half2float(h3))));
        }
        {
            const uint4* sh = (const uint4*)(g_vThi + (size_t)(h * 32 + c) * 32768 + cn * 8192);
            uint4* dh = (uint4*)(smem + VH);
            #pragma unroll
            for (int it = 0; it < 4; it++) {
                int j = it * 256 + tid;
                dh[j] = sh[j];
            }
        }
        FENCE_ASYNC_SHARED();
        __syncthreads();
        if (tid < 32) {
            uint64_t dQ = MAKE_SMEM_DESC(sb + QH);
            uint64_t dKh = MAKE_SMEM_DESC(sb + KHI), dKl = MAKE_SMEM_DESC(sb + KLO);
            if (elect_one_pred()) {
                #pragma unroll
                for (int st = 0; st < 8; st++) {
                    uint32_t uq = ((st >> 2) << 10) + ((st & 3) << 1);
                    uint32_t uk = ((st >> 2) << 9) + ((st & 3) << 1);
                    mma_f16_ss(ST, dQ + uq, dKh + uk, IDESC64F, st != 0);
                    mma_f16_ss(ST, dQ + uq, dKl + uk, IDESC64F, true);
                }
                TCGEN05_COMMIT(mb);
            }
        }
        MBARRIER_WAIT_PARITY(mb, ph & 1); ph++;
        TCGEN05_FENCE_AFTER();
        if (tid < 128) {
            int w = tid >> 5, l = tid & 31, m = w * 32 + l;
            int gm = mi * 128 + m;
            uint32_t r0[32], r1[32];
            TCGEN05_LD_X32(r0, ST);
            TCGEN05_WAIT_LD();
            TCGEN05_LD_X32(r1, ST + 32);
            TCGEN05_WAIT_LD();
            #pragma unroll
            for (int g = 0; g < 8; g++) {
                uint32_t hp[4];
                #pragma unroll
                for (int jj = 0; jj < 4; jj++) {
                    int j0 = g * 8 + jj * 2;
                    float v0 = __uint_as_float(j0 < 32 ? r0[j0] : r1[j0 - 32]);
                    float v1 = __uint_as_float((j0 + 1) < 32 ? r0[j0 + 1] : r1[j0 - 31]);
                    int gn0 = cn * 64 + j0;
                    v0 = (gm >= gn0)     ? v0 * decay_tab[gm - gn0]     : 0.f;
                    v1 = (gm >= gn0 + 1) ? v1 * decay_tab[gm - gn0 - 1] : 0.f;
                    hp[jj] = pkh(__float2half_rn(v0), __float2half_rn(v1));
                }
                uint32_t o = bswz(m, g * 8, 16);
                *(uint4*)(smem + SH + o) = make_uint4(hp[0], hp[1], hp[2], hp[3]);
            }
        }
        FENCE_ASYNC_SHARED();
        __syncthreads();
        if (tid < 32) {
            uint64_t dS = MAKE_SMEM_DESC(sb + SH);
            uint64_t dV = MAKE_SMEM_DESC(sb + VH);
            if (elect_one_pred()) {
                #pragma unroll
                for (int st = 0; st < 4; st++) {
                    uint32_t u = (uint32_t)st << 1;
                    bool first = (cn == 0 && st == 0);
                    mma_f16_ss(OT, dS + u, dV + u, IDESC128F, !first);
                }
                TCGEN05_COMMIT(mb);
            }
        }
        MBARRIER_WAIT_PARITY(mb, ph & 1); ph++;
    }
    // ---- final: O += (qd·q)·kvstT ----
    {
        #pragma unroll
        for (int it = 0; it < 16; it++) {
            int j = it * 256 + tid;
            int r = j >> 5, dq = (j & 31) << 2;
            float qd = decay_tab[mi * 128 + r + 1];
            float4 v = *(const float4*)&qb[(size_t)r * QKVW + dq];
            uint32_t o = bswz(r, dq, 16);
            *(uint2*)(smem + QH + o) = make_uint2(
                pkh(__float2half_rn(v.x * qd), __float2half_rn(v.y * qd)),
                pkh(__float2half_rn(v.z * qd), __float2half_rn(v.w * qd)));
        }
        const float* kvb = g_kvstate + (size_t)(h * 32 + c) * 16384;
        #pragma unroll
        for (int it = 0; it < 16; it++) {
            int j = it * 256 + tid;
            int r = j >> 5, dq = (j & 31) << 2;
            float4 v = *(const float4*)&kvb[(size_t)r * 128 + dq];
            __half h0 = __float2half_rn(v.x), h1 = __float2half_rn(v.y);
            __half h2 = __float2half_rn(v.z), h3 = __float2half_rn(v.w);
            uint32_t o = bswz(r, dq, 16);
            *(uint2*)(smem + KVHI + o) = make_uint2(pkh(h0, h1), pkh(h2, h3));
            *(uint2*)(smem + KVLO + o) = make_uint2(
                pkh(__float2half_rn(v.x - __half2float(h0)), __float2half_rn(v.y - __half2float(h1))),
                pkh(__float2half_rn(v.z - __half2float(h2)), __float2half_rn(v.w - __half2float(h3))));
        }
        FENCE_ASYNC_SHARED();
        __syncthreads();
        if (tid < 32) {
            uint64_t dQ = MAKE_SMEM_DESC(sb + QH);
            uint64_t dKh = MAKE_SMEM_DESC(sb + KVHI), dKl = MAKE_SMEM_DESC(sb + KVLO);
            if (elect_one_pred()) {
                #pragma unroll
                for (int st = 0; st < 8; st++) {
                    uint32_t u = ((st >> 2) << 10) + ((st & 3) << 1);
                    mma_f16_ss(OT, dQ + u, dKh + u, IDESC128F, true);
                    mma_f16_ss(OT, dQ + u, dKl + u, IDESC128F, true);
                }
                TCGEN05_COMMIT(mb);
            }
        }
        MBARRIER_WAIT_PARITY(mb, ph & 1); ph++;
    }
    TCGEN05_FENCE_AFTER();
    if (tid < 128) {
        int w = tid >> 5, l = tid & 31, m = w * 32 + l;
        int gm = mi * 128 + m;
        float* dst = g_attn + (size_t)(c * 256 + gm) * HIDDEN + (size_t)h * DH;
        #pragma unroll
        for (int cb = 0; cb < 4; cb++) {
            uint32_t a[32];
            TCGEN05_LD_X32(a, OT + cb * 32);
            TCGEN05_WAIT_LD();
            #pragma unroll
            for (int j = 0; j < 32; j += 4)
                *(float4*)&dst[cb * 32 + j] = make_float4(
                    __uint_as_float(a[j]),     __uint_as_float(a[j + 1]),
                    __uint_as_float(a[j + 2]), __uint_as_float(a[j + 3]));
        }
    }
    __syncthreads();
    if (tid < 32) TCGEN05_DEALLOC(tmem, 256);
#else
    int mi = blockIdx.x & 1, c = (blockIdx.x >> 1) & 31, h = blockIdx.x >> 6;
    float s = g_slopes[h];
    const float* kvst = g_kvstate + (size_t)(h * 32 + c) * 16384;
    for (int idx = threadIdx.x; idx < 16384; idx += 256) {
        int m = idx >> 7, e = idx & 127;
        int gm = mi * 128 + m;
        size_t tq = (size_t)(c * 256 + gm) * QKVW + (size_t)h * DH;
        float o = 0.f;
        for (int d = 0; d < 128; d++) o += g_qkv[tq + d] * kvst[(size_t)e * 128 + d];
        o *= expf(-s * (float)(gm + 1));
        for (int n = 0; n <= gm; n++) {
            size_t tk = (size_t)(c * 256 + n) * QKVW + (size_t)h * DH;
            float qk = 0.f;
            for (int d = 0; d < 128; d++) qk += g_qkv[tq + d] * g_qkv[tk + 2048 + d];
            o += expf(-s * (float)(gm - n)) * qk * g_qkv[tk + 4096 + e];
        }
        g_attn[(size_t)(c * 256 + gm) * HIDDEN + (size_t)h * DH + e] = o;
    }
#endif
}

// ============ RMS norm + sigmoid gate -> fp16 output ========================
__global__ void rmsgate_kernel(const float* __restrict__ gnw) {
    int t = blockIdx.x;
    int tid = threadIdx.x;
    const float* a = g_attn + (size_t)t * HIDDEN;
    const float* g = g_gate + (size_t)t * HIDDEN;
    float ss = 0.f;
    for (int j = tid; j < HIDDEN; j += 256) { float v = a[j]; ss += v * v; }
    #pragma unroll
    for (int o = 16; o; o >>= 1) ss += __shfl_xor_sync(0xffffffffu, ss, o);
    __shared__ float red[8];
    __shared__ float tot;
    if ((tid & 31) == 0) red[tid >> 5] = ss;
    __syncthreads();
    if (tid == 0) {
        float tsum = 0.f;
        #pragma unroll
        for (int w = 0; w < 8; w++) tsum += red[w];
        tot = tsum;
    }
    __syncthreads();
    float rms = rsqrtf(tot * (1.0f / HIDDEN) + 1e-5f);
    for (int j = tid; j < HIDDEN; j += 256) {
        float gv = g[j];
        float sig = 1.0f / (1.0f + expf(-gv));
        float val = a[j] * rms * gnw[j] * sig;
        g_yh[(size_t)t * HIDDEN + j] = __float2half_rn(val);
    }
}

// ================= launch =====================================================
extern "C" void kernel_launch(void* const* d_in, const int* in_sizes, int n_in,
                              void* d_out, int out_size) {
    const float* hidden    = (const float*)d_in[0];
    const int*   positions = (const int*)d_in[1];
    const float* Wqkv      = (const float*)d_in[2];
    const float* Wg        = (const float*)d_in[3];
    const float* Wd        = (const float*)d_in[4];
    const float* gnw       = (const float*)d_in[5];
    float* out = (float*)d_out;

    void *ah_p, *yh_p;
    void *bqh_p, *bql_p, *bgh_p, *bgl_p, *bdh_p, *bdl_p;
    cudaGetSymbolAddress(&ah_p, g_ah);
    cudaGetSymbolAddress(&yh_p, g_yh);
    cudaGetSymbolAddress(&bqh_p, g_bqkv_hi); cudaGetSymbolAddress(&bql_p, g_bqkv_lo);
    cudaGetSymbolAddress(&bgh_p, g_bg_hi);   cudaGetSymbolAddress(&bgl_p, g_bg_lo);
    cudaGetSymbolAddress(&bdh_p, g_bd_hi);   cudaGetSymbolAddress(&bdl_p, g_bd_lo);

    cudaFuncSetAttribute(gemm_qkvgate, cudaFuncAttributeMaxDynamicSharedMemorySize, CG2_SMEM);
    cudaFuncSetAttribute(gemm_down, cudaFuncAttributeMaxDynamicSharedMemorySize, CG2_SMEM);
    const int kvblk_smem = 2048 + 67584 + 3 * 32768;   // 167936
    cudaFuncSetAttribute(kvblkT_kernel, cudaFuncAttributeMaxDynamicSharedMemorySize, kvblk_smem);
    const int attn_smem = 100352;                      // 98 KB -> 2 CTAs/SM
    cudaFuncSetAttribute(attn_tensor_kernel, cudaFuncAttributeMaxDynamicSharedMemorySize, attn_smem);

    init_tables<<<1, 64>>>();
    conv_act<<<(NTOK * HIDDEN / 4 + 255) / 256, 256>>>(hidden, (__half*)ah_p,
                                                       NTOK * HIDDEN / 4);
    transposeW<<<dim3(QKVW / 32, HIDDEN / 32), 256>>>(Wqkv,
        (__half*)bqh_p, (__half*)bql_p, HIDDEN, QKVW);
    transposeW<<<dim3(HIDDEN / 32, HIDDEN / 32), 256>>>(Wg,
        (__half*)bgh_p, (__half*)bgl_p, HIDDEN, HIDDEN);
    transposeW<<<dim3(HIDDEN / 32, HIDDEN / 32), 256>>>(Wd,
        (__half*)bdh_p, (__half*)bdl_p, HIDDEN, HIDDEN);
    gemm_qkvgate<<<dim3(((QKVW + HIDDEN) / 256) * 2, NTOK / 256), 256, CG2_SMEM>>>(
        (const __half*)ah_p, positions);
    kvblkT_kernel<<<HEADS * NCHUNK, 256, kvblk_smem>>>();
    kvscan_kernel<<<HEADS * 16, 256>>>();
    attn_tensor_kernel<<<HEADS * NCHUNK * 2, 256, attn_smem>>>();
    rmsgate_kernel<<<NTOK, 256>>>(gnw);
    gemm_down<<<dim3((HIDDEN / 256) * 2, NTOK / 256), 256, CG2_SMEM>>>(
        (const __half*)yh_p, (const __half*)bdh_p,
        out, HIDDEN, HIDDEN);
}

// round 15
// speedup vs baseline: 1.2990x; 1.0871x over previous
#include <cuda_runtime.h>
#include <cuda_bf16.h>
#include <cuda_fp16.h>
#include <math.h>
#include <cstdint>

#define NTOK 8192
#define HIDDEN 2048
#define HEADS 16
#define DH 128
#define BLK 256
#define NCHUNK 32
#define QKVW 6144

#if defined(__CUDA_ARCH_FEAT_SM103_ALL) || \
    (defined(__CUDA_ARCH_SPECIFIC__) && (__CUDA_ARCH_SPECIFIC__ == 1030)) || \
    (defined(__CUDA_ARCH_FAMILY_SPECIFIC__) && (__CUDA_ARCH_FAMILY_SPECIFIC__ == 1030))
#define HAS_TCGEN05 1
#else
#define HAS_TCGEN05 0
#endif

// ================= PTX helpers ==============================================
__device__ __forceinline__ uint32_t elect_one_pred() {
    uint32_t pred;
    asm volatile("{\n\t.reg .pred p;\n\telect.sync _|p, 0xFFFFFFFF;\n\t"
                 "selp.b32 %0, 1, 0, p;\n\t}" : "=r"(pred));
    return pred;
}
__device__ __forceinline__ uint32_t smem_to_u32(const void* p) {
    uint32_t a;
    asm("{ .reg .u64 t; cvta.to.shared.u64 t, %1; cvt.u32.u64 %0, t; }"
        : "=r"(a) : "l"(p));
    return a;
}
__device__ __forceinline__ uint32_t cluster_rank() {
    uint32_t r;
    asm("mov.u32 %0, %%cluster_ctarank;" : "=r"(r));
    return r;
}
#define CLUSTER_SYNC() do { \
    asm volatile("barrier.cluster.arrive.aligned;" ::: "memory"); \
    asm volatile("barrier.cluster.wait.aligned;" ::: "memory"); \
} while (0)
#define MBARRIER_INIT(addr, cnt) \
    asm volatile("mbarrier.init.shared.b64 [%0], %1;" :: "r"((uint32_t)(addr)), "r"((uint32_t)(cnt)) : "memory")
#define MBARRIER_WAIT_PARITY(addr, par) do { \
    uint32_t _m = (uint32_t)(addr); uint32_t _p = (uint32_t)(par); uint32_t _d; \
    asm volatile("{\n\t.reg .pred p;\n\t" \
        "mbarrier.try_wait.parity.acquire.cta.shared::cta.b64 p, [%1], %2;\n\t" \
        "selp.b32 %0, 1, 0, p;\n\t}" : "=r"(_d) : "r"(_m), "r"(_p) : "memory"); \
    if (!_d) { \
        asm volatile("{\n\t.reg .pred P1;\n\t" \
            "WL_%=:\n\t" \
            "mbarrier.try_wait.parity.acquire.cta.shared::cta.b64 P1, [%0], %1, 0x989680;\n\t" \
            "@P1 bra.uni WD_%=;\n\tbra.uni WL_%=;\n\tWD_%=:\n\t}" \
            :: "r"(_m), "r"(_p) : "memory"); \
    } } while (0)
#define MBARRIER_WAIT_PARITY_CL(addr, par) do { \
    uint32_t _m = (uint32_t)(addr); uint32_t _p = (uint32_t)(par); uint32_t _d; \
    asm volatile("{\n\t.reg .pred p;\n\t" \
        "mbarrier.try_wait.parity.acquire.cluster.shared::cta.b64 p, [%1], %2;\n\t" \
        "selp.b32 %0, 1, 0, p;\n\t}" : "=r"(_d) : "r"(_m), "r"(_p) : "memory"); \
    if (!_d) { \
        asm volatile("{\n\t.reg .pred P1;\n\t" \
            "WL_%=:\n\t" \
            "mbarrier.try_wait.parity.acquire.cluster.shared::cta.b64 P1, [%0], %1, 0x989680;\n\t" \
            "@P1 bra.uni WD_%=;\n\tbra.uni WL_%=;\n\tWD_%=:\n\t}" \
            :: "r"(_m), "r"(_p) : "memory"); \
    } } while (0)
#define MBARRIER_ARRIVE_CLUSTER(local_addr, target_rank) \
    asm volatile( \
        "{\n\t.reg .b32 remAddr32;\n\t" \
        "mapa.shared::cluster.u32 remAddr32, %0, %1;\n\t" \
        "mbarrier.arrive.release.cluster.shared::cluster.b64 _, [remAddr32];\n\t}" \
        :: "r"((uint32_t)(local_addr)), "r"((uint32_t)(target_rank)) : "memory")
#define TCGEN05_ALLOC(smem_addr, n) \
    asm volatile("tcgen05.alloc.cta_group::1.sync.aligned.shared::cta.b32 [%0], %1;" \
        :: "r"((uint32_t)(smem_addr)), "r"((uint32_t)(n)) : "memory")
#define TCGEN05_DEALLOC(tmem, n) \
    asm volatile("tcgen05.dealloc.cta_group::1.sync.aligned.b32 %0, %1;" :: "r"(tmem), "r"((uint32_t)(n)))
#define TCGEN05_RELINQ() \
    asm volatile("tcgen05.relinquish_alloc_permit.cta_group::1.sync.aligned;")
#define TCGEN05_ALLOC_CG2(smem_addr, n) \
    asm volatile("tcgen05.alloc.cta_group::2.sync.aligned.shared::cta.b32 [%0], %1;" \
        :: "r"((uint32_t)(smem_addr)), "r"((uint32_t)(n)) : "memory")
#define TCGEN05_DEALLOC_CG2(tmem, n) \
    asm volatile("tcgen05.dealloc.cta_group::2.sync.aligned.b32 %0, %1;" :: "r"(tmem), "r"((uint32_t)(n)))
#define TCGEN05_RELINQ_CG2() \
    asm volatile("tcgen05.relinquish_alloc_permit.cta_group::2.sync.aligned;")
#define TCGEN05_COMMIT(mbar) \
    asm volatile("tcgen05.commit.cta_group::1.mbarrier::arrive::one.shared::cluster.b64 [%0];" \
        :: "r"((uint32_t)(mbar)) : "memory")
#define TCGEN05_COMMIT_MC_CG2(mbar, mask) \
    asm volatile("tcgen05.commit.cta_group::2.mbarrier::arrive::one.shared::cluster.multicast::cluster.b64 [%0], %1;" \
        :: "r"((uint32_t)(mbar)), "h"((uint16_t)(mask)) : "memory")
#define TCGEN05_FENCE_AFTER() asm volatile("tcgen05.fence::after_thread_sync;" ::: "memory")
#define TCGEN05_WAIT_LD() asm volatile("tcgen05.wait::ld.sync.aligned;" ::: "memory")
#define FENCE_ASYNC_SHARED() asm volatile("fence.proxy.async.shared::cta;" ::: "memory")
#define TCGEN05_LD_X32(r, addr) \
    asm volatile("tcgen05.ld.sync.aligned.32x32b.x32.b32 " \
        "{%0, %1, %2, %3, %4, %5, %6, %7, %8, %9, %10, %11, %12, %13, %14, %15, " \
        " %16, %17, %18, %19, %20, %21, %22, %23, %24, %25, %26, %27, %28, %29, %30, %31}, [%32];" \
        : "=r"((r)[0]),  "=r"((r)[1]),  "=r"((r)[2]),  "=r"((r)[3]), \
          "=r"((r)[4]),  "=r"((r)[5]),  "=r"((r)[6]),  "=r"((r)[7]), \
          "=r"((r)[8]),  "=r"((r)[9]),  "=r"((r)[10]), "=r"((r)[11]), \
          "=r"((r)[12]), "=r"((r)[13]), "=r"((r)[14]), "=r"((r)[15]), \
          "=r"((r)[16]), "=r"((r)[17]), "=r"((r)[18]), "=r"((r)[19]), \
          "=r"((r)[20]), "=r"((r)[21]), "=r"((r)[22]), "=r"((r)[23]), \
          "=r"((r)[24]), "=r"((r)[25]), "=r"((r)[26]), "=r"((r)[27]), \
          "=r"((r)[28]), "=r"((r)[29]), "=r"((r)[30]), "=r"((r)[31]) \
        : "r"(addr))

static constexpr uint64_t SMEM_DESC_BASE_SW128 =
    (uint64_t(2) << 61) | (uint64_t(1) << 46) | (uint64_t(64) << 32) | (uint64_t(1) << 16);
#define MAKE_SMEM_DESC(a) (SMEM_DESC_BASE_SW128 | ((uint64_t)((a) >> 4) & 0x3FFF))

#if HAS_TCGEN05
__device__ __forceinline__ void mma_f16_ss(uint32_t d_tmem, uint64_t a_desc,
                                           uint64_t b_desc, uint32_t idesc, bool acc) {
    uint32_t en = acc ? 1u : 0u;
    asm volatile(
        "{\n\t.reg .pred p;\n\tsetp.ne.u32 p, %5, 0;\n\t"
        "tcgen05.mma.cta_group::1.kind::f16 [%0], %1, %2, %3, {%4, %4, %4, %4}, p;\n\t}"
        :: "r"(d_tmem), "l"(a_desc), "l"(b_desc), "r"(idesc), "r"(0u), "r"(en)
        : "memory");
}
__device__ __forceinline__ void mma_f16_ss_cg2(uint32_t d_tmem, uint64_t a_desc,
                                               uint64_t b_desc, uint32_t idesc, bool acc) {
    uint32_t en = acc ? 1u : 0u;
    asm volatile(
        "{\n\t.reg .pred p;\n\tsetp.ne.u32 p, %5, 0;\n\t"
        "tcgen05.mma.cta_group::2.kind::f16 [%0], %1, %2, %3, "
        "{%4, %4, %4, %4, %4, %4, %4, %4}, p;\n\t}"
        :: "r"(d_tmem), "l"(a_desc), "l"(b_desc), "r"(idesc), "r"(0u), "r"(en)
        : "memory");
}
#endif

__device__ __forceinline__ uint32_t bswz(int row, int col, int atomrows) {
    uint32_t off = (uint32_t)(((row >> 3) + (col >> 6) * atomrows) << 10)
                 + ((row & 7) << 7) + ((col & 63) << 1);
    return off ^ ((off >> 3) & 0x70);
}
__device__ __forceinline__ uint32_t pkh(__half a, __half b) {
    __half2 t{a, b};
    return *(uint32_t*)&t;
}

// ================= scratch ===================================================
__device__ float g_qkv[(size_t)NTOK * QKVW];
__device__ float g_gate[(size_t)NTOK * HIDDEN];
__device__ float g_attn[(size_t)NTOK * HIDDEN];
__device__ float g_kvblk[(size_t)HEADS * NCHUNK * DH * DH];
__device__ float g_kvstate[(size_t)HEADS * NCHUNK * DH * DH];
__device__ float g_invf[64];
__device__ float g_slopes[HEADS];
__device__ __half g_vThi[(size_t)HEADS * NCHUNK * 32768];
__device__ __half g_ah[(size_t)NTOK * HIDDEN];
__device__ __half g_yh[(size_t)NTOK * HIDDEN];
__device__ __half g_bqkv_hi[(size_t)QKVW * HIDDEN];
__device__ __half g_bg_hi[(size_t)HIDDEN * HIDDEN];
__device__ __half g_bd_hi[(size_t)HIDDEN * HIDDEN];

// ================= init tables ================================================
__global__ void init_tables() {
    int t = threadIdx.x;
    if (t < 64) g_invf[t] = (float)pow(600000.0, -(double)t / 64.0);
    if (t < HEADS) {
        double start = pow(2.0, -pow(2.0, -(log2(16.0) - 3.0)));
        g_slopes[t] = (float)(start * pow(start, (double)t) * (1.0 + 1e-5));
    }
}

// ================= convert fp32 -> fp16 (A operand, single) =================
__global__ void conv_act(const float* __restrict__ x, __half* __restrict__ h, int n4) {
    int i = blockIdx.x * blockDim.x + threadIdx.x;
    if (i >= n4) return;
    float4 v = ((const float4*)x)[i];
    __half2 a{__float2half_rn(v.x), __float2half_rn(v.y)};
    __half2 b{__float2half_rn(v.z), __float2half_rn(v.w)};
    ((__half2*)h)[i * 2]     = a;
    ((__half2*)h)[i * 2 + 1] = b;
}

// ======= transpose W[K,N] fp32 -> Thi [N,K] fp16 (single) ===================
__global__ void transposeW(const float* __restrict__ W, __half* __restrict__ Thi,
                           int K, int N) {
    __shared__ float t[32][33];
    int n0 = blockIdx.x * 32, k0 = blockIdx.y * 32;
    int c = threadIdx.x & 31, r0 = threadIdx.x >> 5;
    #pragma unroll
    for (int rr = r0; rr < 32; rr += 8)
        t[rr][c] = W[(size_t)(k0 + rr) * N + n0 + c];
    __syncthreads();
    #pragma unroll
    for (int rr = r0; rr < 32; rr += 8)
        Thi[(size_t)(n0 + rr) * K + k0 + c] = __float2half_rn(t[c][rr]);
}

#if HAS_TCGEN05
template <int ROWS>
__device__ __forceinline__ void load_tile(char* dst, const __half* src, int ld) {
    int tid = threadIdx.x;
    #pragma unroll
    for (int l = 0; l < ROWS / 32; l++) {
        int i = l * 256 + tid;
        int r = i >> 3, sg = i & 7;
        uint4 v = *(const uint4*)(src + (size_t)r * ld + sg * 8);
        uint32_t off = (uint32_t)(r * 128 + sg * 16);
        off ^= (off >> 3) & 0x70;
        *(uint4*)(dst + off) = v;
    }
}
#endif

// ======= cg2 fp16 single-term GEMM constants (K-chunk 64) ====================
// per-buffer: A 16K | Bhi 16K = 32KB; x2 buffers -> 65KB smem (2 CTAs/SM free)
#define CG2_BUF 32768
#define CG2_SMEM (1024 + 2 * CG2_BUF)
#define IDESC_CG2 ((1u << 4) | (32u << 17) | (16u << 24))

// ======= fused qkv+gate GEMM (cg2 fp16 single-term) with RoPE epilogue =======
__global__ __launch_bounds__(256, 1) __cluster_dims__(2, 1, 1)
void gemm_qkvgate(const __half* __restrict__ A, const int* __restrict__ positions) {
    const int K = HIDDEN;
    uint32_t rank = cluster_rank();
    int bm = blockIdx.y * 256;
    int bn = (blockIdx.x >> 1) * 256;
    int gcs = bn + (int)rank * 128;
    const __half* Bhi = (gcs < QKVW) ? g_bqkv_hi + (size_t)gcs * K
                                     : g_bg_hi + (size_t)(gcs - QKVW) * K;
#if HAS_TCGEN05
    extern __shared__ char smem[];
    uint32_t sb = smem_to_u32(smem);
    int tid = threadIdx.x;
    const uint32_t dn0 = sb + 8,  dn1 = sb + 16;
    const uint32_t rd0 = sb + 24, rd1 = sb + 32;
    if (tid < 32) TCGEN05_ALLOC_CG2(sb, 256);
    if (tid == 0) {
        MBARRIER_INIT(dn0, 1); MBARRIER_INIT(dn1, 1);
        MBARRIER_INIT(rd0, 2); MBARRIER_INIT(rd1, 2);
    }
    __syncthreads();
    uint32_t tmem;
    asm volatile("ld.shared.b32 %0, [%1];" : "=r"(tmem) : "r"(sb));
    if (tid < 32) TCGEN05_RELINQ_CG2();
    CLUSTER_SYNC();

    const __half* pA = A + (size_t)(bm + rank * 128) * K;

    int phd[2] = {0, 0};
    int phr[2] = {0, 0};
    for (int ch = 0; ch < 32; ch++) {
        int b = ch & 1;
        char* st = smem + 1024 + b * CG2_BUF;
        if (ch >= 2) {
            MBARRIER_WAIT_PARITY_CL(b ? dn1 : dn0, phd[b]);
            phd[b] ^= 1;
        }
        int k0 = ch << 6;
        load_tile<128>(st,         pA + k0,  K);
        load_tile<128>(st + 16384, Bhi + k0, K);
        FENCE_ASYNC_SHARED();
        __syncthreads();
        if (tid == 0) MBARRIER_ARRIVE_CLUSTER(b ? rd1 : rd0, 0);
        if (rank == 0 && tid < 32) {
            MBARRIER_WAIT_PARITY_CL(b ? rd1 : rd0, phr[b]);
            phr[b] ^= 1;
            uint32_t sa = sb + 1024 + b * CG2_BUF;
            uint64_t dA  = MAKE_SMEM_DESC(sa);
            uint64_t dBh = MAKE_SMEM_DESC(sa + 16384);
            if (elect_one_pred()) {
                #pragma unroll
                for (int k = 0; k < 4; k++) {
                    bool first = (ch == 0) && (k == 0);
                    mma_f16_ss_cg2(tmem, dA + k * 2, dBh + k * 2, IDESC_CG2, !first);
                }
                TCGEN05_COMMIT_MC_CG2(b ? dn1 : dn0, 0x3);
            }
        }
    }
    MBARRIER_WAIT_PARITY_CL(dn0, phd[0]);
    MBARRIER_WAIT_PARITY_CL(dn1, phd[1]);
    TCGEN05_FENCE_AFTER();
    __syncthreads();

    int w = tid >> 5, l = tid & 31;
    int sub = w & 3;
    int colbase = (w >> 2) * 128;
    int row = bm + (int)rank * 128 + sub * 32 + l;
    int gc0 = bn + colbase;
    bool isQ = gc0 < 2048;
    bool isK = (gc0 >= 2048) && (gc0 < 4096);
    float* dst = (gc0 < QKVW) ? g_qkv + (size_t)row * QKVW + gc0
                              : g_gate + (size_t)row * HIDDEN + (gc0 - QKVW);
    if (isQ || isK) {
        float pos = (float)positions[row];
        float qs = isQ ? 0.08838834764831845f : 1.0f;
        #pragma unroll
        for (int half = 0; half < 2; half++) {
            uint32_t a[32], b[32];
            TCGEN05_LD_X32(a, tmem + colbase + half * 32);
            TCGEN05_WAIT_LD();
            TCGEN05_LD_X32(b, tmem + colbase + half * 32 + 64);
            TCGEN05_WAIT_LD();
            #pragma unroll
            for (int j0 = 0; j0 < 32; j0 += 4) {
                float o1[4], o2[4];
                #pragma unroll
                for (int j = 0; j < 4; j++) {
                    int jin = half * 32 + j0 + j;
                    float f = pos * g_invf[jin];
                    float sv, cv;
                    sincosf(f, &sv, &cv);
                    float x1 = __uint_as_float(a[j0 + j]);
                    float x2 = __uint_as_float(b[j0 + j]);
                    o1[j] = (x1 * cv - x2 * sv) * qs;
                    o2[j] = (x2 * cv + x1 * sv) * qs;
                }
                *(float4*)&dst[half * 32 + j0]      = make_float4(o1[0], o1[1], o1[2], o1[3]);
                *(float4*)&dst[half * 32 + 64 + j0] = make_float4(o2[0], o2[1], o2[2], o2[3]);
            }
        }
    } else {
        #pragma unroll
        for (int cb = 0; cb < 128; cb += 32) {
            uint32_t r[32];
            TCGEN05_LD_X32(r, tmem + colbase + cb);
            TCGEN05_WAIT_LD();
            #pragma unroll
            for (int j = 0; j < 32; j += 4)
                *(float4*)&dst[cb + j] = make_float4(
                    __uint_as_float(r[j]), __uint_as_float(r[j + 1]),
                    __uint_as_float(r[j + 2]), __uint_as_float(r[j + 3]));
        }
    }
    __syncthreads();
    if (tid < 32) TCGEN05_DEALLOC_CG2(tmem, 256);
    CLUSTER_SYNC();
#else
    extern __shared__ char smemraw[];
    float* As = (float*)smemraw;
    float* Bs = As + 16 * 128;
    int tid = threadIdx.x;
    int bmr = bm + (int)rank * 128;
    int ty = tid >> 4, tx = tid & 15;
    float acc[8][16];
    #pragma unroll
    for (int i = 0; i < 8; i++)
        #pragma unroll
        for (int j = 0; j < 16; j++) acc[i][j] = 0.f;
    for (int k0 = 0; k0 < K; k0 += 16) {
        #pragma unroll
        for (int l = 0; l < 8; l++) {
            int i = l * 256 + tid;
            int k = i & 15, m = i >> 4;
            As[k * 128 + m] = __half2float(A[(size_t)(bmr + m) * K + k0 + k]);
        }
        #pragma unroll
        for (int l = 0; l < 16; l++) {
            int i = l * 256 + tid;
            int k = i & 15, n = i >> 4;
            int gc = bn + n;
            const __half* bh = (gc < QKVW) ? g_bqkv_hi + (size_t)gc * K
                                           : g_bg_hi + (size_t)(gc - QKVW) * K;
            Bs[k * 256 + n] = __half2float(bh[k0 + k]);
        }
        __syncthreads();
        #pragma unroll
        for (int kk = 0; kk < 16; kk++) {
            float a[8], b[16];
            #pragma unroll
            for (int i = 0; i < 8; i++) a[i] = As[kk * 128 + ty * 8 + i];
            #pragma unroll
            for (int j = 0; j < 16; j++) b[j] = Bs[kk * 256 + tx * 16 + j];
            #pragma unroll
            for (int i = 0; i < 8; i++)
                #pragma unroll
                for (int j = 0; j < 16; j++) acc[i][j] += a[i] * b[j];
        }
        __syncthreads();
    }
    float* tileS = (float*)smemraw;
    #pragma unroll
    for (int i = 0; i < 8; i++)
        #pragma unroll
        for (int j = 0; j < 16; j++)
            tileS[(ty * 8 + i) * 257 + tx * 16 + j] = acc[i][j];
    __syncthreads();
    {
        int r = tid >> 1, sp = tid & 1;
        int row = bmr + r;
        int gc0 = bn + sp * 128;
        bool isQ = gc0 < 2048;
        bool isK = (gc0 >= 2048) && (gc0 < 4096);
        float* dst = (gc0 < QKVW) ? g_qkv + (size_t)row * QKVW + gc0
                                  : g_gate + (size_t)row * HIDDEN + (gc0 - QKVW);
        const float* src = &tileS[r * 257 + sp * 128];
        if (isQ || isK) {
            float pos = (float)positions[row];
            float qs = isQ ? 0.08838834764831845f : 1.0f;
            for (int j = 0; j < 64; j++) {
                float f = pos * g_invf[j];
                float sv, cv;
                sincosf(f, &sv, &cv);
                float x1 = src[j], x2 = src[j + 64];
                dst[j]      = (x1 * cv - x2 * sv) * qs;
                dst[j + 64] = (x2 * cv + x1 * sv) * qs;
            }
        } else {
            for (int j = 0; j < 128; j++) dst[j] = src[j];
        }
    }
#endif
}

// ============ cg2 fp16 single-term down-projection GEMM =====================
__global__ __launch_bounds__(256, 1) __cluster_dims__(2, 1, 1)
void gemm_down(const __half* __restrict__ A,
               const __half* __restrict__ Bhi,
               float* __restrict__ C, int Nn, int K) {
    uint32_t rank = cluster_rank();
    int bm = blockIdx.y * 256;
    int bn = (blockIdx.x >> 1) * 256;
#if HAS_TCGEN05
    extern __shared__ char smem[];
    uint32_t sb = smem_to_u32(smem);
    int tid = threadIdx.x;
    const uint32_t dn0 = sb + 8,  dn1 = sb + 16;
    const uint32_t rd0 = sb + 24, rd1 = sb + 32;
    if (tid < 32) TCGEN05_ALLOC_CG2(sb, 256);
    if (tid == 0) {
        MBARRIER_INIT(dn0, 1); MBARRIER_INIT(dn1, 1);
        MBARRIER_INIT(rd0, 2); MBARRIER_INIT(rd1, 2);
    }
    __syncthreads();
    uint32_t tmem;
    asm volatile("ld.shared.b32 %0, [%1];" : "=r"(tmem) : "r"(sb));
    if (tid < 32) TCGEN05_RELINQ_CG2();
    CLUSTER_SYNC();

    const __half* pA   = A   + (size_t)(bm + rank * 128) * K;
    const __half* pBhi = Bhi + (size_t)(bn + rank * 128) * K;

    int phd[2] = {0, 0};
    int phr[2] = {0, 0};
    const int nch = K >> 6;
    for (int ch = 0; ch < nch; ch++) {
        int b = ch & 1;
        char* st = smem + 1024 + b * CG2_BUF;
        if (ch >= 2) {
            MBARRIER_WAIT_PARITY_CL(b ? dn1 : dn0, phd[b]);
            phd[b] ^= 1;
        }
        int k0 = ch << 6;
        load_tile<128>(st,         pA + k0,   K);
        load_tile<128>(st + 16384, pBhi + k0, K);
        FENCE_ASYNC_SHARED();
        __syncthreads();
        if (tid == 0) MBARRIER_ARRIVE_CLUSTER(b ? rd1 : rd0, 0);
        if (rank == 0 && tid < 32) {
            MBARRIER_WAIT_PARITY_CL(b ? rd1 : rd0, phr[b]);
            phr[b] ^= 1;
            uint32_t sa = sb + 1024 + b * CG2_BUF;
            uint64_t dA  = MAKE_SMEM_DESC(sa);
            uint64_t dBh = MAKE_SMEM_DESC(sa + 16384);
            if (elect_one_pred()) {
                #pragma unroll
                for (int k = 0; k < 4; k++) {
                    bool first = (ch == 0) && (k == 0);
                    mma_f16_ss_cg2(tmem, dA + k * 2, dBh + k * 2, IDESC_CG2, !first);
                }
                TCGEN05_COMMIT_MC_CG2(b ? dn1 : dn0, 0x3);
            }
        }
    }
    MBARRIER_WAIT_PARITY_CL(dn0, phd[0]);
    MBARRIER_WAIT_PARITY_CL(dn1, phd[1]);
    TCGEN05_FENCE_AFTER();
    __syncthreads();

    int w = tid >> 5, l = tid & 31;
    int sub = w & 3;
    int colbase = (w >> 2) * 128;
    int row = bm + (int)rank * 128 + sub * 32 + l;
    float* dst_row = C + (size_t)row * Nn + bn + colbase;
    #pragma unroll
    for (int cb = 0; cb < 128; cb += 32) {
        uint32_t r[32];
        TCGEN05_LD_X32(r, tmem + colbase + cb);
        TCGEN05_WAIT_LD();
        #pragma unroll
        for (int j = 0; j < 32; j += 4)
            *(float4*)(dst_row + cb + j) = make_float4(
                __uint_as_float(r[j]), __uint_as_float(r[j + 1]),
                __uint_as_float(r[j + 2]), __uint_as_float(r[j + 3]));
    }
    __syncthreads();
    if (tid < 32) TCGEN05_DEALLOC_CG2(tmem, 256);
    CLUSTER_SYNC();
#else
    extern __shared__ char smemraw[];
    float* As = (float*)smemraw;
    float* Bs = As + 16 * 128;
    int tid = threadIdx.x;
    int bmr = bm + (int)rank * 128;
    int ty = tid >> 4, tx = tid & 15;
    float acc[8][16];
    #pragma unroll
    for (int i = 0; i < 8; i++)
        #pragma unroll
        for (int j = 0; j < 16; j++) acc[i][j] = 0.f;
    for (int k0 = 0; k0 < K; k0 += 16) {
        #pragma unroll
        for (int l = 0; l < 8; l++) {
            int i = l * 256 + tid;
            int k = i & 15, m = i >> 4;
            As[k * 128 + m] = __half2float(A[(size_t)(bmr + m) * K + k0 + k]);
        }
        #pragma unroll
        for (int l = 0; l < 16; l++) {
            int i = l * 256 + tid;
            int k = i & 15, n = i >> 4;
            size_t off = (size_t)(bn + n) * K + k0 + k;
            Bs[k * 256 + n] = __half2float(Bhi[off]);
        }
        __syncthreads();
        #pragma unroll
        for (int kk = 0; kk < 16; kk++) {
            float a[8], b[16];
            #pragma unroll
            for (int i = 0; i < 8; i++) a[i] = As[kk * 128 + ty * 8 + i];
            #pragma unroll
            for (int j = 0; j < 16; j++) b[j] = Bs[kk * 256 + tx * 16 + j];
            #pragma unroll
            for (int i = 0; i < 8; i++)
                #pragma unroll
                for (int j = 0; j < 16; j++) acc[i][j] += a[i] * b[j];
        }
        __syncthreads();
    }
    #pragma unroll
    for (int i = 0; i < 8; i++) {
        size_t off = (size_t)(bmr + ty * 8 + i) * Nn + bn + tx * 16;
        #pragma unroll
        for (int j = 0; j < 16; j += 4)
            *(float4*)&C[off + j] = make_float4(acc[i][j], acc[i][j + 1],
                                                acc[i][j + 2], acc[i][j + 3]);
    }
#endif
}

// ============ Phase A: kvblkT (tensor, fp16 2-term; V single) ===============
__global__ __launch_bounds__(256, 1) void kvblkT_kernel() {
#if HAS_TCGEN05
    extern __shared__ char smem[];
    uint32_t sb = smem_to_u32(smem);
    int tid = threadIdx.x;
    int h = blockIdx.x & 15, c = blockIdx.x >> 4;
    float s = g_slopes[h];
    float* decay_tab = (float*)(smem + 16);
    const int STG = 2048;
    const int KTHI = STG + 67584;
    const int KTLO = KTHI + 32768;
    const int VTHI = KTLO + 32768;
    uint32_t mb = sb + 8;
    if (tid < 32) TCGEN05_ALLOC(sb, 128);
    if (tid == 0) MBARRIER_INIT(mb, 1);
    for (int i = tid; i < 257; i += 256) decay_tab[i] = expf(-s * (float)i);
    __syncthreads();
    uint32_t tmem;
    asm volatile("ld.shared.b32 %0, [%1];" : "=r"(tmem) : "r"(sb));
    if (tid < 32) TCGEN05_RELINQ();
    float* stg = (float*)(smem + STG);
    const uint32_t IDESC128F = (1u << 4) | (16u << 17) | (8u << 24);

    for (int half = 0; half < 2; half++) {
        if (half == 1) MBARRIER_WAIT_PARITY(mb, 0);
        const float* kb = g_qkv + (size_t)(c * 256 + half * 128) * QKVW + 2048 + (size_t)h * DH;
        #pragma unroll
        for (int it = 0; it < 16; it++) {
            int j = it * 256 + tid;
            int r = j >> 5, dq = (j & 31) << 2;
            *(float4*)&stg[r * 132 + dq] = *(const float4*)&kb[(size_t)r * QKVW + dq];
        }
        __syncthreads();
        #pragma unroll
        for (int it = 0; it < 8; it++) {
            int t = it * 256 + tid;
            int d = t & 127, g = t >> 7;
            uint32_t hp[4], lp[4];
            #pragma unroll
            for (int jj = 0; jj < 4; jj++) {
                int n0 = g * 8 + jj * 2;
                float v0 = stg[n0 * 132 + d]       * decay_tab[255 - (half * 128 + n0)];
                float v1 = stg[(n0 + 1) * 132 + d] * decay_tab[255 - (half * 128 + n0 + 1)];
                __half h0 = __float2half_rn(v0), h1 = __float2half_rn(v1);
                hp[jj] = pkh(h0, h1);
                lp[jj] = pkh(__float2half_rn(v0 - __half2float(h0)),
                             __float2half_rn(v1 - __half2float(h1)));
            }
            uint32_t o = bswz(d, g * 8, 16);
            *(uint4*)(smem + KTHI + o) = make_uint4(hp[0], hp[1], hp[2], hp[3]);
            *(uint4*)(smem + KTLO + o) = make_uint4(lp[0], lp[1], lp[2], lp[3]);
        }
        __syncthreads();
        const float* vb = g_qkv + (size_t)(c * 256 + half * 128) * QKVW + 4096 + (size_t)h * DH;
        #pragma unroll
        for (int it = 0; it < 16; it++) {
            int j = it * 256 + tid;
            int r = j >> 5, dq = (j & 31) << 2;
            *(float4*)&stg[r * 132 + dq] = *(const float4*)&vb[(size_t)r * QKVW + dq];
        }
        __syncthreads();
        #pragma unroll
        for (int it = 0; it < 8; it++) {
            int t = it * 256 + tid;
            int d = t & 127, g = t >> 7;
            uint32_t hp[4];
            #pragma unroll
            for (int jj = 0; jj < 4; jj++) {
                int n0 = g * 8 + jj * 2;
                hp[jj] = pkh(__float2half_rn(stg[n0 * 132 + d]),
                             __float2half_rn(stg[(n0 + 1) * 132 + d]));
            }
            uint32_t o = bswz(d, g * 8, 16);
            *(uint4*)(smem + VTHI + o) = make_uint4(hp[0], hp[1], hp[2], hp[3]);
        }
        __syncthreads();
        {
            uint4* dh = (uint4*)(g_vThi + ((size_t)(h * 32 + c)) * 32768 + half * 16384);
            const uint4* sh = (const uint4*)(smem + VTHI);
            #pragma unroll
            for (int it = 0; it < 8; it++) {
                int j = it * 256 + tid;
                dh[j] = sh[j];
            }
        }
        FENCE_ASYNC_SHARED();
        __syncthreads();
        if (tid < 32) {
            uint64_t dVh = MAKE_SMEM_DESC(sb + VTHI);
            uint64_t dKh = MAKE_SMEM_DESC(sb + KTHI), dKl = MAKE_SMEM_DESC(sb + KTLO);
            if (elect_one_pred()) {
                #pragma unroll
                for (int st = 0; st < 8; st++) {
                    uint32_t u = ((st >> 2) << 10) + ((st & 3) << 1);
                    bool first = (half == 0 && st == 0);
                    mma_f16_ss(tmem, dVh + u, dKh + u, IDESC128F, !first);
                    mma_f16_ss(tmem, dVh + u, dKl + u, IDESC128F, true);
                }
                TCGEN05_COMMIT(mb);
            }
        }
    }
    MBARRIER_WAIT_PARITY(mb, 1);
    TCGEN05_FENCE_AFTER();
    __syncthreads();
    if (tid < 128) {
        int w = tid >> 5, l = tid & 31, e = w * 32 + l;
        float* dst = g_kvblk + ((size_t)(h * 32 + c)) * 16384 + (size_t)e * 128;
        #pragma unroll
        for (int cb = 0; cb < 4; cb++) {
            uint32_t r[32];
            TCGEN05_LD_X32(r, tmem + cb * 32);
            TCGEN05_WAIT_LD();
            #pragma unroll
            for (int j = 0; j < 32; j += 4)
                *(float4*)&dst[cb * 32 + j] = make_float4(
                    __uint_as_float(r[j]), __uint_as_float(r[j + 1]),
                    __uint_as_float(r[j + 2]), __uint_as_float(r[j + 3]));
        }
    }
    __syncthreads();
    if (tid < 32) TCGEN05_DEALLOC(tmem, 128);
#else
    int h = blockIdx.x & 15, c = blockIdx.x >> 4;
    float s = g_slopes[h];
    for (int idx = threadIdx.x; idx < 16384; idx += 256) {
        int e = idx >> 7, d = idx & 127;
        float acc = 0.f;
        for (int n = 0; n < 256; n++) {
            size_t t = (size_t)(c * 256 + n) * QKVW + (size_t)h * DH;
            acc += expf(-s * (float)(255 - n)) * g_qkv[t + 2048 + d] * g_qkv[t + 4096 + e];
        }
        g_kvblk[((size_t)(h * 32 + c)) * 16384 + (size_t)e * 128 + d] = acc;
    }
#endif
}

// ============ Phase B: decay scan — 256 CTAs ================================
__global__ void kvscan_kernel() {
    int h = blockIdx.x >> 4;
    int seg = blockIdx.x & 15;
    float bdec = expf(-g_slopes[h] * 256.0f);
    int e = seg * 1024 + threadIdx.x;
    #pragma unroll
    for (int r = 0; r < 4; r++, e += 256) {
        float acc = 0.f;
        size_t base = (size_t)h * NCHUNK * 16384 + e;
        #pragma unroll
        for (int c = 0; c < NCHUNK; c++) {
            g_kvstate[base + (size_t)c * 16384] = acc;
            acc = bdec * acc + g_kvblk[base + (size_t)c * 16384];
        }
    }
}

// ============ Phase C: attention (single O accumulator, 2 CTAs/SM) ==========
__global__ __launch_bounds__(256, 2) void attn_tensor_kernel() {
#if HAS_TCGEN05
    extern __shared__ char smem[];
    uint32_t sb = smem_to_u32(smem);
    int tid = threadIdx.x;
    int mi = blockIdx.x & 1, c = (blockIdx.x >> 1) & 31, h = blockIdx.x >> 6;
    float s = g_slopes[h];
    float* decay_tab = (float*)(smem + 16);
    const int QH   = 2048;
    const int KHI  = 34816, KLO = 51200;
    const int VH   = 67584;
    const int SH   = 83968;
    const int KVHI = 34816, KVLO = 67584;
    uint32_t mb = sb + 8;
    if (tid < 32) TCGEN05_ALLOC(sb, 256);
    if (tid == 0) MBARRIER_INIT(mb, 1);
    for (int i = tid; i < 257; i += 256) decay_tab[i] = expf(-s * (float)i);
    __syncthreads();
    uint32_t tmem;
    asm volatile("ld.shared.b32 %0, [%1];" : "=r"(tmem) : "r"(sb));
    if (tid < 32) TCGEN05_RELINQ();
    const uint32_t OT = tmem, ST = tmem + 128;
    const uint32_t IDESC128F = (1u << 4) | (16u << 17) | (8u << 24);
    const uint32_t IDESC64F  = (1u << 4) | (8u  << 17) | (8u << 24);

    const float* qb = g_qkv + (size_t)(c * 256 + mi * 128) * QKVW + (size_t)h * DH;
    #pragma unroll
    for (int it = 0; it < 16; it++) {
        int j = it * 256 + tid;
        int r = j >> 5, dq = (j & 31) << 2;
        float4 v = *(const float4*)&qb[(size_t)r * QKVW + dq];
        uint32_t o = bswz(r, dq, 16);
        *(uint2*)(smem + QH + o) = make_uint2(
            pkh(__float2half_rn(v.x), __float2half_rn(v.y)),
            pkh(__float2half_rn(v.z), __float2half_rn(v.w)));
    }
    int ph = 0;
    const int nch = 2 * mi + 2;
    for (int cn = 0; cn < nch; cn++) {
        const float* kb = g_qkv + (size_t)(c * 256 + cn * 64) * QKVW + 2048 + (size_t)h * DH;
        #pragma unroll
        for (int it = 0; it < 8; it++) {
            int j = it * 256 + tid;
            int r = j >> 5, dq = (j & 31) << 2;
            float4 v = *(const float4*)&kb[(size_t)r * QKVW + dq];
            __half h0 = __float2half_rn(v.x), h1 = __float2half_rn(v.y);
            __half h2 = __float2half_rn(v.z), h3 = __float2half_rn(v.w);
            uint32_t o = bswz(r, dq, 8);
            *(uint2*)(smem + KHI + o) = make_uint2(pkh(h0, h1), pkh(h2, h3));
            *(uint2*)(smem + KLO + o) = make_uint2(
                pkh(__float2half_rn(v.x - __half2float(h0)), __float2half_rn(v.y - __half2float(h1))),
                pkh(__float2half_rn(v.z - __half2float(h2)), __float2half_rn(v.w - __half2float(h3))));
        }
        {
            const uint4* sh = (const uint4*)(g_vThi + (size_t)(h * 32 + c) * 32768 + cn * 8192);
            uint4* dh = (uint4*)(smem + VH);
            #pragma unroll
            for (int it = 0; it < 4; it++) {
                int j = it * 256 + tid;
                dh[j] = sh[j];
            }
        }
        FENCE_ASYNC_SHARED();
        __syncthreads();
        if (tid < 32) {
            uint64_t dQ = MAKE_SMEM_DESC(sb + QH);
            uint64_t dKh = MAKE_SMEM_DESC(sb + KHI), dKl = MAKE_SMEM_DESC(sb + KLO);
            if (elect_one_pred()) {
                #pragma unroll
                for (int st = 0; st < 8; st++) {
                    uint32_t uq = ((st >> 2) << 10) + ((st & 3) << 1);
                    uint32_t uk = ((st >> 2) << 9) + ((st & 3) << 1);
                    mma_f16_ss(ST, dQ + uq, dKh + uk, IDESC64F, st != 0);
                    mma_f16_ss(ST, dQ + uq, dKl + uk, IDESC64F, true);
                }
                TCGEN05_COMMIT(mb);
            }
        }
        MBARRIER_WAIT_PARITY(mb, ph & 1); ph++;
        TCGEN05_FENCE_AFTER();
        if (tid < 128) {
            int w = tid >> 5, l = tid & 31, m = w * 32 + l;
            int gm = mi * 128 + m;
            uint32_t r0[32], r1[32];
            TCGEN05_LD_X32(r0, ST);
            TCGEN05_WAIT_LD();
            TCGEN05_LD_X32(r1, ST + 32);
            TCGEN05_WAIT_LD();
            #pragma unroll
            for (int g = 0; g < 8; g++) {
                uint32_t hp[4];
                #pragma unroll
                for (int jj = 0; jj < 4; jj++) {
                    int j0 = g * 8 + jj * 2;
                    float v0 = __uint_as_float(j0 < 32 ? r0[j0] : r1[j0 - 32]);
                    float v1 = __uint_as_float((j0 + 1) < 32 ? r0[j0 + 1] : r1[j0 - 31]);
                    int gn0 = cn * 64 + j0;
                    v0 = (gm >= gn0)     ? v0 * decay_tab[gm - gn0]     : 0.f;
                    v1 = (gm >= gn0 + 1) ? v1 * decay_tab[gm - gn0 - 1] : 0.f;
                    hp[jj] = pkh(__float2half_rn(v0), __float2half_rn(v1));
                }
                uint32_t o = bswz(m, g * 8, 16);
                *(uint4*)(smem + SH + o) = make_uint4(hp[0], hp[1], hp[2], hp[3]);
            }
        }
        FENCE_ASYNC_SHARED();
        __syncthreads();
        if (tid < 32) {
            uint64_t dS = MAKE_SMEM_DESC(sb + SH);
            uint64_t dV = MAKE_SMEM_DESC(sb + VH);
            if (elect_one_pred()) {
                #pragma unroll
                for (int st = 0; st < 4; st++) {
                    uint32_t u = (uint32_t)st << 1;
                    bool first = (cn == 0 && st == 0);
                    mma_f16_ss(OT, dS + u, dV + u, IDESC128F, !first);
                }
                TCGEN05_COMMIT(mb);
            }
        }
        MBARRIER_WAIT_PARITY(mb, ph & 1); ph++;
    }
    // ---- final: O += (qd·q)·kvstT ----
    {
        #pragma unroll
        for (int it = 0; it < 16; it++) {
            int j = it * 256 + tid;
            int r = j >> 5, dq = (j & 31) << 2;
            float qd = decay_tab[mi * 128 + r + 1];
            float4 v = *(const float4*)&qb[(size_t)r * QKVW + dq];
            uint32_t o = bswz(r, dq, 16);
            *(uint2*)(smem + QH + o) = make_uint2(
                pkh(__float2half_rn(v.x * qd), __float2half_rn(v.y * qd)),
                pkh(__float2half_rn(v.z * qd), __float2half_rn(v.w * qd)));
        }
        const float* kvb = g_kvstate + (size_t)(h * 32 + c) * 16384;
        #pragma unroll
        for (int it = 0; it < 16; it++) {
            int j = it * 256 + tid;
            int r = j >> 5, dq = (j & 31) << 2;
            float4 v = *(const float4*)&kvb[(size_t)r * 128 + dq];
            __half h0 = __float2half_rn(v.x), h1 = __float2half_rn(v.y);
            __half h2 = __float2half_rn(v.z), h3 = __float2half_rn(v.w);
            uint32_t o = bswz(r, dq, 16);
            *(uint2*)(smem + KVHI + o) = make_uint2(pkh(h0, h1), pkh(h2, h3));
            *(uint2*)(smem + KVLO + o) = make_uint2(
                pkh(__float2half_rn(v.x - __half2float(h0)), __float2half_rn(v.y - __half2float(h1))),
                pkh(__float2half_rn(v.z - __half2float(h2)), __float2half_rn(v.w - __half2float(h3))));
        }
        FENCE_ASYNC_SHARED();
        __syncthreads();
        if (tid < 32) {
            uint64_t dQ = MAKE_SMEM_DESC(sb + QH);
            uint64_t dKh = MAKE_SMEM_DESC(sb + KVHI), dKl = MAKE_SMEM_DESC(sb + KVLO);
            if (elect_one_pred()) {
                #pragma unroll
                for (int st = 0; st < 8; st++) {
                    uint32_t u = ((st >> 2) << 10) + ((st & 3) << 1);
                    mma_f16_ss(OT, dQ + u, dKh + u, IDESC128F, true);
                    mma_f16_ss(OT, dQ + u, dKl + u, IDESC128F, true);
                }
                TCGEN05_COMMIT(mb);
            }
        }
        MBARRIER_WAIT_PARITY(mb, ph & 1); ph++;
    }
    TCGEN05_FENCE_AFTER();
    if (tid < 128) {
        int w = tid >> 5, l = tid & 31, m = w * 32 + l;
        int gm = mi * 128 + m;
        float* dst = g_attn + (size_t)(c * 256 + gm) * HIDDEN + (size_t)h * DH;
        #pragma unroll
        for (int cb = 0; cb < 4; cb++) {
            uint32_t a[32];
            TCGEN05_LD_X32(a, OT + cb * 32);
            TCGEN05_WAIT_LD();
            #pragma unroll
            for (int j = 0; j < 32; j += 4)
                *(float4*)&dst[cb * 32 + j] = make_float4(
                    __uint_as_float(a[j]),     __uint_as_float(a[j + 1]),
                    __uint_as_float(a[j + 2]), __uint_as_float(a[j + 3]));
        }
    }
    __syncthreads();
    if (tid < 32) TCGEN05_DEALLOC(tmem, 256);
#else
    int mi = blockIdx.x & 1, c = (blockIdx.x >> 1) & 31, h = blockIdx.x >> 6;
    float s = g_slopes[h];
    const float* kvst = g_kvstate + (size_t)(h * 32 + c) * 16384;
    for (int idx = threadIdx.x; idx < 16384; idx += 256) {
        int m = idx >> 7, e = idx & 127;
        int gm = mi * 128 + m;
        size_t tq = (size_t)(c * 256 + gm) * QKVW + (size_t)h * DH;
        float o = 0.f;
        for (int d = 0; d < 128; d++) o += g_qkv[tq + d] * kvst[(size_t)e * 128 + d];
        o *= expf(-s * (float)(gm + 1));
        for (int n = 0; n <= gm; n++) {
            size_t tk = (size_t)(c * 256 + n) * QKVW + (size_t)h * DH;
            float qk = 0.f;
            for (int d = 0; d < 128; d++) qk += g_qkv[tq + d] * g_qkv[tk + 2048 + d];
            o += expf(-s * (float)(gm - n)) * qk * g_qkv[tk + 4096 + e];
        }
        g_attn[(size_t)(c * 256 + gm) * HIDDEN + (size_t)h * DH + e] = o;
    }
#endif
}

// ============ RMS norm + sigmoid gate -> fp16 output ========================
__global__ void rmsgate_kernel(const float* __restrict__ gnw) {
    int t = blockIdx.x;
    int tid = threadIdx.x;
    const float* a = g_attn + (size_t)t * HIDDEN;
    const float* g = g_gate + (size_t)t * HIDDEN;
    float ss = 0.f;
    for (int j = tid; j < HIDDEN; j += 256) { float v = a[j]; ss += v * v; }
    #pragma unroll
    for (int o = 16; o; o >>= 1) ss += __shfl_xor_sync(0xffffffffu, ss, o);
    __shared__ float red[8];
    __shared__ float tot;
    if ((tid & 31) == 0) red[tid >> 5] = ss;
    __syncthreads();
    if (tid == 0) {
        float tsum = 0.f;
        #pragma unroll
        for (int w = 0; w < 8; w++) tsum += red[w];
        tot = tsum;
    }
    __syncthreads();
    float rms = rsqrtf(tot * (1.0f / HIDDEN) + 1e-5f);
    for (int j = tid; j < HIDDEN; j += 256) {
        float gv = g[j];
        float sig = 1.0f / (1.0f + expf(-gv));
        float val = a[j] * rms * gnw[j] * sig;
        g_yh[(size_t)t * HIDDEN + j] = __float2half_rn(val);
    }
}

// ================= launch =====================================================
extern "C" void kernel_launch(void* const* d_in, const int* in_sizes, int n_in,
                              void* d_out, int out_size) {
    const float* hidden    = (const float*)d_in[0];
    const int*   positions = (const int*)d_in[1];
    const float* Wqkv      = (const float*)d_in[2];
    const float* Wg        = (const float*)d_in[3];
    const float* Wd        = (const float*)d_in[4];
    const float* gnw       = (const float*)d_in[5];
    float* out = (float*)d_out;

    void *ah_p, *yh_p;
    void *bqh_p, *bgh_p, *bdh_p;
    cudaGetSymbolAddress(&ah_p, g_ah);
    cudaGetSymbolAddress(&yh_p, g_yh);
    cudaGetSymbolAddress(&bqh_p, g_bqkv_hi);
    cudaGetSymbolAddress(&bgh_p, g_bg_hi);
    cudaGetSymbolAddress(&bdh_p, g_bd_hi);

    cudaFuncSetAttribute(gemm_qkvgate, cudaFuncAttributeMaxDynamicSharedMemorySize, CG2_SMEM);
    cudaFuncSetAttribute(gemm_down, cudaFuncAttributeMaxDynamicSharedMemorySize, CG2_SMEM);
    const int kvblk_smem = 2048 + 67584 + 3 * 32768;   // 167936
    cudaFuncSetAttribute(kvblkT_kernel, cudaFuncAttributeMaxDynamicSharedMemorySize, kvblk_smem);
    const int attn_smem = 100352;                      // 98 KB -> 2 CTAs/SM
    cudaFuncSetAttribute(attn_tensor_kernel, cudaFuncAttributeMaxDynamicSharedMemorySize, attn_smem);

    init_tables<<<1, 64>>>();
    conv_act<<<(NTOK * HIDDEN / 4 + 255) / 256, 256>>>(hidden, (__half*)ah_p,
                                                       NTOK * HIDDEN / 4);
    transposeW<<<dim3(QKVW / 32, HIDDEN / 32), 256>>>(Wqkv, (__half*)bqh_p, HIDDEN, QKVW);
    transposeW<<<dim3(HIDDEN / 32, HIDDEN / 32), 256>>>(Wg, (__half*)bgh_p, HIDDEN, HIDDEN);
    transposeW<<<dim3(HIDDEN / 32, HIDDEN / 32), 256>>>(Wd, (__half*)bdh_p, HIDDEN, HIDDEN);
    gemm_qkvgate<<<dim3(((QKVW + HIDDEN) / 256) * 2, NTOK / 256), 256, CG2_SMEM>>>(
        (const __half*)ah_p, positions);
    kvblkT_kernel<<<HEADS * NCHUNK, 256, kvblk_smem>>>();
    kvscan_kernel<<<HEADS * 16, 256>>>();
    attn_tensor_kernel<<<HEADS * NCHUNK * 2, 256, attn_smem>>>();
    rmsgate_kernel<<<NTOK, 256>>>(gnw);
    gemm_down<<<dim3((HIDDEN / 256) * 2, NTOK / 256), 256, CG2_SMEM>>>(
        (const __half*)yh_p, (const __half*)bdh_p,
        out, HIDDEN, HIDDEN);
}

// round 16
// speedup vs baseline: 1.3333x; 1.0264x over previous
#include <cuda_runtime.h>
#include <cuda_bf16.h>
#include <cuda_fp16.h>
#include <math.h>
#include <cstdint>

#define NTOK 8192
#define HIDDEN 2048
#define HEADS 16
#define DH 128
#define BLK 256
#define NCHUNK 32
#define QKVW 6144

#if defined(__CUDA_ARCH_FEAT_SM103_ALL) || \
    (defined(__CUDA_ARCH_SPECIFIC__) && (__CUDA_ARCH_SPECIFIC__ == 1030)) || \
    (defined(__CUDA_ARCH_FAMILY_SPECIFIC__) && (__CUDA_ARCH_FAMILY_SPECIFIC__ == 1030))
#define HAS_TCGEN05 1
#else
#define HAS_TCGEN05 0
#endif

// ================= PTX helpers ==============================================
__device__ __forceinline__ uint32_t elect_one_pred() {
    uint32_t pred;
    asm volatile("{\n\t.reg .pred p;\n\telect.sync _|p, 0xFFFFFFFF;\n\t"
                 "selp.b32 %0, 1, 0, p;\n\t}" : "=r"(pred));
    return pred;
}
__device__ __forceinline__ uint32_t smem_to_u32(const void* p) {
    uint32_t a;
    asm("{ .reg .u64 t; cvta.to.shared.u64 t, %1; cvt.u32.u64 %0, t; }"
        : "=r"(a) : "l"(p));
    return a;
}
__device__ __forceinline__ uint32_t cluster_rank() {
    uint32_t r;
    asm("mov.u32 %0, %%cluster_ctarank;" : "=r"(r));
    return r;
}
#define CLUSTER_SYNC() do { \
    asm volatile("barrier.cluster.arrive.aligned;" ::: "memory"); \
    asm volatile("barrier.cluster.wait.aligned;" ::: "memory"); \
} while (0)
#define MBARRIER_INIT(addr, cnt) \
    asm volatile("mbarrier.init.shared.b64 [%0], %1;" :: "r"((uint32_t)(addr)), "r"((uint32_t)(cnt)) : "memory")
#define MBARRIER_WAIT_PARITY(addr, par) do { \
    uint32_t _m = (uint32_t)(addr); uint32_t _p = (uint32_t)(par); uint32_t _d; \
    asm volatile("{\n\t.reg .pred p;\n\t" \
        "mbarrier.try_wait.parity.acquire.cta.shared::cta.b64 p, [%1], %2;\n\t" \
        "selp.b32 %0, 1, 0, p;\n\t}" : "=r"(_d) : "r"(_m), "r"(_p) : "memory"); \
    if (!_d) { \
        asm volatile("{\n\t.reg .pred P1;\n\t" \
            "WL_%=:\n\t" \
            "mbarrier.try_wait.parity.acquire.cta.shared::cta.b64 P1, [%0], %1, 0x989680;\n\t" \
            "@P1 bra.uni WD_%=;\n\tbra.uni WL_%=;\n\tWD_%=:\n\t}" \
            :: "r"(_m), "r"(_p) : "memory"); \
    } } while (0)
#define MBARRIER_WAIT_PARITY_CL(addr, par) do { \
    uint32_t _m = (uint32_t)(addr); uint32_t _p = (uint32_t)(par); uint32_t _d; \
    asm volatile("{\n\t.reg .pred p;\n\t" \
        "mbarrier.try_wait.parity.acquire.cluster.shared::cta.b64 p, [%1], %2;\n\t" \
        "selp.b32 %0, 1, 0, p;\n\t}" : "=r"(_d) : "r"(_m), "r"(_p) : "memory"); \
    if (!_d) { \
        asm volatile("{\n\t.reg .pred P1;\n\t" \
            "WL_%=:\n\t" \
            "mbarrier.try_wait.parity.acquire.cluster.shared::cta.b64 P1, [%0], %1, 0x989680;\n\t" \
            "@P1 bra.uni WD_%=;\n\tbra.uni WL_%=;\n\tWD_%=:\n\t}" \
            :: "r"(_m), "r"(_p) : "memory"); \
    } } while (0)
#define MBARRIER_ARRIVE_CLUSTER(local_addr, target_rank) \
    asm volatile( \
        "{\n\t.reg .b32 remAddr32;\n\t" \
        "mapa.shared::cluster.u32 remAddr32, %0, %1;\n\t" \
        "mbarrier.arrive.release.cluster.shared::cluster.b64 _, [remAddr32];\n\t}" \
        :: "r"((uint32_t)(local_addr)), "r"((uint32_t)(target_rank)) : "memory")
#define TCGEN05_ALLOC(smem_addr, n) \
    asm volatile("tcgen05.alloc.cta_group::1.sync.aligned.shared::cta.b32 [%0], %1;" \
        :: "r"((uint32_t)(smem_addr)), "r"((uint32_t)(n)) : "memory")
#define TCGEN05_DEALLOC(tmem, n) \
    asm volatile("tcgen05.dealloc.cta_group::1.sync.aligned.b32 %0, %1;" :: "r"(tmem), "r"((uint32_t)(n)))
#define TCGEN05_RELINQ() \
    asm volatile("tcgen05.relinquish_alloc_permit.cta_group::1.sync.aligned;")
#define TCGEN05_ALLOC_CG2(smem_addr, n) \
    asm volatile("tcgen05.alloc.cta_group::2.sync.aligned.shared::cta.b32 [%0], %1;" \
        :: "r"((uint32_t)(smem_addr)), "r"((uint32_t)(n)) : "memory")
#define TCGEN05_DEALLOC_CG2(tmem, n) \
    asm volatile("tcgen05.dealloc.cta_group::2.sync.aligned.b32 %0, %1;" :: "r"(tmem), "r"((uint32_t)(n)))
#define TCGEN05_RELINQ_CG2() \
    asm volatile("tcgen05.relinquish_alloc_permit.cta_group::2.sync.aligned;")
#define TCGEN05_COMMIT(mbar) \
    asm volatile("tcgen05.commit.cta_group::1.mbarrier::arrive::one.shared::cluster.b64 [%0];" \
        :: "r"((uint32_t)(mbar)) : "memory")
#define TCGEN05_COMMIT_MC_CG2(mbar, mask) \
    asm volatile("tcgen05.commit.cta_group::2.mbarrier::arrive::one.shared::cluster.multicast::cluster.b64 [%0], %1;" \
        :: "r"((uint32_t)(mbar)), "h"((uint16_t)(mask)) : "memory")
#define TCGEN05_FENCE_AFTER() asm volatile("tcgen05.fence::after_thread_sync;" ::: "memory")
#define TCGEN05_WAIT_LD() asm volatile("tcgen05.wait::ld.sync.aligned;" ::: "memory")
#define FENCE_ASYNC_SHARED() asm volatile("fence.proxy.async.shared::cta;" ::: "memory")
#define TCGEN05_LD_X32(r, addr) \
    asm volatile("tcgen05.ld.sync.aligned.32x32b.x32.b32 " \
        "{%0, %1, %2, %3, %4, %5, %6, %7, %8, %9, %10, %11, %12, %13, %14, %15, " \
        " %16, %17, %18, %19, %20, %21, %22, %23, %24, %25, %26, %27, %28, %29, %30, %31}, [%32];" \
        : "=r"((r)[0]),  "=r"((r)[1]),  "=r"((r)[2]),  "=r"((r)[3]), \
          "=r"((r)[4]),  "=r"((r)[5]),  "=r"((r)[6]),  "=r"((r)[7]), \
          "=r"((r)[8]),  "=r"((r)[9]),  "=r"((r)[10]), "=r"((r)[11]), \
          "=r"((r)[12]), "=r"((r)[13]), "=r"((r)[14]), "=r"((r)[15]), \
          "=r"((r)[16]), "=r"((r)[17]), "=r"((r)[18]), "=r"((r)[19]), \
          "=r"((r)[20]), "=r"((r)[21]), "=r"((r)[22]), "=r"((r)[23]), \
          "=r"((r)[24]), "=r"((r)[25]), "=r"((r)[26]), "=r"((r)[27]), \
          "=r"((r)[28]), "=r"((r)[29]), "=r"((r)[30]), "=r"((r)[31]) \
        : "r"(addr))

static constexpr uint64_t SMEM_DESC_BASE_SW128 =
    (uint64_t(2) << 61) | (uint64_t(1) << 46) | (uint64_t(64) << 32) | (uint64_t(1) << 16);
#define MAKE_SMEM_DESC(a) (SMEM_DESC_BASE_SW128 | ((uint64_t)((a) >> 4) & 0x3FFF))

#if HAS_TCGEN05
__device__ __forceinline__ void mma_f16_ss(uint32_t d_tmem, uint64_t a_desc,
                                           uint64_t b_desc, uint32_t idesc, bool acc) {
    uint32_t en = acc ? 1u : 0u;
    asm volatile(
        "{\n\t.reg .pred p;\n\tsetp.ne.u32 p, %5, 0;\n\t"
        "tcgen05.mma.cta_group::1.kind::f16 [%0], %1, %2, %3, {%4, %4, %4, %4}, p;\n\t}"
        :: "r"(d_tmem), "l"(a_desc), "l"(b_desc), "r"(idesc), "r"(0u), "r"(en)
        : "memory");
}
__device__ __forceinline__ void mma_f16_ss_cg2(uint32_t d_tmem, uint64_t a_desc,
                                               uint64_t b_desc, uint32_t idesc, bool acc) {
    uint32_t en = acc ? 1u : 0u;
    asm volatile(
        "{\n\t.reg .pred p;\n\tsetp.ne.u32 p, %5, 0;\n\t"
        "tcgen05.mma.cta_group::2.kind::f16 [%0], %1, %2, %3, "
        "{%4, %4, %4, %4, %4, %4, %4, %4}, p;\n\t}"
        :: "r"(d_tmem), "l"(a_desc), "l"(b_desc), "r"(idesc), "r"(0u), "r"(en)
        : "memory");
}
#endif

__device__ __forceinline__ uint32_t bswz(int row, int col, int atomrows) {
    uint32_t off = (uint32_t)(((row >> 3) + (col >> 6) * atomrows) << 10)
                 + ((row & 7) << 7) + ((col & 63) << 1);
    return off ^ ((off >> 3) & 0x70);
}
__device__ __forceinline__ uint32_t pkh(__half a, __half b) {
    __half2 t{a, b};
    return *(uint32_t*)&t;
}

// ================= scratch ===================================================
__device__ float g_qkv[(size_t)NTOK * QKVW];
__device__ float g_gate[(size_t)NTOK * HIDDEN];
__device__ float g_attn[(size_t)NTOK * HIDDEN];
__device__ float g_kvblk[(size_t)HEADS * NCHUNK * DH * DH];
__device__ float g_kvstate[(size_t)HEADS * NCHUNK * DH * DH];
__device__ float g_invf[64];
__device__ float g_slopes[HEADS];
__device__ __half g_vThi[(size_t)HEADS * NCHUNK * 32768];
__device__ __half g_ah[(size_t)NTOK * HIDDEN];
__device__ __half g_yh[(size_t)NTOK * HIDDEN];
__device__ __half g_bqkv_hi[(size_t)QKVW * HIDDEN];
__device__ __half g_bg_hi[(size_t)HIDDEN * HIDDEN];
__device__ __half g_bd_hi[(size_t)HIDDEN * HIDDEN];

// ================= init tables ================================================
__global__ void init_tables() {
    int t = threadIdx.x;
    if (t < 64) g_invf[t] = (float)pow(600000.0, -(double)t / 64.0);
    if (t < HEADS) {
        double start = pow(2.0, -pow(2.0, -(log2(16.0) - 3.0)));
        g_slopes[t] = (float)(start * pow(start, (double)t) * (1.0 + 1e-5));
    }
}

// ================= convert fp32 -> fp16 (A operand, single) =================
__global__ void conv_act(const float* __restrict__ x, __half* __restrict__ h, int n4) {
    int i = blockIdx.x * blockDim.x + threadIdx.x;
    if (i >= n4) return;
    float4 v = ((const float4*)x)[i];
    __half2 a{__float2half_rn(v.x), __float2half_rn(v.y)};
    __half2 b{__float2half_rn(v.z), __float2half_rn(v.w)};
    ((__half2*)h)[i * 2]     = a;
    ((__half2*)h)[i * 2 + 1] = b;
}

// ======= transpose W[K,N] fp32 -> Thi [N,K] fp16 (single) ===================
__global__ void transposeW(const float* __restrict__ W, __half* __restrict__ Thi,
                           int K, int N) {
    __shared__ float t[32][33];
    int n0 = blockIdx.x * 32, k0 = blockIdx.y * 32;
    int c = threadIdx.x & 31, r0 = threadIdx.x >> 5;
    #pragma unroll
    for (int rr = r0; rr < 32; rr += 8)
        t[rr][c] = W[(size_t)(k0 + rr) * N + n0 + c];
    __syncthreads();
    #pragma unroll
    for (int rr = r0; rr < 32; rr += 8)
        Thi[(size_t)(n0 + rr) * K + k0 + c] = __float2half_rn(t[c][rr]);
}

#if HAS_TCGEN05
template <int ROWS>
__device__ __forceinline__ void load_tile(char* dst, const __half* src, int ld) {
    int tid = threadIdx.x;
    #pragma unroll
    for (int l = 0; l < ROWS / 32; l++) {
        int i = l * 256 + tid;
        int r = i >> 3, sg = i & 7;
        uint4 v = *(const uint4*)(src + (size_t)r * ld + sg * 8);
        uint32_t off = (uint32_t)(r * 128 + sg * 16);
        off ^= (off >> 3) & 0x70;
        *(uint4*)(dst + off) = v;
    }
}
#endif

// ======= cg2 fp16 single-term GEMM constants (K-chunk 64) ====================
#define CG2_BUF 32768
#define CG2_SMEM (1024 + 2 * CG2_BUF)
#define IDESC_CG2 ((1u << 4) | (32u << 17) | (16u << 24))

// ======= fused qkv+gate GEMM (cg2 fp16 single-term) with RoPE epilogue =======
__global__ __launch_bounds__(256, 1) __cluster_dims__(2, 1, 1)
void gemm_qkvgate(const __half* __restrict__ A, const int* __restrict__ positions) {
    const int K = HIDDEN;
    uint32_t rank = cluster_rank();
    int bm = blockIdx.y * 256;
    int bn = (blockIdx.x >> 1) * 256;
    int gcs = bn + (int)rank * 128;
    const __half* Bhi = (gcs < QKVW) ? g_bqkv_hi + (size_t)gcs * K
                                     : g_bg_hi + (size_t)(gcs - QKVW) * K;
#if HAS_TCGEN05
    extern __shared__ char smem[];
    uint32_t sb = smem_to_u32(smem);
    int tid = threadIdx.x;
    const uint32_t dn0 = sb + 8,  dn1 = sb + 16;
    const uint32_t rd0 = sb + 24, rd1 = sb + 32;
    if (tid < 32) TCGEN05_ALLOC_CG2(sb, 256);
    if (tid == 0) {
        MBARRIER_INIT(dn0, 1); MBARRIER_INIT(dn1, 1);
        MBARRIER_INIT(rd0, 2); MBARRIER_INIT(rd1, 2);
    }
    __syncthreads();
    uint32_t tmem;
    asm volatile("ld.shared.b32 %0, [%1];" : "=r"(tmem) : "r"(sb));
    if (tid < 32) TCGEN05_RELINQ_CG2();
    CLUSTER_SYNC();

    const __half* pA = A + (size_t)(bm + rank * 128) * K;

    int phd[2] = {0, 0};
    int phr[2] = {0, 0};
    for (int ch = 0; ch < 32; ch++) {
        int b = ch & 1;
        char* st = smem + 1024 + b * CG2_BUF;
        if (ch >= 2) {
            MBARRIER_WAIT_PARITY_CL(b ? dn1 : dn0, phd[b]);
            phd[b] ^= 1;
        }
        int k0 = ch << 6;
        load_tile<128>(st,         pA + k0,  K);
        load_tile<128>(st + 16384, Bhi + k0, K);
        FENCE_ASYNC_SHARED();
        __syncthreads();
        if (tid == 0) MBARRIER_ARRIVE_CLUSTER(b ? rd1 : rd0, 0);
        if (rank == 0 && tid < 32) {
            MBARRIER_WAIT_PARITY_CL(b ? rd1 : rd0, phr[b]);
            phr[b] ^= 1;
            uint32_t sa = sb + 1024 + b * CG2_BUF;
            uint64_t dA  = MAKE_SMEM_DESC(sa);
            uint64_t dBh = MAKE_SMEM_DESC(sa + 16384);
            if (elect_one_pred()) {
                #pragma unroll
                for (int k = 0; k < 4; k++) {
                    bool first = (ch == 0) && (k == 0);
                    mma_f16_ss_cg2(tmem, dA + k * 2, dBh + k * 2, IDESC_CG2, !first);
                }
                TCGEN05_COMMIT_MC_CG2(b ? dn1 : dn0, 0x3);
            }
        }
    }
    MBARRIER_WAIT_PARITY_CL(dn0, phd[0]);
    MBARRIER_WAIT_PARITY_CL(dn1, phd[1]);
    TCGEN05_FENCE_AFTER();
    __syncthreads();

    int w = tid >> 5, l = tid & 31;
    int sub = w & 3;
    int colbase = (w >> 2) * 128;
    int row = bm + (int)rank * 128 + sub * 32 + l;
    int gc0 = bn + colbase;
    bool isQ = gc0 < 2048;
    bool isK = (gc0 >= 2048) && (gc0 < 4096);
    float* dst = (gc0 < QKVW) ? g_qkv + (size_t)row * QKVW + gc0
                              : g_gate + (size_t)row * HIDDEN + (gc0 - QKVW);
    if (isQ || isK) {
        float pos = (float)positions[row];
        float qs = isQ ? 0.08838834764831845f : 1.0f;
        #pragma unroll
        for (int half = 0; half < 2; half++) {
            uint32_t a[32], b[32];
            TCGEN05_LD_X32(a, tmem + colbase + half * 32);
            TCGEN05_WAIT_LD();
            TCGEN05_LD_X32(b, tmem + colbase + half * 32 + 64);
            TCGEN05_WAIT_LD();
            #pragma unroll
            for (int j0 = 0; j0 < 32; j0 += 4) {
                float o1[4], o2[4];
                #pragma unroll
                for (int j = 0; j < 4; j++) {
                    int jin = half * 32 + j0 + j;
                    float f = pos * g_invf[jin];
                    float sv, cv;
                    sincosf(f, &sv, &cv);
                    float x1 = __uint_as_float(a[j0 + j]);
                    float x2 = __uint_as_float(b[j0 + j]);
                    o1[j] = (x1 * cv - x2 * sv) * qs;
                    o2[j] = (x2 * cv + x1 * sv) * qs;
                }
                *(float4*)&dst[half * 32 + j0]      = make_float4(o1[0], o1[1], o1[2], o1[3]);
                *(float4*)&dst[half * 32 + 64 + j0] = make_float4(o2[0], o2[1], o2[2], o2[3]);
            }
        }
    } else {
        #pragma unroll
        for (int cb = 0; cb < 128; cb += 32) {
            uint32_t r[32];
            TCGEN05_LD_X32(r, tmem + colbase + cb);
            TCGEN05_WAIT_LD();
            #pragma unroll
            for (int j = 0; j < 32; j += 4)
                *(float4*)&dst[cb + j] = make_float4(
                    __uint_as_float(r[j]), __uint_as_float(r[j + 1]),
                    __uint_as_float(r[j + 2]), __uint_as_float(r[j + 3]));
        }
    }
    __syncthreads();
    if (tid < 32) TCGEN05_DEALLOC_CG2(tmem, 256);
    CLUSTER_SYNC();
#else
    extern __shared__ char smemraw[];
    float* As = (float*)smemraw;
    float* Bs = As + 16 * 128;
    int tid = threadIdx.x;
    int bmr = bm + (int)rank * 128;
    int ty = tid >> 4, tx = tid & 15;
    float acc[8][16];
    #pragma unroll
    for (int i = 0; i < 8; i++)
        #pragma unroll
        for (int j = 0; j < 16; j++) acc[i][j] = 0.f;
    for (int k0 = 0; k0 < K; k0 += 16) {
        #pragma unroll
        for (int l = 0; l < 8; l++) {
            int i = l * 256 + tid;
            int k = i & 15, m = i >> 4;
            As[k * 128 + m] = __half2float(A[(size_t)(bmr + m) * K + k0 + k]);
        }
        #pragma unroll
        for (int l = 0; l < 16; l++) {
            int i = l * 256 + tid;
            int k = i & 15, n = i >> 4;
            int gc = bn + n;
            const __half* bh = (gc < QKVW) ? g_bqkv_hi + (size_t)gc * K
                                           : g_bg_hi + (size_t)(gc - QKVW) * K;
            Bs[k * 256 + n] = __half2float(bh[k0 + k]);
        }
        __syncthreads();
        #pragma unroll
        for (int kk = 0; kk < 16; kk++) {
            float a[8], b[16];
            #pragma unroll
            for (int i = 0; i < 8; i++) a[i] = As[kk * 128 + ty * 8 + i];
            #pragma unroll
            for (int j = 0; j < 16; j++) b[j] = Bs[kk * 256 + tx * 16 + j];
            #pragma unroll
            for (int i = 0; i < 8; i++)
                #pragma unroll
                for (int j = 0; j < 16; j++) acc[i][j] += a[i] * b[j];
        }
        __syncthreads();
    }
    float* tileS = (float*)smemraw;
    #pragma unroll
    for (int i = 0; i < 8; i++)
        #pragma unroll
        for (int j = 0; j < 16; j++)
            tileS[(ty * 8 + i) * 257 + tx * 16 + j] = acc[i][j];
    __syncthreads();
    {
        int r = tid >> 1, sp = tid & 1;
        int row = bmr + r;
        int gc0 = bn + sp * 128;
        bool isQ = gc0 < 2048;
        bool isK = (gc0 >= 2048) && (gc0 < 4096);
        float* dst = (gc0 < QKVW) ? g_qkv + (size_t)row * QKVW + gc0
                                  : g_gate + (size_t)row * HIDDEN + (gc0 - QKVW);
        const float* src = &tileS[r * 257 + sp * 128];
        if (isQ || isK) {
            float pos = (float)positions[row];
            float qs = isQ ? 0.08838834764831845f : 1.0f;
            for (int j = 0; j < 64; j++) {
                float f = pos * g_invf[j];
                float sv, cv;
                sincosf(f, &sv, &cv);
                float x1 = src[j], x2 = src[j + 64];
                dst[j]      = (x1 * cv - x2 * sv) * qs;
                dst[j + 64] = (x2 * cv + x1 * sv) * qs;
            }
        } else {
            for (int j = 0; j < 128; j++) dst[j] = src[j];
        }
    }
#endif
}

// ============ cg2 fp16 single-term down-projection GEMM =====================
__global__ __launch_bounds__(256, 1) __cluster_dims__(2, 1, 1)
void gemm_down(const __half* __restrict__ A,
               const __half* __restrict__ Bhi,
               float* __restrict__ C, int Nn, int K) {
    uint32_t rank = cluster_rank();
    int bm = blockIdx.y * 256;
    int bn = (blockIdx.x >> 1) * 256;
#if HAS_TCGEN05
    extern __shared__ char smem[];
    uint32_t sb = smem_to_u32(smem);
    int tid = threadIdx.x;
    const uint32_t dn0 = sb + 8,  dn1 = sb + 16;
    const uint32_t rd0 = sb + 24, rd1 = sb + 32;
    if (tid < 32) TCGEN05_ALLOC_CG2(sb, 256);
    if (tid == 0) {
        MBARRIER_INIT(dn0, 1); MBARRIER_INIT(dn1, 1);
        MBARRIER_INIT(rd0, 2); MBARRIER_INIT(rd1, 2);
    }
    __syncthreads();
    uint32_t tmem;
    asm volatile("ld.shared.b32 %0, [%1];" : "=r"(tmem) : "r"(sb));
    if (tid < 32) TCGEN05_RELINQ_CG2();
    CLUSTER_SYNC();

    const __half* pA   = A   + (size_t)(bm + rank * 128) * K;
    const __half* pBhi = Bhi + (size_t)(bn + rank * 128) * K;

    int phd[2] = {0, 0};
    int phr[2] = {0, 0};
    const int nch = K >> 6;
    for (int ch = 0; ch < nch; ch++) {
        int b = ch & 1;
        char* st = smem + 1024 + b * CG2_BUF;
        if (ch >= 2) {
            MBARRIER_WAIT_PARITY_CL(b ? dn1 : dn0, phd[b]);
            phd[b] ^= 1;
        }
        int k0 = ch << 6;
        load_tile<128>(st,         pA + k0,   K);
        load_tile<128>(st + 16384, pBhi + k0, K);
        FENCE_ASYNC_SHARED();
        __syncthreads();
        if (tid == 0) MBARRIER_ARRIVE_CLUSTER(b ? rd1 : rd0, 0);
        if (rank == 0 && tid < 32) {
            MBARRIER_WAIT_PARITY_CL(b ? rd1 : rd0, phr[b]);
            phr[b] ^= 1;
            uint32_t sa = sb + 1024 + b * CG2_BUF;
            uint64_t dA  = MAKE_SMEM_DESC(sa);
            uint64_t dBh = MAKE_SMEM_DESC(sa + 16384);
            if (elect_one_pred()) {
                #pragma unroll
                for (int k = 0; k < 4; k++) {
                    bool first = (ch == 0) && (k == 0);
                    mma_f16_ss_cg2(tmem, dA + k * 2, dBh + k * 2, IDESC_CG2, !first);
                }
                TCGEN05_COMMIT_MC_CG2(b ? dn1 : dn0, 0x3);
            }
        }
    }
    MBARRIER_WAIT_PARITY_CL(dn0, phd[0]);
    MBARRIER_WAIT_PARITY_CL(dn1, phd[1]);
    TCGEN05_FENCE_AFTER();
    __syncthreads();

    int w = tid >> 5, l = tid & 31;
    int sub = w & 3;
    int colbase = (w >> 2) * 128;
    int row = bm + (int)rank * 128 + sub * 32 + l;
    float* dst_row = C + (size_t)row * Nn + bn + colbase;
    #pragma unroll
    for (int cb = 0; cb < 128; cb += 32) {
        uint32_t r[32];
        TCGEN05_LD_X32(r, tmem + colbase + cb);
        TCGEN05_WAIT_LD();
        #pragma unroll
        for (int j = 0; j < 32; j += 4)
            *(float4*)(dst_row + cb + j) = make_float4(
                __uint_as_float(r[j]), __uint_as_float(r[j + 1]),
                __uint_as_float(r[j + 2]), __uint_as_float(r[j + 3]));
    }
    __syncthreads();
    if (tid < 32) TCGEN05_DEALLOC_CG2(tmem, 256);
    CLUSTER_SYNC();
#else
    extern __shared__ char smemraw[];
    float* As = (float*)smemraw;
    float* Bs = As + 16 * 128;
    int tid = threadIdx.x;
    int bmr = bm + (int)rank * 128;
    int ty = tid >> 4, tx = tid & 15;
    float acc[8][16];
    #pragma unroll
    for (int i = 0; i < 8; i++)
        #pragma unroll
        for (int j = 0; j < 16; j++) acc[i][j] = 0.f;
    for (int k0 = 0; k0 < K; k0 += 16) {
        #pragma unroll
        for (int l = 0; l < 8; l++) {
            int i = l * 256 + tid;
            int k = i & 15, m = i >> 4;
            As[k * 128 + m] = __half2float(A[(size_t)(bmr + m) * K + k0 + k]);
        }
        #pragma unroll
        for (int l = 0; l < 16; l++) {
            int i = l * 256 + tid;
            int k = i & 15, n = i >> 4;
            size_t off = (size_t)(bn + n) * K + k0 + k;
            Bs[k * 256 + n] = __half2float(Bhi[off]);
        }
        __syncthreads();
        #pragma unroll
        for (int kk = 0; kk < 16; kk++) {
            float a[8], b[16];
            #pragma unroll
            for (int i = 0; i < 8; i++) a[i] = As[kk * 128 + ty * 8 + i];
            #pragma unroll
            for (int j = 0; j < 16; j++) b[j] = Bs[kk * 256 + tx * 16 + j];
            #pragma unroll
            for (int i = 0; i < 8; i++)
                #pragma unroll
                for (int j = 0; j < 16; j++) acc[i][j] += a[i] * b[j];
        }
        __syncthreads();
    }
    #pragma unroll
    for (int i = 0; i < 8; i++) {
        size_t off = (size_t)(bmr + ty * 8 + i) * Nn + bn + tx * 16;
        #pragma unroll
        for (int j = 0; j < 16; j += 4)
            *(float4*)&C[off + j] = make_float4(acc[i][j], acc[i][j + 1],
                                                acc[i][j + 2], acc[i][j + 3]);
    }
#endif
}

// ============ Phase A: kvblkT (fp16 single-term, 64-row staging, 2 CTA/SM) ==
__global__ __launch_bounds__(256, 2) void kvblkT_kernel() {
#if HAS_TCGEN05
    extern __shared__ char smem[];
    uint32_t sb = smem_to_u32(smem);
    int tid = threadIdx.x;
    int h = blockIdx.x & 15, c = blockIdx.x >> 4;
    float s = g_slopes[h];
    float* decay_tab = (float*)(smem + 16);
    const int STG  = 2048;                 // fp32 staging [64][132] = 33792 B
    const int KTHI = STG + 33792;          // 35840, 32KB
    const int VTHI = KTHI + 32768;         // 68608, 32KB -> total 101376 (99KB)
    uint32_t mb = sb + 8;
    if (tid < 32) TCGEN05_ALLOC(sb, 128);
    if (tid == 0) MBARRIER_INIT(mb, 1);
    for (int i = tid; i < 257; i += 256) decay_tab[i] = expf(-s * (float)i);
    __syncthreads();
    uint32_t tmem;
    asm volatile("ld.shared.b32 %0, [%1];" : "=r"(tmem) : "r"(sb));
    if (tid < 32) TCGEN05_RELINQ();
    float* stg = (float*)(smem + STG);
    const uint32_t IDESC128F = (1u << 4) | (16u << 17) | (8u << 24);

    for (int half = 0; half < 2; half++) {
        if (half == 1) MBARRIER_WAIT_PARITY(mb, 0);
        // ---- K: two 64-row subpasses (decay applied), fp16 single ----
        #pragma unroll
        for (int sub = 0; sub < 2; sub++) {
            const float* kb = g_qkv + (size_t)(c * 256 + half * 128 + sub * 64) * QKVW
                            + 2048 + (size_t)h * DH;
            #pragma unroll
            for (int it = 0; it < 8; it++) {
                int j = it * 256 + tid;
                int r = j >> 5, dq = (j & 31) << 2;
                *(float4*)&stg[r * 132 + dq] = *(const float4*)&kb[(size_t)r * QKVW + dq];
            }
            __syncthreads();
            #pragma unroll
            for (int it = 0; it < 4; it++) {
                int t = it * 256 + tid;
                int d = t & 127, g = t >> 7;           // g in 0..7
                uint32_t hp[4];
                #pragma unroll
                for (int jj = 0; jj < 4; jj++) {
                    int n0 = g * 8 + jj * 2;           // local row 0..63
                    int grow = half * 128 + sub * 64 + n0;
                    float v0 = stg[n0 * 132 + d]       * decay_tab[255 - grow];
                    float v1 = stg[(n0 + 1) * 132 + d] * decay_tab[254 - grow];
                    hp[jj] = pkh(__float2half_rn(v0), __float2half_rn(v1));
                }
                uint32_t o = bswz(d, sub * 64 + g * 8, 16);
                *(uint4*)(smem + KTHI + o) = make_uint4(hp[0], hp[1], hp[2], hp[3]);
            }
            __syncthreads();
        }
        // ---- V: two 64-row subpasses, fp16 single ----
        #pragma unroll
        for (int sub = 0; sub < 2; sub++) {
            const float* vb = g_qkv + (size_t)(c * 256 + half * 128 + sub * 64) * QKVW
                            + 4096 + (size_t)h * DH;
            #pragma unroll
            for (int it = 0; it < 8; it++) {
                int j = it * 256 + tid;
                int r = j >> 5, dq = (j & 31) << 2;
                *(float4*)&stg[r * 132 + dq] = *(const float4*)&vb[(size_t)r * QKVW + dq];
            }
            __syncthreads();
            #pragma unroll
            for (int it = 0; it < 4; it++) {
                int t = it * 256 + tid;
                int d = t & 127, g = t >> 7;
                uint32_t hp[4];
                #pragma unroll
                for (int jj = 0; jj < 4; jj++) {
                    int n0 = g * 8 + jj * 2;
                    hp[jj] = pkh(__float2half_rn(stg[n0 * 132 + d]),
                                 __float2half_rn(stg[(n0 + 1) * 132 + d]));
                }
                uint32_t o = bswz(d, sub * 64 + g * 8, 16);
                *(uint4*)(smem + VTHI + o) = make_uint4(hp[0], hp[1], hp[2], hp[3]);
            }
            __syncthreads();
        }
        // ---- persist vThi blob (32KB raw) ----
        {
            uint4* dh = (uint4*)(g_vThi + ((size_t)(h * 32 + c)) * 32768 + half * 16384);
            const uint4* sh = (const uint4*)(smem + VTHI);
            #pragma unroll
            for (int it = 0; it < 8; it++) {
                int j = it * 256 + tid;
                dh[j] = sh[j];
            }
        }
        FENCE_ASYNC_SHARED();
        __syncthreads();
        // ---- MMA: D += vThi · kThi^T (single term) ----
        if (tid < 32) {
            uint64_t dVh = MAKE_SMEM_DESC(sb + VTHI);
            uint64_t dKh = MAKE_SMEM_DESC(sb + KTHI);
            if (elect_one_pred()) {
                #pragma unroll
                for (int st = 0; st < 8; st++) {
                    uint32_t u = ((st >> 2) << 10) + ((st & 3) << 1);
                    bool first = (half == 0 && st == 0);
                    mma_f16_ss(tmem, dVh + u, dKh + u, IDESC128F, !first);
                }
                TCGEN05_COMMIT(mb);
            }
        }
    }
    MBARRIER_WAIT_PARITY(mb, 1);
    TCGEN05_FENCE_AFTER();
    __syncthreads();
    if (tid < 128) {
        int w = tid >> 5, l = tid & 31, e = w * 32 + l;
        float* dst = g_kvblk + ((size_t)(h * 32 + c)) * 16384 + (size_t)e * 128;
        #pragma unroll
        for (int cb = 0; cb < 4; cb++) {
            uint32_t r[32];
            TCGEN05_LD_X32(r, tmem + cb * 32);
            TCGEN05_WAIT_LD();
            #pragma unroll
            for (int j = 0; j < 32; j += 4)
                *(float4*)&dst[cb * 32 + j] = make_float4(
                    __uint_as_float(r[j]), __uint_as_float(r[j + 1]),
                    __uint_as_float(r[j + 2]), __uint_as_float(r[j + 3]));
        }
    }
    __syncthreads();
    if (tid < 32) TCGEN05_DEALLOC(tmem, 128);
#else
    int h = blockIdx.x & 15, c = blockIdx.x >> 4;
    float s = g_slopes[h];
    for (int idx = threadIdx.x; idx < 16384; idx += 256) {
        int e = idx >> 7, d = idx & 127;
        float acc = 0.f;
        for (int n = 0; n < 256; n++) {
            size_t t = (size_t)(c * 256 + n) * QKVW + (size_t)h * DH;
            acc += expf(-s * (float)(255 - n)) * g_qkv[t + 2048 + d] * g_qkv[t + 4096 + e];
        }
        g_kvblk[((size_t)(h * 32 + c)) * 16384 + (size_t)e * 128 + d] = acc;
    }
#endif
}

// ============ Phase B: decay scan — 256 CTAs ================================
__global__ void kvscan_kernel() {
    int h = blockIdx.x >> 4;
    int seg = blockIdx.x & 15;
    float bdec = expf(-g_slopes[h] * 256.0f);
    int e = seg * 1024 + threadIdx.x;
    #pragma unroll
    for (int r = 0; r < 4; r++, e += 256) {
        float acc = 0.f;
        size_t base = (size_t)h * NCHUNK * 16384 + e;
        #pragma unroll
        for (int c = 0; c < NCHUNK; c++) {
            g_kvstate[base + (size_t)c * 16384] = acc;
            acc = bdec * acc + g_kvblk[base + (size_t)c * 16384];
        }
    }
}

// ============ Phase C: attention (k single-term S, 2 CTAs/SM) ===============
__global__ __launch_bounds__(256, 2) void attn_tensor_kernel() {
#if HAS_TCGEN05
    extern __shared__ char smem[];
    uint32_t sb = smem_to_u32(smem);
    int tid = threadIdx.x;
    int mi = blockIdx.x & 1, c = (blockIdx.x >> 1) & 31, h = blockIdx.x >> 6;
    float s = g_slopes[h];
    float* decay_tab = (float*)(smem + 16);
    const int QH   = 2048;                 // q single fp16 32KB
    const int KH   = 34816;                // k chunk single 16KB
    const int VH   = 51200;                // vT chunk single 16KB
    const int SH   = 67584;                // S single fp16 16KB
    const int KVHI = 34816, KVLO = 67584;  // final: kvstT hi/lo 32KB each (reuse)
    uint32_t mb = sb + 8;
    if (tid < 32) TCGEN05_ALLOC(sb, 256);
    if (tid == 0) MBARRIER_INIT(mb, 1);
    for (int i = tid; i < 257; i += 256) decay_tab[i] = expf(-s * (float)i);
    __syncthreads();
    uint32_t tmem;
    asm volatile("ld.shared.b32 %0, [%1];" : "=r"(tmem) : "r"(sb));
    if (tid < 32) TCGEN05_RELINQ();
    const uint32_t OT = tmem, ST = tmem + 128;
    const uint32_t IDESC128F = (1u << 4) | (16u << 17) | (8u << 24);
    const uint32_t IDESC64F  = (1u << 4) | (8u  << 17) | (8u << 24);

    const float* qb = g_qkv + (size_t)(c * 256 + mi * 128) * QKVW + (size_t)h * DH;
    #pragma unroll
    for (int it = 0; it < 16; it++) {
        int j = it * 256 + tid;
        int r = j >> 5, dq = (j & 31) << 2;
        float4 v = *(const float4*)&qb[(size_t)r * QKVW + dq];
        uint32_t o = bswz(r, dq, 16);
        *(uint2*)(smem + QH + o) = make_uint2(
            pkh(__float2half_rn(v.x), __float2half_rn(v.y)),
            pkh(__float2half_rn(v.z), __float2half_rn(v.w)));
    }
    int ph = 0;
    const int nch = 2 * mi + 2;
    for (int cn = 0; cn < nch; cn++) {
        // ---- load k chunk [64,128] fp16 single ----
        const float* kb = g_qkv + (size_t)(c * 256 + cn * 64) * QKVW + 2048 + (size_t)h * DH;
        #pragma unroll
        for (int it = 0; it < 8; it++) {
            int j = it * 256 + tid;
            int r = j >> 5, dq = (j & 31) << 2;
            float4 v = *(const float4*)&kb[(size_t)r * QKVW + dq];
            uint32_t o = bswz(r, dq, 8);
            *(uint2*)(smem + KH + o) = make_uint2(
                pkh(__float2half_rn(v.x), __float2half_rn(v.y)),
                pkh(__float2half_rn(v.z), __float2half_rn(v.w)));
        }
        // ---- load vT chunk (pre-swizzled fp16 blob) ----
        {
            const uint4* sh = (const uint4*)(g_vThi + (size_t)(h * 32 + c) * 32768 + cn * 8192);
            uint4* dh = (uint4*)(smem + VH);
            #pragma unroll
            for (int it = 0; it < 4; it++) {
                int j = it * 256 + tid;
                dh[j] = sh[j];
            }
        }
        FENCE_ASYNC_SHARED();
        __syncthreads();
        // ---- MMA_S: S = q·k^T (single term) ----
        if (tid < 32) {
            uint64_t dQ = MAKE_SMEM_DESC(sb + QH);
            uint64_t dK = MAKE_SMEM_DESC(sb + KH);
            if (elect_one_pred()) {
                #pragma unroll
                for (int st = 0; st < 8; st++) {
                    uint32_t uq = ((st >> 2) << 10) + ((st & 3) << 1);
                    uint32_t uk = ((st >> 2) << 9) + ((st & 3) << 1);
                    mma_f16_ss(ST, dQ + uq, dK + uk, IDESC64F, st != 0);
                }
                TCGEN05_COMMIT(mb);
            }
        }
        MBARRIER_WAIT_PARITY(mb, ph & 1); ph++;
        TCGEN05_FENCE_AFTER();
        // ---- read S, apply decay, single fp16 store ----
        if (tid < 128) {
            int w = tid >> 5, l = tid & 31, m = w * 32 + l;
            int gm = mi * 128 + m;
            uint32_t r0[32], r1[32];
            TCGEN05_LD_X32(r0, ST);
            TCGEN05_WAIT_LD();
            TCGEN05_LD_X32(r1, ST + 32);
            TCGEN05_WAIT_LD();
            #pragma unroll
            for (int g = 0; g < 8; g++) {
                uint32_t hp[4];
                #pragma unroll
                for (int jj = 0; jj < 4; jj++) {
                    int j0 = g * 8 + jj * 2;
                    float v0 = __uint_as_float(j0 < 32 ? r0[j0] : r1[j0 - 32]);
                    float v1 = __uint_as_float((j0 + 1) < 32 ? r0[j0 + 1] : r1[j0 - 31]);
                    int gn0 = cn * 64 + j0;
                    v0 = (gm >= gn0)     ? v0 * decay_tab[gm - gn0]     : 0.f;
                    v1 = (gm >= gn0 + 1) ? v1 * decay_tab[gm - gn0 - 1] : 0.f;
                    hp[jj] = pkh(__float2half_rn(v0), __float2half_rn(v1));
                }
                uint32_t o = bswz(m, g * 8, 16);
                *(uint4*)(smem + SH + o) = make_uint4(hp[0], hp[1], hp[2], hp[3]);
            }
        }
        FENCE_ASYNC_SHARED();
        __syncthreads();
        // ---- MMA_O: O += S·vT^T (single term) ----
        if (tid < 32) {
            uint64_t dS = MAKE_SMEM_DESC(sb + SH);
            uint64_t dV = MAKE_SMEM_DESC(sb + VH);
            if (elect_one_pred()) {
                #pragma unroll
                for (int st = 0; st < 4; st++) {
                    uint32_t u = (uint32_t)st << 1;
                    bool first = (cn == 0 && st == 0);
                    mma_f16_ss(OT, dS + u, dV + u, IDESC128F, !first);
                }
                TCGEN05_COMMIT(mb);
            }
        }
        MBARRIER_WAIT_PARITY(mb, ph & 1); ph++;
    }
    // ---- final: O += (qd·q)·kvstT (kvst hi/lo retained) ----
    {
        #pragma unroll
        for (int it = 0; it < 16; it++) {
            int j = it * 256 + tid;
            int r = j >> 5, dq = (j & 31) << 2;
            float qd = decay_tab[mi * 128 + r + 1];
            float4 v = *(const float4*)&qb[(size_t)r * QKVW + dq];
            uint32_t o = bswz(r, dq, 16);
            *(uint2*)(smem + QH + o) = make_uint2(
                pkh(__float2half_rn(v.x * qd), __float2half_rn(v.y * qd)),
                pkh(__float2half_rn(v.z * qd), __float2half_rn(v.w * qd)));
        }
        const float* kvb = g_kvstate + (size_t)(h * 32 + c) * 16384;
        #pragma unroll
        for (int it = 0; it < 16; it++) {
            int j = it * 256 + tid;
            int r = j >> 5, dq = (j & 31) << 2;
            float4 v = *(const float4*)&kvb[(size_t)r * 128 + dq];
            __half h0 = __float2half_rn(v.x), h1 = __float2half_rn(v.y);
            __half h2 = __float2half_rn(v.z), h3 = __float2half_rn(v.w);
            uint32_t o = bswz(r, dq, 16);
            *(uint2*)(smem + KVHI + o) = make_uint2(pkh(h0, h1), pkh(h2, h3));
            *(uint2*)(smem + KVLO + o) = make_uint2(
                pkh(__float2half_rn(v.x - __half2float(h0)), __float2half_rn(v.y - __half2float(h1))),
                pkh(__float2half_rn(v.z - __half2float(h2)), __float2half_rn(v.w - __half2float(h3))));
        }
        FENCE_ASYNC_SHARED();
        __syncthreads();
        if (tid < 32) {
            uint64_t dQ = MAKE_SMEM_DESC(sb + QH);
            uint64_t dKh = MAKE_SMEM_DESC(sb + KVHI), dKl = MAKE_SMEM_DESC(sb + KVLO);
            if (elect_one_pred()) {
                #pragma unroll
                for (int st = 0; st < 8; st++) {
                    uint32_t u = ((st >> 2) << 10) + ((st & 3) << 1);
                    mma_f16_ss(OT, dQ + u, dKh + u, IDESC128F, true);
                    mma_f16_ss(OT, dQ + u, dKl + u, IDESC128F, true);
                }
                TCGEN05_COMMIT(mb);
            }
        }
        MBARRIER_WAIT_PARITY(mb, ph & 1); ph++;
    }
    TCGEN05_FENCE_AFTER();
    if (tid < 128) {
        int w = tid >> 5, l = tid & 31, m = w * 32 + l;
        int gm = mi * 128 + m;
        float* dst = g_attn + (size_t)(c * 256 + gm) * HIDDEN + (size_t)h * DH;
        #pragma unroll
        for (int cb = 0; cb < 4; cb++) {
            uint32_t a[32];
            TCGEN05_LD_X32(a, OT + cb * 32);
            TCGEN05_WAIT_LD();
            #pragma unroll
            for (int j = 0; j < 32; j += 4)
                *(float4*)&dst[cb * 32 + j] = make_float4(
                    __uint_as_float(a[j]),     __uint_as_float(a[j + 1]),
                    __uint_as_float(a[j + 2]), __uint_as_float(a[j + 3]));
        }
    }
    __syncthreads();
    if (tid < 32) TCGEN05_DEALLOC(tmem, 256);
#else
    int mi = blockIdx.x & 1, c = (blockIdx.x >> 1) & 31, h = blockIdx.x >> 6;
    float s = g_slopes[h];
    const float* kvst = g_kvstate + (size_t)(h * 32 + c) * 16384;
    for (int idx = threadIdx.x; idx < 16384; idx += 256) {
        int m = idx >> 7, e = idx & 127;
        int gm = mi * 128 + m;
        size_t tq = (size_t)(c * 256 + gm) * QKVW + (size_t)h * DH;
        float o = 0.f;
        for (int d = 0; d < 128; d++) o += g_qkv[tq + d] * kvst[(size_t)e * 128 + d];
        o *= expf(-s * (float)(gm + 1));
        for (int n = 0; n <= gm; n++) {
            size_t tk = (size_t)(c * 256 + n) * QKVW + (size_t)h * DH;
            float qk = 0.f;
            for (int d = 0; d < 128; d++) qk += g_qkv[tq + d] * g_qkv[tk + 2048 + d];
            o += expf(-s * (float)(gm - n)) * qk * g_qkv[tk + 4096 + e];
        }
        g_attn[(size_t)(c * 256 + gm) * HIDDEN + (size_t)h * DH + e] = o;
    }
#endif
}

// ============ RMS norm + sigmoid gate -> fp16 output ========================
__global__ void rmsgate_kernel(const float* __restrict__ gnw) {
    int t = blockIdx.x;
    int tid = threadIdx.x;
    const float* a = g_attn + (size_t)t * HIDDEN;
    const float* g = g_gate + (size_t)t * HIDDEN;
    float ss = 0.f;
    for (int j = tid; j < HIDDEN; j += 256) { float v = a[j]; ss += v * v; }
    #pragma unroll
    for (int o = 16; o; o >>= 1) ss += __shfl_xor_sync(0xffffffffu, ss, o);
    __shared__ float red[8];
    __shared__ float tot;
    if ((tid & 31) == 0) red[tid >> 5] = ss;
    __syncthreads();
    if (tid == 0) {
        float tsum = 0.f;
        #pragma unroll
        for (int w = 0; w < 8; w++) tsum += red[w];
        tot = tsum;
    }
    __syncthreads();
    float rms = rsqrtf(tot * (1.0f / HIDDEN) + 1e-5f);
    for (int j = tid; j < HIDDEN; j += 256) {
        float gv = g[j];
        float sig = 1.0f / (1.0f + expf(-gv));
        float val = a[j] * rms * gnw[j] * sig;
        g_yh[(size_t)t * HIDDEN + j] = __float2half_rn(val);
    }
}

// ================= launch =====================================================
extern "C" void kernel_launch(void* const* d_in, const int* in_sizes, int n_in,
                              void* d_out, int out_size) {
    const float* hidden    = (const float*)d_in[0];
    const int*   positions = (const int*)d_in[1];
    const float* Wqkv      = (const float*)d_in[2];
    const float* Wg        = (const float*)d_in[3];
    const float* Wd        = (const float*)d_in[4];
    const float* gnw       = (const float*)d_in[5];
    float* out = (float*)d_out;

    void *ah_p, *yh_p;
    void *bqh_p, *bgh_p, *bdh_p;
    cudaGetSymbolAddress(&ah_p, g_ah);
    cudaGetSymbolAddress(&yh_p, g_yh);
    cudaGetSymbolAddress(&bqh_p, g_bqkv_hi);
    cudaGetSymbolAddress(&bgh_p, g_bg_hi);
    cudaGetSymbolAddress(&bdh_p, g_bd_hi);

    cudaFuncSetAttribute(gemm_qkvgate, cudaFuncAttributeMaxDynamicSharedMemorySize, CG2_SMEM);
    cudaFuncSetAttribute(gemm_down, cudaFuncAttributeMaxDynamicSharedMemorySize, CG2_SMEM);
    const int kvblk_smem = 2048 + 33792 + 2 * 32768;   // 101376 (99KB) -> 2 CTAs/SM
    cudaFuncSetAttribute(kvblkT_kernel, cudaFuncAttributeMaxDynamicSharedMemorySize, kvblk_smem);
    const int attn_smem = 100352;                      // 98KB -> 2 CTAs/SM
    cudaFuncSetAttribute(attn_tensor_kernel, cudaFuncAttributeMaxDynamicSharedMemorySize, attn_smem);

    init_tables<<<1, 64>>>();
    conv_act<<<(NTOK * HIDDEN / 4 + 255) / 256, 256>>>(hidden, (__half*)ah_p,
                                                       NTOK * HIDDEN / 4);
    transposeW<<<dim3(QKVW / 32, HIDDEN / 32), 256>>>(Wqkv, (__half*)bqh_p, HIDDEN, QKVW);
    transposeW<<<dim3(HIDDEN / 32, HIDDEN / 32), 256>>>(Wg, (__half*)bgh_p, HIDDEN, HIDDEN);
    transposeW<<<dim3(HIDDEN / 32, HIDDEN / 32), 256>>>(Wd, (__half*)bdh_p, HIDDEN, HIDDEN);
    gemm_qkvgate<<<dim3(((QKVW + HIDDEN) / 256) * 2, NTOK / 256), 256, CG2_SMEM>>>(
        (const __half*)ah_p, positions);
    kvblkT_kernel<<<HEADS * NCHUNK, 256, kvblk_smem>>>();
    kvscan_kernel<<<HEADS * 16, 256>>>();
    attn_tensor_kernel<<<HEADS * NCHUNK * 2, 256, attn_smem>>>();
    rmsgate_kernel<<<NTOK, 256>>>(gnw);
    gemm_down<<<dim3((HIDDEN / 256) * 2, NTOK / 256), 256, CG2_SMEM>>>(
        (const __half*)yh_p, (const __half*)bdh_p,
        out, HIDDEN, HIDDEN);
}